// round 6
// baseline (speedup 1.0000x reference)
#include <cuda_runtime.h>
#include <cuda_bf16.h>
#include <math.h>
#include <stdint.h>

#define QL 1024
#define NH 16
#define DH 64
#define DM 1024
#define DI 4096
#define RL 2048
#define M2 (QL*2)
#define MR (RL*2)
#define ATT_SCALE 0.125f

__device__ __forceinline__ uint32_t smem_u32(const void* p) {
    uint32_t a;
    asm("{ .reg .u64 t; cvta.to.shared.u64 t, %1; cvt.u32.u64 %0, t; }" : "=r"(a) : "l"(p));
    return a;
}
__device__ __forceinline__ void cp16(uint32_t dst, const void* src) {
    asm volatile("cp.async.cg.shared.global [%0], [%1], 16;" :: "r"(dst), "l"(src));
}
__device__ __forceinline__ void cp_commit() { asm volatile("cp.async.commit_group;" ::: "memory"); }
__device__ __forceinline__ void ldsm4(uint32_t (&r)[4], uint32_t addr) {
    asm volatile("ldmatrix.sync.aligned.m8n8.x4.shared.b16 {%0,%1,%2,%3}, [%4];"
        : "=r"(r[0]), "=r"(r[1]), "=r"(r[2]), "=r"(r[3]) : "r"(addr));
}
__device__ __forceinline__ void mma16816(float (&d)[4], const uint32_t (&a)[4],
                                         uint32_t b0, uint32_t b1) {
    asm volatile("mma.sync.aligned.m16n8k16.row.col.f32.bf16.bf16.f32 "
        "{%0,%1,%2,%3},{%4,%5,%6,%7},{%8,%9},{%0,%1,%2,%3};"
        : "+f"(d[0]), "+f"(d[1]), "+f"(d[2]), "+f"(d[3])
        : "r"(a[0]), "r"(a[1]), "r"(a[2]), "r"(a[3]), "r"(b0), "r"(b1));
}

// ---------------- scratch ----------------
__device__ float g_q [M2*DM];
__device__ float g_q2[M2*DM];
__device__ float g_k [M2*DM];
__device__ float g_v [M2*DM];
__device__ float g_kr[MR*DM];
__device__ float g_ef[M2*NH*2];
__device__ float g_o [M2*DM];
__device__ float g_y [M2*DM];
__device__ float g_z [M2*DM];
__device__ float g_bkT [32*QL];
__device__ float g_bkrT[32*RL];
__device__ __align__(256) __nv_bfloat16 g_diffb[(size_t)2*QL*QL];
__device__ __align__(256) __nv_bfloat16 g_Ah [MR*DM], g_Al [MR*DM];
__device__ __align__(256) __nv_bfloat16 g_wqT[2*DM*DM], g_wkT[2*DM*DM], g_wvT[2*DM*DM];
__device__ __align__(256) __nv_bfloat16 g_wrT[2*DM*DM], g_woC[2*DM*DM];
__device__ __align__(256) __nv_bfloat16 g_w1T[2*DM*DI], g_w2T[2*DI*DM];
__device__ __align__(256) __nv_bfloat16 g_q1h[32*QL*DH], g_q1l[32*QL*DH];
__device__ __align__(256) __nv_bfloat16 g_q2h[32*QL*DH], g_q2l[32*QL*DH];
__device__ __align__(256) __nv_bfloat16 g_khh[32*QL*DH], g_khl[32*QL*DH];
__device__ __align__(256) __nv_bfloat16 g_krh[32*RL*DH], g_krl[32*RL*DH];
__device__ __align__(256) __nv_bfloat16 g_vth[32*DH*QL], g_vtl[32*DH*QL];
__device__ __align__(256) __nv_bfloat16 g_ath[M2*DM], g_atl[M2*DM];
__device__ __align__(256) __nv_bfloat16 g_yh [M2*DM], g_yl [M2*DM];
__device__ __align__(256) __nv_bfloat16 g_th [M2*DI], g_tl [M2*DI];

// ---------------- small kernels ----------------
__global__ void conv_split(const float* __restrict__ X, __nv_bfloat16* __restrict__ hi,
                           __nv_bfloat16* __restrict__ lo, int n4)
{
    int i = blockIdx.x * blockDim.x + threadIdx.x;
    if (i >= n4) return;
    float4 v = ((const float4*)X)[i];
    __nv_bfloat16 hx = __float2bfloat16(v.x), hy = __float2bfloat16(v.y);
    __nv_bfloat16 hz = __float2bfloat16(v.z), hw = __float2bfloat16(v.w);
    ((__nv_bfloat162*)hi)[2*i]   = __nv_bfloat162(hx, hy);
    ((__nv_bfloat162*)hi)[2*i+1] = __nv_bfloat162(hz, hw);
    ((__nv_bfloat162*)lo)[2*i]   = __nv_bfloat162(
        __float2bfloat16(v.x - __bfloat162float(hx)), __float2bfloat16(v.y - __bfloat162float(hy)));
    ((__nv_bfloat162*)lo)[2*i+1] = __nv_bfloat162(
        __float2bfloat16(v.z - __bfloat162float(hz)), __float2bfloat16(v.w - __bfloat162float(hw)));
}

__global__ void convT_split(const float* __restrict__ W, __nv_bfloat16* __restrict__ hi,
                            __nv_bfloat16* __restrict__ lo, int K, int N)
{
    __shared__ float t[32][33];
    int k0 = blockIdx.y * 32, n0 = blockIdx.x * 32;
    int tx = threadIdx.x, ty = threadIdx.y;
#pragma unroll
    for (int p = 0; p < 4; p++)
        t[ty + p*8][tx] = W[(size_t)(k0 + ty + p*8)*N + n0 + tx];
    __syncthreads();
#pragma unroll
    for (int p = 0; p < 4; p++) {
        float v = t[tx][ty + p*8];
        __nv_bfloat16 h = __float2bfloat16(v);
        size_t o = (size_t)(n0 + ty + p*8)*K + k0 + tx;
        hi[o] = h;
        lo[o] = __float2bfloat16(v - __bfloat162float(h));
    }
}

__global__ void repack_vT(const float* __restrict__ V, __nv_bfloat16* __restrict__ hi,
                          __nv_bfloat16* __restrict__ lo)
{
    __shared__ float tile[32][33];
    int j0 = blockIdx.x * 32, d0 = blockIdx.y * 32;
    int bn = blockIdx.z, b = bn >> 4, n = bn & 15;
    int tx = threadIdx.x, ty = threadIdx.y;
#pragma unroll
    for (int p = 0; p < 4; p++)
        tile[ty + p*8][tx] = V[((size_t)(j0 + ty + p*8)*2 + b)*DM + n*DH + d0 + tx];
    __syncthreads();
#pragma unroll
    for (int p = 0; p < 4; p++) {
        float v = tile[tx][ty + p*8];
        __nv_bfloat16 h = __float2bfloat16(v);
        size_t o = ((size_t)bn*DH + d0 + ty + p*8)*QL + j0 + tx;
        hi[o] = h;
        lo[o] = __float2bfloat16(v - __bfloat162float(h));
    }
}

__global__ void prep_diff(const float* __restrict__ seg_mat, __nv_bfloat16* __restrict__ diff)
{
    size_t idx = (size_t)blockIdx.x * blockDim.x + threadIdx.x;
    if (idx >= (size_t)2*QL*QL) return;
    int j = idx & 1023, i = (idx >> 10) & 1023, b = (int)(idx >> 20);
    diff[idx] = __float2bfloat16(seg_mat[(((size_t)i*QL + j)*2 + b)*2 + 1]);
}

__global__ void bias_dotT(const float* __restrict__ X, const float* __restrict__ bias,
                          float* __restrict__ outT, int rowsPerB)
{
    const int gw = (blockIdx.x * blockDim.x + threadIdx.x) >> 5;
    const int lane = threadIdx.x & 31;
    if (gw >= rowsPerB * 2 * NH) return;
    const int row = gw >> 4, n = gw & 15;
    const int j = row >> 1, b = row & 1;
    float s = bias[n*DH + lane]      * X[(size_t)row*DM + n*DH + lane]
            + bias[n*DH + 32 + lane] * X[(size_t)row*DM + n*DH + 32 + lane];
#pragma unroll
    for (int o = 16; o; o >>= 1) s += __shfl_xor_sync(0xffffffffu, s, o);
    if (!lane) outT[(size_t)(b*16 + n)*rowsPerB + j] = s;
}

__global__ void ef_kernel(const float* __restrict__ q, const float* __restrict__ rsb,
                          const float* __restrict__ se, float* __restrict__ ef)
{
    const int gw = (blockIdx.x * blockDim.x + threadIdx.x) >> 5;
    const int lane = threadIdx.x & 31;
    if (gw >= M2 * NH) return;
    const int row = gw >> 4, n = gw & 15;
    const float v0 = q[(size_t)row*DM + n*DH + lane]      + rsb[n*DH + lane];
    const float v1 = q[(size_t)row*DM + n*DH + 32 + lane] + rsb[n*DH + 32 + lane];
    float s0 = v0*se[n*DH + lane] + v1*se[n*DH + 32 + lane];
    float s1 = v0*se[NH*DH + n*DH + lane] + v1*se[NH*DH + n*DH + 32 + lane];
#pragma unroll
    for (int o = 16; o; o >>= 1) {
        s0 += __shfl_xor_sync(0xffffffffu, s0, o);
        s1 += __shfl_xor_sync(0xffffffffu, s1, o);
    }
    if (!lane) { ef[gw*2] = s0; ef[gw*2 + 1] = s1; }
}

// ---------------- dense split-bf16 GEMM (OUT: 0 fp32, 1 bf16 hi/lo, 2 fp32+head-major) ----------------
#define GSTAGE 65536
#define GSMEM_BYTES (2*GSTAGE)

__device__ __forceinline__ void g_load_stage(
    const __nv_bfloat16* __restrict__ Ah, const __nv_bfloat16* __restrict__ Al,
    const __nv_bfloat16* __restrict__ Bh, const __nv_bfloat16* __restrict__ Bl,
    uint32_t st, int m0, int n0, int K, int kc, int tid)
{
    const size_t ko = (size_t)kc * 64;
#pragma unroll
    for (int p = 0; p < 4; p++) {
        int c = p*256 + tid;
        int row = c >> 3, kcol = c & 7;
        uint32_t sw = (uint32_t)(row*128 + kcol*16) ^ ((row & 7) << 4);
        const size_t ga = (size_t)(m0 + row)*K + ko + kcol*8;
        const size_t gb = (size_t)(n0 + row)*K + ko + kcol*8;
        cp16(st + sw,         Ah + ga);
        cp16(st + 16384 + sw, Al + ga);
        cp16(st + 32768 + sw, Bh + gb);
        cp16(st + 49152 + sw, Bl + gb);
    }
    cp_commit();
}

template<int EPI, int OUT>
__global__ void __launch_bounds__(256, 1) gemm_mma(
    const __nv_bfloat16* __restrict__ Ah, const __nv_bfloat16* __restrict__ Al,
    const __nv_bfloat16* __restrict__ Bh, const __nv_bfloat16* __restrict__ Bl,
    const float* __restrict__ bias, float* __restrict__ C,
    __nv_bfloat16* __restrict__ Chi, __nv_bfloat16* __restrict__ Clo,
    int rowsPerB, int K, int ldc)
{
    extern __shared__ char dsm[];
    const uint32_t sbase = smem_u32(dsm);
    const int tid = threadIdx.x, lane = tid & 31, warp = tid >> 5;
    const int m0 = blockIdx.y * 128, n0 = blockIdx.x * 128;
    const int wm = (warp & 1) * 64, wn = (warp >> 1) * 32;
    const int NC = K >> 6;

    float acc[4][4][4] = {};
    g_load_stage(Ah, Al, Bh, Bl, sbase,          m0, n0, K, 0, tid);
    g_load_stage(Ah, Al, Bh, Bl, sbase + GSTAGE, m0, n0, K, 1, tid);
    asm volatile("cp.async.wait_group 1;" ::: "memory");
    __syncthreads();

    const int arow = wm + (lane & 15), akb = lane & 16;
    const int brow = wn + ((lane & 16) >> 1) + (lane & 7), bkb = (lane & 8) << 1;

    for (int kc = 0; kc < NC; kc++) {
        const uint32_t st = sbase + (kc & 1) * GSTAGE;
#pragma unroll
        for (int ks = 0; ks < 4; ks++) {
            const int kb = ks*32;
            uint32_t ah[4][4], al[4][4], bh[2][4], bl[2][4];
#pragma unroll
            for (int im = 0; im < 4; im++) {
                int row = arow + im*16;
                uint32_t off = (uint32_t)(row*128 + kb + akb) ^ ((row & 7) << 4);
                ldsm4(ah[im], st + off);
                ldsm4(al[im], st + 16384 + off);
            }
#pragma unroll
            for (int np = 0; np < 2; np++) {
                int row = brow + np*16;
                uint32_t off = (uint32_t)(row*128 + kb + bkb) ^ ((row & 7) << 4);
                ldsm4(bh[np], st + 32768 + off);
                ldsm4(bl[np], st + 49152 + off);
            }
#pragma unroll
            for (int im = 0; im < 4; im++)
#pragma unroll
                for (int in = 0; in < 4; in++) {
                    const int np = in >> 1, hf = (in & 1) * 2;
                    mma16816(acc[im][in], ah[im], bh[np][hf], bh[np][hf+1]);
                    mma16816(acc[im][in], ah[im], bl[np][hf], bl[np][hf+1]);
                    mma16816(acc[im][in], al[im], bh[np][hf], bh[np][hf+1]);
                }
        }
        __syncthreads();
        if (kc + 2 < NC) {
            g_load_stage(Ah, Al, Bh, Bl, sbase + (kc & 1)*GSTAGE, m0, n0, K, kc + 2, tid);
            asm volatile("cp.async.wait_group 1;" ::: "memory");
        } else {
            asm volatile("cp.async.wait_group 0;" ::: "memory");
        }
        __syncthreads();
    }

    const int rbase = m0 + wm + (lane >> 2);
    const int cbase = n0 + wn + 2*(lane & 3);
#pragma unroll
    for (int im = 0; im < 4; im++) {
#pragma unroll
        for (int in = 0; in < 4; in++) {
            int col = cbase + in*8;
            float v0 = acc[im][in][0], v1 = acc[im][in][1];
            float v2 = acc[im][in][2], v3 = acc[im][in][3];
            if (EPI >= 1) {
                float b0 = bias[col], b1 = bias[col+1];
                v0 += b0; v1 += b1; v2 += b0; v3 += b1;
            }
            if (EPI == 2) {
                v0 = 0.5f*v0*(1.0f + erff(v0*0.7071067811865476f));
                v1 = 0.5f*v1*(1.0f + erff(v1*0.7071067811865476f));
                v2 = 0.5f*v2*(1.0f + erff(v2*0.7071067811865476f));
                v3 = 0.5f*v3*(1.0f + erff(v3*0.7071067811865476f));
            }
            int r0 = rbase + im*16, r1 = r0 + 8;
            if (OUT != 1) {
                *(float2*)(C + (size_t)r0*ldc + col) = make_float2(v0, v1);
                *(float2*)(C + (size_t)r1*ldc + col) = make_float2(v2, v3);
            }
            if (OUT >= 1) {
                __nv_bfloat16 h0 = __float2bfloat16(v0), h1 = __float2bfloat16(v1);
                __nv_bfloat16 h2 = __float2bfloat16(v2), h3 = __float2bfloat16(v3);
                size_t d0, d1;
                if (OUT == 1) { d0 = (size_t)r0*ldc + col; d1 = (size_t)r1*ldc + col; }
                else {
                    int nh = col >> 6, d = col & 63;
                    d0 = (((size_t)(r0 & 1)*NH + nh)*rowsPerB + (r0 >> 1))*DH + d;
                    d1 = (((size_t)(r1 & 1)*NH + nh)*rowsPerB + (r1 >> 1))*DH + d;
                }
                *(__nv_bfloat162*)(Chi + d0) = __nv_bfloat162(h0, h1);
                *(__nv_bfloat162*)(Chi + d1) = __nv_bfloat162(h2, h3);
                *(__nv_bfloat162*)(Clo + d0) = __nv_bfloat162(
                    __float2bfloat16(v0 - __bfloat162float(h0)), __float2bfloat16(v1 - __bfloat162float(h1)));
                *(__nv_bfloat162*)(Clo + d1) = __nv_bfloat162(
                    __float2bfloat16(v2 - __bfloat162float(h2)), __float2bfloat16(v3 - __bfloat162float(h3)));
            }
        }
    }
}

// ---------------- fused flash attention with rel-shift ----------------
#define FL_QH   0
#define FL_QLO  16384
#define FL_KH   32768
#define FL_KLO  49152
#define FL_KRH  65536
#define FL_KRL  98304
#define FL_SC   131072
#define FL_M    197120
#define FL_L    197632
#define FL_AL   198144
#define FL_RED  198656
#define FL_BK   199680
#define FL_BKR  200192
#define FL_E0   201216
#define FL_DE   201728
#define FL_SMEM 202240

__global__ void __launch_bounds__(256, 1) flash_attn(
    const __nv_bfloat16* __restrict__ Qh, const __nv_bfloat16* __restrict__ Ql,
    const __nv_bfloat16* __restrict__ Kh, const __nv_bfloat16* __restrict__ Kl,
    const __nv_bfloat16* __restrict__ Krh, const __nv_bfloat16* __restrict__ Krl,
    const __nv_bfloat16* __restrict__ Vh, const __nv_bfloat16* __restrict__ Vl,
    const float* __restrict__ bkT, const float* __restrict__ bkrT,
    const float* __restrict__ ef, const __nv_bfloat16* __restrict__ diff,
    __nv_bfloat16* __restrict__ Oh, __nv_bfloat16* __restrict__ Ol, int gstream)
{
    extern __shared__ char sm[];
    const uint32_t sb = smem_u32(sm);
    float* sc    = (float*)(sm + FL_SC);
    float* m_s   = (float*)(sm + FL_M);
    float* l_s   = (float*)(sm + FL_L);
    float* al_s  = (float*)(sm + FL_AL);
    float* red   = (float*)(sm + FL_RED);
    float* bk_s  = (float*)(sm + FL_BK);
    float* bkr_s = (float*)(sm + FL_BKR);
    float* e0_s  = (float*)(sm + FL_E0);
    float* de_s  = (float*)(sm + FL_DE);

    const int tid = threadIdx.x, lane = tid & 31, warp = tid >> 5;
    const int it = blockIdx.x, bn = blockIdx.y;
    const int b = bn >> 4, n = bn & 15;
    const int i0 = it * 128;

#pragma unroll
    for (int p = 0; p < 4; p++) {
        int c = p*256 + tid;
        int row = c >> 3, kcol = c & 7;
        uint32_t sw = (uint32_t)(row*128 + kcol*16) ^ ((row & 7) << 4);
        size_t src = ((size_t)bn*QL + i0 + row)*DH + kcol*8;
        cp16(sb + FL_QH  + sw, Qh + src);
        cp16(sb + FL_QLO + sw, Ql + src);
    }
    cp_commit();
    if (tid < 128) {
        size_t idx = (((size_t)(i0 + tid)*2 + b)*NH + n)*2;
        float a = ef[idx];
        e0_s[tid] = a; de_s[tid] = ef[idx + 1] - a;
        m_s[tid] = -INFINITY; l_s[tid] = 0.f;
    }
    float acc_o[2][4][4] = {};

    const int wm = (warp & 1) * 64, wn = (warp >> 1) * 32;
    const int arow = wm + (lane & 15), akb = lane & 16;
    const int brow = wn + ((lane & 16) >> 1) + (lane & 7), bkb = (lane & 8) << 1;
    const int rb = wm + (lane >> 2), cbx = wn + 2*(lane & 3);
    const int wmP = (warp & 3) * 32, wnP = (warp >> 2) * 32;
    const int parow = wmP + (lane & 15), pakb = lane & 16;
    const int pbrow = wnP + ((lane & 16) >> 1) + (lane & 7), pbkb = (lane & 8) << 1;
    const int prb = wmP + (lane >> 2), pcb = wnP + 2*(lane & 3);

    asm volatile("cp.async.wait_group 0;" ::: "memory");
    __syncthreads();

    for (int jt = 0; jt < 8; jt++) {
        const int j0 = jt * 128;
        const int W = 896 + (jt - it) * 128;

#pragma unroll
        for (int p = 0; p < 4; p++) {
            int c = p*256 + tid;
            int row = c >> 3, kcol = c & 7;
            uint32_t sw = (uint32_t)(row*128 + kcol*16) ^ ((row & 7) << 4);
            size_t src = ((size_t)bn*QL + j0 + row)*DH + kcol*8;
            cp16(sb + FL_KH  + sw, Kh + src);
            cp16(sb + FL_KLO + sw, Kl + src);
        }
#pragma unroll
        for (int p = 0; p < 8; p++) {
            int c = p*256 + tid;
            int row = c >> 3, kcol = c & 7;
            uint32_t sw = (uint32_t)(row*128 + kcol*16) ^ ((row & 7) << 4);
            size_t src = ((size_t)bn*RL + W + row)*DH + kcol*8;
            cp16(sb + FL_KRH + sw, Krh + src);
            cp16(sb + FL_KRL + sw, Krl + src);
        }
        if (tid < 32) cp16(sb + FL_BK + tid*16, bkT + (size_t)bn*QL + j0 + tid*4);
        else if (tid < 96) cp16(sb + FL_BKR + (tid-32)*16, bkrT + (size_t)bn*RL + W + (tid-32)*4);
        cp_commit();
        asm volatile("cp.async.wait_group 0;" ::: "memory");
        __syncthreads();

        // ac = Q.K^T + bk
        {
            float a_s[4][4][4] = {};
#pragma unroll
            for (int ks = 0; ks < 4; ks++) {
                const int kb = ks*32;
                uint32_t ah[4][4], al[4][4], bh[2][4], bl[2][4];
#pragma unroll
                for (int im = 0; im < 4; im++) {
                    int row = arow + im*16;
                    uint32_t off = (uint32_t)(row*128 + kb + akb) ^ ((row & 7) << 4);
                    ldsm4(ah[im], sb + FL_QH  + off);
                    ldsm4(al[im], sb + FL_QLO + off);
                }
#pragma unroll
                for (int np = 0; np < 2; np++) {
                    int row = brow + np*16;
                    uint32_t off = (uint32_t)(row*128 + kb + bkb) ^ ((row & 7) << 4);
                    ldsm4(bh[np], sb + FL_KH  + off);
                    ldsm4(bl[np], sb + FL_KLO + off);
                }
#pragma unroll
                for (int im = 0; im < 4; im++)
#pragma unroll
                    for (int in = 0; in < 4; in++) {
                        const int np = in >> 1, hfx = (in & 1)*2;
                        mma16816(a_s[im][in], ah[im], bh[np][hfx], bh[np][hfx+1]);
                        mma16816(a_s[im][in], ah[im], bl[np][hfx], bl[np][hfx+1]);
                        mma16816(a_s[im][in], al[im], bh[np][hfx], bh[np][hfx+1]);
                    }
            }
#pragma unroll
            for (int im = 0; im < 4; im++)
#pragma unroll
                for (int in = 0; in < 4; in++) {
                    int col = cbx + in*8, r0 = rb + im*16;
                    sc[r0*129 + col]         = a_s[im][in][0] + bk_s[col];
                    sc[r0*129 + col + 1]     = a_s[im][in][1] + bk_s[col+1];
                    sc[(r0+8)*129 + col]     = a_s[im][in][2] + bk_s[col];
                    sc[(r0+8)*129 + col + 1] = a_s[im][in][3] + bk_s[col+1];
                }
        }
        __syncthreads();

        // bd = Q.Kr^T with rel-shift scatter (+bkr)
#pragma unroll
        for (int c2 = 0; c2 < 2; c2++) {
            float a_b[4][4][4] = {};
#pragma unroll
            for (int ks = 0; ks < 4; ks++) {
                const int kb = ks*32;
                uint32_t ah[4][4], al[4][4], bh[2][4], bl[2][4];
#pragma unroll
                for (int im = 0; im < 4; im++) {
                    int row = arow + im*16;
                    uint32_t off = (uint32_t)(row*128 + kb + akb) ^ ((row & 7) << 4);
                    ldsm4(ah[im], sb + FL_QH  + off);
                    ldsm4(al[im], sb + FL_QLO + off);
                }
#pragma unroll
                for (int np = 0; np < 2; np++) {
                    int row = brow + np*16;
                    uint32_t off = (uint32_t)(row*128 + kb + bkb) ^ ((row & 7) << 4);
                    ldsm4(bh[np], sb + FL_KRH + c2*16384 + off);
                    ldsm4(bl[np], sb + FL_KRL + c2*16384 + off);
                }
#pragma unroll
                for (int im = 0; im < 4; im++)
#pragma unroll
                    for (int in = 0; in < 4; in++) {
                        const int np = in >> 1, hfx = (in & 1)*2;
                        mma16816(a_b[im][in], ah[im], bh[np][hfx], bh[np][hfx+1]);
                        mma16816(a_b[im][in], ah[im], bl[np][hfx], bl[np][hfx+1]);
                        mma16816(a_b[im][in], al[im], bh[np][hfx], bh[np][hfx+1]);
                    }
            }
#pragma unroll
            for (int im = 0; im < 4; im++)
#pragma unroll
                for (int in = 0; in < 4; in++)
#pragma unroll
                    for (int rr = 0; rr < 4; rr++) {
                        int il = rb + im*16 + ((rr >= 2) ? 8 : 0);
                        int t = c2*128 + cbx + in*8 + (rr & 1);
                        int jl = t + il - 128;
                        if (jl >= 0 && jl < 128)
                            sc[il*129 + jl] += a_b[im][in][rr] + bkr_s[t];
                    }
        }
        __syncthreads();

        // V load into K buffers (2 chunks of 64 j each)
#pragma unroll
        for (int p = 0; p < 4; p++) {
            int c = p*256 + tid;
            int c2v = c >> 9, drow = (c >> 3) & 63, kcol = c & 7;
            uint32_t sw = (uint32_t)(drow*128 + kcol*16) ^ ((drow & 7) << 4);
            size_t src = ((size_t)bn*DH + drow)*QL + j0 + c2v*64 + kcol*8;
            cp16(sb + FL_KH  + c2v*8192 + sw, Vh + src);
            cp16(sb + FL_KLO + c2v*8192 + sw, Vl + src);
        }
        cp_commit();

        // online softmax + P hi/lo into Kr buffers
        {
            const int r = tid & 127, hf = tid >> 7;
            const int ig = i0 + r;
            const float e0v = e0_s[r], dev = de_s[r];
            const __nv_bfloat16* drp = diff + ((size_t)b << 20) + ((size_t)ig << 10) + j0 + hf*64;
            float mx = -INFINITY;
#pragma unroll 8
            for (int c = 0; c < 64; c++) {
                int jl = hf*64 + c;
                int jg = j0 + jl;
                float s = (sc[r*129 + jl] + e0v + dev * __bfloat162float(drp[c])) * ATT_SCALE;
                bool blocked = gstream ? (jg >= ig) : (jg > ig);
                if (blocked) s -= 1e30f;
                sc[r*129 + jl] = s;
                mx = fmaxf(mx, s);
            }
            red[hf*128 + r] = mx;
            __syncthreads();
            if (hf == 0) {
                float mo = m_s[r];
                float mn = fmaxf(mo, fmaxf(red[r], red[128 + r]));
                al_s[r] = expf(mo - mn);
                m_s[r] = mn;
            }
            __syncthreads();
            float mn = m_s[r];
            float ls = 0.f;
#pragma unroll 8
            for (int c = 0; c < 64; c++) {
                int jl = hf*64 + c;
                float pv = expf(sc[r*129 + jl] - mn);
                ls += pv;
                __nv_bfloat16 ph = __float2bfloat16(pv);
                uint32_t off = (uint32_t)(r*128 + (jl & 63)*2) ^ ((r & 7) << 4);
                *(__nv_bfloat16*)(sm + FL_KRH + hf*16384 + off) = ph;
                *(__nv_bfloat16*)(sm + FL_KRL + hf*16384 + off) =
                    __float2bfloat16(pv - __bfloat162float(ph));
            }
            red[hf*128 + r] = ls;
            __syncthreads();
            if (hf == 0) l_s[r] = l_s[r] * al_s[r] + red[r] + red[128 + r];
        }
        asm volatile("cp.async.wait_group 0;" ::: "memory");
        __syncthreads();

        // rescale O, O += P @ V
#pragma unroll
        for (int im = 0; im < 2; im++) {
            float a0 = al_s[prb + im*16], a1 = al_s[prb + im*16 + 8];
#pragma unroll
            for (int in = 0; in < 4; in++) {
                acc_o[im][in][0] *= a0; acc_o[im][in][1] *= a0;
                acc_o[im][in][2] *= a1; acc_o[im][in][3] *= a1;
            }
        }
#pragma unroll
        for (int ch = 0; ch < 2; ch++) {
#pragma unroll
            for (int ks = 0; ks < 4; ks++) {
                const int kb = ks*32;
                uint32_t ah[2][4], al2[2][4], bh[2][4], bl[2][4];
#pragma unroll
                for (int im = 0; im < 2; im++) {
                    int row = parow + im*16;
                    uint32_t off = (uint32_t)(row*128 + kb + pakb) ^ ((row & 7) << 4);
                    ldsm4(ah[im],  sb + FL_KRH + ch*16384 + off);
                    ldsm4(al2[im], sb + FL_KRL + ch*16384 + off);
                }
#pragma unroll
                for (int np = 0; np < 2; np++) {
                    int row = pbrow + np*16;
                    uint32_t off = (uint32_t)(row*128 + kb + pbkb) ^ ((row & 7) << 4);
                    ldsm4(bh[np], sb + FL_KH  + ch*8192 + off);
                    ldsm4(bl[np], sb + FL_KLO + ch*8192 + off);
                }
#pragma unroll
                for (int im = 0; im < 2; im++)
#pragma unroll
                    for (int in = 0; in < 4; in++) {
                        const int np = in >> 1, hfx = (in & 1)*2;
                        mma16816(acc_o[im][in], ah[im],  bh[np][hfx], bh[np][hfx+1]);
                        mma16816(acc_o[im][in], ah[im],  bl[np][hfx], bl[np][hfx+1]);
                        mma16816(acc_o[im][in], al2[im], bh[np][hfx], bh[np][hfx+1]);
                    }
            }
        }
        __syncthreads();
    }

#pragma unroll
    for (int im = 0; im < 2; im++) {
        int r0 = prb + im*16;
        float inv0 = 1.f / l_s[r0], inv1 = 1.f / l_s[r0 + 8];
#pragma unroll
        for (int in = 0; in < 4; in++) {
            int col = pcb + in*8;
            float v0 = acc_o[im][in][0]*inv0, v1 = acc_o[im][in][1]*inv0;
            float v2 = acc_o[im][in][2]*inv1, v3 = acc_o[im][in][3]*inv1;
            size_t m0i = ((size_t)(i0 + r0)*2 + b)*DM + n*DH + col;
            size_t m1i = ((size_t)(i0 + r0 + 8)*2 + b)*DM + n*DH + col;
            __nv_bfloat16 h0 = __float2bfloat16(v0), h1 = __float2bfloat16(v1);
            __nv_bfloat16 h2 = __float2bfloat16(v2), h3 = __float2bfloat16(v3);
            *(__nv_bfloat162*)(Oh + m0i) = __nv_bfloat162(h0, h1);
            *(__nv_bfloat162*)(Oh + m1i) = __nv_bfloat162(h2, h3);
            *(__nv_bfloat162*)(Ol + m0i) = __nv_bfloat162(
                __float2bfloat16(v0 - __bfloat162float(h0)), __float2bfloat16(v1 - __bfloat162float(h1)));
            *(__nv_bfloat162*)(Ol + m1i) = __nv_bfloat162(
                __float2bfloat16(v2 - __bfloat162float(h2)), __float2bfloat16(v3 - __bfloat162float(h3)));
        }
    }
}

// ---------------- residual + LayerNorm ----------------
template<int WB16>
__global__ void __launch_bounds__(256) add_ln(
    const float* __restrict__ a, const float* __restrict__ x,
    const float* __restrict__ gamma, const float* __restrict__ beta,
    float* __restrict__ out, __nv_bfloat16* __restrict__ oh, __nv_bfloat16* __restrict__ ol)
{
    __shared__ float buf[1024];
    __shared__ float red[8];
    __shared__ float s_stat;
    const size_t base = (size_t)blockIdx.x << 10;
    const int t = threadIdx.x, lane = t & 31, w = t >> 5;
    float sum = 0.f;
#pragma unroll
    for (int p = 0; p < 4; p++) {
        float v = a[base + t + p*256] + x[base + t + p*256];
        buf[t + p*256] = v; sum += v;
    }
#pragma unroll
    for (int o = 16; o; o >>= 1) sum += __shfl_xor_sync(0xffffffffu, sum, o);
    if (!lane) red[w] = sum;
    __syncthreads();
    if (t == 0) { float s = 0; for (int i = 0; i < 8; i++) s += red[i]; s_stat = s * (1.0f/1024.0f); }
    __syncthreads();
    const float mean = s_stat;
    float vs = 0.f;
#pragma unroll
    for (int p = 0; p < 4; p++) { float d = buf[t + p*256] - mean; vs += d*d; }
#pragma unroll
    for (int o = 16; o; o >>= 1) vs += __shfl_xor_sync(0xffffffffu, vs, o);
    __syncthreads();
    if (!lane) red[w] = vs;
    __syncthreads();
    if (t == 0) { float s = 0; for (int i = 0; i < 8; i++) s += red[i]; s_stat = s * (1.0f/1024.0f); }
    __syncthreads();
    const float r = rsqrtf(s_stat + 1e-12f);
#pragma unroll
    for (int p = 0; p < 4; p++) {
        int c = t + p*256;
        float val = (buf[c] - mean) * r * gamma[c] + beta[c];
        out[base + c] = val;
        if (WB16) {
            __nv_bfloat16 hh = __float2bfloat16(val);
            oh[base + c] = hh;
            ol[base + c] = __float2bfloat16(val - __bfloat162float(hh));
        }
    }
}

// ---------------- host ----------------
extern "C" void kernel_launch(void* const* d_in, const int* in_sizes, int n_in,
                              void* d_out, int out_size)
{
    (void)in_sizes; (void)n_in; (void)out_size;
    const float* h       = (const float*)d_in[0];
    const float* g       = (const float*)d_in[1];
    const float* r       = (const float*)d_in[2];
    const float* seg_mat = (const float*)d_in[5];
    const float* wq      = (const float*)d_in[6];
    const float* wk      = (const float*)d_in[7];
    const float* wv      = (const float*)d_in[8];
    const float* wo      = (const float*)d_in[9];
    const float* wr      = (const float*)d_in[10];
    const float* rwb     = (const float*)d_in[11];
    const float* rrb     = (const float*)d_in[12];
    const float* rsb     = (const float*)d_in[13];
    const float* se      = (const float*)d_in[14];
    const float* lnga    = (const float*)d_in[15];
    const float* lnba    = (const float*)d_in[16];
    const float* w1      = (const float*)d_in[17];
    const float* b1      = (const float*)d_in[18];
    const float* w2      = (const float*)d_in[19];
    const float* b2      = (const float*)d_in[20];
    const float* lngf    = (const float*)d_in[21];
    const float* lnbf    = (const float*)d_in[22];

    cudaFuncSetAttribute(gemm_mma<0,0>, cudaFuncAttributeMaxDynamicSharedMemorySize, GSMEM_BYTES);
    cudaFuncSetAttribute(gemm_mma<0,2>, cudaFuncAttributeMaxDynamicSharedMemorySize, GSMEM_BYTES);
    cudaFuncSetAttribute(gemm_mma<2,1>, cudaFuncAttributeMaxDynamicSharedMemorySize, GSMEM_BYTES);
    cudaFuncSetAttribute(gemm_mma<1,0>, cudaFuncAttributeMaxDynamicSharedMemorySize, GSMEM_BYTES);
    cudaFuncSetAttribute(flash_attn,    cudaFuncAttributeMaxDynamicSharedMemorySize, FL_SMEM);

    float *q,*q2,*k,*v,*kr,*ef,*o,*y,*z,*bkT,*bkrT;
    __nv_bfloat16 *Ah,*Al,*wqT,*wkT,*wvT,*wrT,*woC,*w1T,*w2T,*diffb;
    __nv_bfloat16 *q1h,*q1l,*q2h,*q2l,*khh,*khl,*krh,*krl,*vth,*vtl,*ath,*atl,*yh,*yl,*th,*tl;
    cudaGetSymbolAddress((void**)&q,    g_q);
    cudaGetSymbolAddress((void**)&q2,   g_q2);
    cudaGetSymbolAddress((void**)&k,    g_k);
    cudaGetSymbolAddress((void**)&v,    g_v);
    cudaGetSymbolAddress((void**)&kr,   g_kr);
    cudaGetSymbolAddress((void**)&ef,   g_ef);
    cudaGetSymbolAddress((void**)&o,    g_o);
    cudaGetSymbolAddress((void**)&y,    g_y);
    cudaGetSymbolAddress((void**)&z,    g_z);
    cudaGetSymbolAddress((void**)&bkT,  g_bkT);
    cudaGetSymbolAddress((void**)&bkrT, g_bkrT);
    cudaGetSymbolAddress((void**)&diffb,g_diffb);
    cudaGetSymbolAddress((void**)&Ah,   g_Ah);
    cudaGetSymbolAddress((void**)&Al,   g_Al);
    cudaGetSymbolAddress((void**)&wqT,  g_wqT);
    cudaGetSymbolAddress((void**)&wkT,  g_wkT);
    cudaGetSymbolAddress((void**)&wvT,  g_wvT);
    cudaGetSymbolAddress((void**)&wrT,  g_wrT);
    cudaGetSymbolAddress((void**)&woC,  g_woC);
    cudaGetSymbolAddress((void**)&w1T,  g_w1T);
    cudaGetSymbolAddress((void**)&w2T,  g_w2T);
    cudaGetSymbolAddress((void**)&q1h,  g_q1h);
    cudaGetSymbolAddress((void**)&q1l,  g_q1l);
    cudaGetSymbolAddress((void**)&q2h,  g_q2h);
    cudaGetSymbolAddress((void**)&q2l,  g_q2l);
    cudaGetSymbolAddress((void**)&khh,  g_khh);
    cudaGetSymbolAddress((void**)&khl,  g_khl);
    cudaGetSymbolAddress((void**)&krh,  g_krh);
    cudaGetSymbolAddress((void**)&krl,  g_krl);
    cudaGetSymbolAddress((void**)&vth,  g_vth);
    cudaGetSymbolAddress((void**)&vtl,  g_vtl);
    cudaGetSymbolAddress((void**)&ath,  g_ath);
    cudaGetSymbolAddress((void**)&atl,  g_atl);
    cudaGetSymbolAddress((void**)&yh,   g_yh);
    cudaGetSymbolAddress((void**)&yl,   g_yl);
    cudaGetSymbolAddress((void**)&th,   g_th);
    cudaGetSymbolAddress((void**)&tl,   g_tl);

    dim3 tb(32, 8);
    convT_split<<<dim3(DM/32, DM/32), tb>>>(wq, wqT, wqT + (size_t)DM*DM, DM, DM);
    convT_split<<<dim3(DM/32, DM/32), tb>>>(wk, wkT, wkT + (size_t)DM*DM, DM, DM);
    convT_split<<<dim3(DM/32, DM/32), tb>>>(wv, wvT, wvT + (size_t)DM*DM, DM, DM);
    convT_split<<<dim3(DM/32, DM/32), tb>>>(wr, wrT, wrT + (size_t)DM*DM, DM, DM);
    conv_split<<<(DM*DM/4 + 255)/256, 256>>>(wo, woC, woC + (size_t)DM*DM, DM*DM/4);
    convT_split<<<dim3(DI/32, DM/32), tb>>>(w1, w1T, w1T + (size_t)DM*DI, DM, DI);
    convT_split<<<dim3(DM/32, DI/32), tb>>>(w2, w2T, w2T + (size_t)DI*DM, DI, DM);
    prep_diff<<<(2*QL*QL + 255)/256, 256>>>(seg_mat, diffb);

    // projections (fp32 C + head-major bf16 hi/lo)
    conv_split<<<(M2*DM/4 + 255)/256, 256>>>(h, Ah, Al, M2*DM/4);
    gemm_mma<0,2><<<dim3(8,16), 256, GSMEM_BYTES>>>(Ah, Al, wkT, wkT+(size_t)DM*DM, nullptr, k,  khh, khl, QL, DM, DM);
    gemm_mma<0,2><<<dim3(8,16), 256, GSMEM_BYTES>>>(Ah, Al, wvT, wvT+(size_t)DM*DM, nullptr, v,  khh, khl, QL, DM, DM); // bf16 dest overwritten below
    repack_vT<<<dim3(QL/32, DH/32, 32), tb>>>(v, vth, vtl);
    gemm_mma<0,2><<<dim3(8,16), 256, GSMEM_BYTES>>>(Ah, Al, wkT, wkT+(size_t)DM*DM, nullptr, k,  khh, khl, QL, DM, DM);
    gemm_mma<0,2><<<dim3(8,16), 256, GSMEM_BYTES>>>(Ah, Al, wqT, wqT+(size_t)DM*DM, nullptr, q,  q1h, q1l, QL, DM, DM);
    conv_split<<<(MR*DM/4 + 255)/256, 256>>>(r, Ah, Al, MR*DM/4);
    gemm_mma<0,2><<<dim3(8,32), 256, GSMEM_BYTES>>>(Ah, Al, wrT, wrT+(size_t)DM*DM, nullptr, kr, krh, krl, RL, DM, DM);
    conv_split<<<(M2*DM/4 + 255)/256, 256>>>(g, Ah, Al, M2*DM/4);
    gemm_mma<0,2><<<dim3(8,16), 256, GSMEM_BYTES>>>(Ah, Al, wqT, wqT+(size_t)DM*DM, nullptr, q2, q2h, q2l, QL, DM, DM);

    bias_dotT<<<(M2*NH*32 + 255)/256, 256>>>(k,  rwb, bkT,  QL);
    bias_dotT<<<(MR*NH*32 + 255)/256, 256>>>(kr, rrb, bkrT, RL);

    float* out_h = (float*)d_out;
    float* out_g = out_h + (size_t)M2*DM;

    for (int s = 0; s < 2; s++) {
        const float* x = s ? g : h;
        const float* qs = s ? q2 : q;
        const __nv_bfloat16* qh = s ? q2h : q1h;
        const __nv_bfloat16* ql = s ? q2l : q1l;
        float* outp = s ? out_g : out_h;

        ef_kernel<<<(M2*NH*32 + 255)/256, 256>>>(qs, rsb, se, ef);
        flash_attn<<<dim3(8, 32), 256, FL_SMEM>>>(qh, ql, khh, khl, krh, krl, vth, vtl,
                                                  bkT, bkrT, ef, diffb, ath, atl, s);
        gemm_mma<0,0><<<dim3(8,16), 256, GSMEM_BYTES>>>(ath, atl, woC, woC+(size_t)DM*DM,
                                                        nullptr, o, nullptr, nullptr, QL, DM, DM);
        add_ln<1><<<M2, 256>>>(o, x, lnga, lnba, y, yh, yl);
        gemm_mma<2,1><<<dim3(32,16), 256, GSMEM_BYTES>>>(yh, yl, w1T, w1T+(size_t)DM*DI,
                                                         b1, nullptr, th, tl, QL, DM, DI);
        gemm_mma<1,0><<<dim3(8,16), 256, GSMEM_BYTES>>>(th, tl, w2T, w2T+(size_t)DI*DM,
                                                        b2, z, nullptr, nullptr, QL, DI, DM);
        add_ln<0><<<M2, 256>>>(z, y, lngf, lnbf, outp, nullptr, nullptr);
    }
}

// round 7
// speedup vs baseline: 1.3283x; 1.3283x over previous
#include <cuda_runtime.h>
#include <cuda_bf16.h>
#include <math.h>
#include <stdint.h>

#define QL 1024
#define NH 16
#define DH 64
#define DM 1024
#define DI 4096
#define RL 2048
#define M2 (QL*2)
#define MR (RL*2)
#define ATT_SCALE 0.125f
#define SSTR ((size_t)32*QL*QL)   // per-stream S / P stride
#define BSTR ((size_t)32*QL*RL)   // per-stream BD stride

__device__ __forceinline__ uint32_t smem_u32(const void* p) {
    uint32_t a;
    asm("{ .reg .u64 t; cvta.to.shared.u64 t, %1; cvt.u32.u64 %0, t; }" : "=r"(a) : "l"(p));
    return a;
}
__device__ __forceinline__ void cp16(uint32_t dst, const void* src) {
    asm volatile("cp.async.cg.shared.global [%0], [%1], 16;" :: "r"(dst), "l"(src));
}
__device__ __forceinline__ void cp_commit() { asm volatile("cp.async.commit_group;" ::: "memory"); }
__device__ __forceinline__ void ldsm4(uint32_t (&r)[4], uint32_t addr) {
    asm volatile("ldmatrix.sync.aligned.m8n8.x4.shared.b16 {%0,%1,%2,%3}, [%4];"
        : "=r"(r[0]), "=r"(r[1]), "=r"(r[2]), "=r"(r[3]) : "r"(addr));
}
__device__ __forceinline__ void mma16816(float (&d)[4], const uint32_t (&a)[4],
                                         uint32_t b0, uint32_t b1) {
    asm volatile("mma.sync.aligned.m16n8k16.row.col.f32.bf16.bf16.f32 "
        "{%0,%1,%2,%3},{%4,%5,%6,%7},{%8,%9},{%0,%1,%2,%3};"
        : "+f"(d[0]), "+f"(d[1]), "+f"(d[2]), "+f"(d[3])
        : "r"(a[0]), "r"(a[1]), "r"(a[2]), "r"(a[3]), "r"(b0), "r"(b1));
}
__device__ __forceinline__ void bsplit(float v, __nv_bfloat16& h, __nv_bfloat16& l) {
    h = __float2bfloat16(v);
    l = __float2bfloat16(v - __bfloat162float(h));
}

// ---------------- scratch ----------------
__device__ float g_q [M2*DM];
__device__ float g_q2[M2*DM];
__device__ float g_k [M2*DM];
__device__ float g_v [M2*DM];
__device__ float g_kr[MR*DM];
__device__ float g_ef[2*M2*NH*2];
__device__ float g_o [2*M2*DM];
__device__ float g_y [2*M2*DM];
__device__ float g_z [2*M2*DM];
__device__ float g_bkT [32*QL];
__device__ float g_bkrT[32*RL];
__device__ float g_S [2*SSTR];
__device__ float g_BD[2*BSTR];
__device__ __align__(256) __nv_bfloat16 g_diffb[(size_t)2*QL*QL];
__device__ __align__(256) __nv_bfloat16 g_Ah [MR*DM], g_Al [MR*DM];
__device__ __align__(256) __nv_bfloat16 g_wqT[2*DM*DM], g_wkT[2*DM*DM], g_wvT[2*DM*DM];
__device__ __align__(256) __nv_bfloat16 g_wrT[2*DM*DM], g_woC[2*DM*DM];
__device__ __align__(256) __nv_bfloat16 g_w1T[2*DM*DI], g_w2T[2*DI*DM];
__device__ __align__(256) __nv_bfloat16 g_q1h[32*QL*DH], g_q1l[32*QL*DH];
__device__ __align__(256) __nv_bfloat16 g_q2h[32*QL*DH], g_q2l[32*QL*DH];
__device__ __align__(256) __nv_bfloat16 g_khh[32*QL*DH], g_khl[32*QL*DH];
__device__ __align__(256) __nv_bfloat16 g_krh[32*RL*DH], g_krl[32*RL*DH];
__device__ __align__(256) __nv_bfloat16 g_vth[32*DH*QL], g_vtl[32*DH*QL];
__device__ __align__(256) __nv_bfloat16 g_Ph [2*SSTR], g_Pl [2*SSTR];
__device__ __align__(256) __nv_bfloat16 g_ath[2*M2*DM], g_atl[2*M2*DM];
__device__ __align__(256) __nv_bfloat16 g_yh [2*M2*DM], g_yl [2*M2*DM];
__device__ __align__(256) __nv_bfloat16 g_th [2*M2*DI], g_tl [2*M2*DI];

// ---------------- small kernels ----------------
__global__ void conv_split(const float* __restrict__ X, __nv_bfloat16* __restrict__ hi,
                           __nv_bfloat16* __restrict__ lo, int n4)
{
    int i = blockIdx.x * blockDim.x + threadIdx.x;
    if (i >= n4) return;
    float4 v = ((const float4*)X)[i];
    __nv_bfloat16 h0,h1,h2,h3,l0,l1,l2,l3;
    bsplit(v.x,h0,l0); bsplit(v.y,h1,l1); bsplit(v.z,h2,l2); bsplit(v.w,h3,l3);
    ((__nv_bfloat162*)hi)[2*i]   = __nv_bfloat162(h0,h1);
    ((__nv_bfloat162*)hi)[2*i+1] = __nv_bfloat162(h2,h3);
    ((__nv_bfloat162*)lo)[2*i]   = __nv_bfloat162(l0,l1);
    ((__nv_bfloat162*)lo)[2*i+1] = __nv_bfloat162(l2,l3);
}

__global__ void convT_split(const float* __restrict__ W, __nv_bfloat16* __restrict__ hi,
                            __nv_bfloat16* __restrict__ lo, int K, int N)
{
    __shared__ float t[32][33];
    int k0 = blockIdx.y * 32, n0 = blockIdx.x * 32;
    int tx = threadIdx.x, ty = threadIdx.y;
#pragma unroll
    for (int p = 0; p < 4; p++)
        t[ty + p*8][tx] = W[(size_t)(k0 + ty + p*8)*N + n0 + tx];
    __syncthreads();
#pragma unroll
    for (int p = 0; p < 4; p++) {
        __nv_bfloat16 h, l;
        bsplit(t[tx][ty + p*8], h, l);
        size_t o = (size_t)(n0 + ty + p*8)*K + k0 + tx;
        hi[o] = h; lo[o] = l;
    }
}

__global__ void repack_vT(const float* __restrict__ V, __nv_bfloat16* __restrict__ hi,
                          __nv_bfloat16* __restrict__ lo)
{
    __shared__ float tile[32][33];
    int j0 = blockIdx.x * 32, d0 = blockIdx.y * 32;
    int bn = blockIdx.z, b = bn >> 4, n = bn & 15;
    int tx = threadIdx.x, ty = threadIdx.y;
#pragma unroll
    for (int p = 0; p < 4; p++)
        tile[ty + p*8][tx] = V[((size_t)(j0 + ty + p*8)*2 + b)*DM + n*DH + d0 + tx];
    __syncthreads();
#pragma unroll
    for (int p = 0; p < 4; p++) {
        __nv_bfloat16 h, l;
        bsplit(tile[tx][ty + p*8], h, l);
        size_t o = ((size_t)bn*DH + d0 + ty + p*8)*QL + j0 + tx;
        hi[o] = h; lo[o] = l;
    }
}

__global__ void prep_diff(const float* __restrict__ seg_mat, __nv_bfloat16* __restrict__ diff)
{
    size_t idx = (size_t)blockIdx.x * blockDim.x + threadIdx.x;
    if (idx >= (size_t)2*QL*QL) return;
    int j = idx & 1023, i = (idx >> 10) & 1023, b = (int)(idx >> 20);
    diff[idx] = __float2bfloat16(seg_mat[(((size_t)i*QL + j)*2 + b)*2 + 1]);
}

__global__ void bias_dotT(const float* __restrict__ X, const float* __restrict__ bias,
                          float* __restrict__ outT, int rowsPerB)
{
    const int gw = (blockIdx.x * blockDim.x + threadIdx.x) >> 5;
    const int lane = threadIdx.x & 31;
    if (gw >= rowsPerB * 2 * NH) return;
    const int row = gw >> 4, n = gw & 15;
    const int j = row >> 1, b = row & 1;
    float s = bias[n*DH + lane]      * X[(size_t)row*DM + n*DH + lane]
            + bias[n*DH + 32 + lane] * X[(size_t)row*DM + n*DH + 32 + lane];
#pragma unroll
    for (int o = 16; o; o >>= 1) s += __shfl_xor_sync(0xffffffffu, s, o);
    if (!lane) outT[(size_t)(b*16 + n)*rowsPerB + j] = s;
}

__global__ void ef_kernel(const float* __restrict__ q, const float* __restrict__ rsb,
                          const float* __restrict__ se, float* __restrict__ ef)
{
    const int gw = (blockIdx.x * blockDim.x + threadIdx.x) >> 5;
    const int lane = threadIdx.x & 31;
    if (gw >= M2 * NH) return;
    const int row = gw >> 4, n = gw & 15;
    const float v0 = q[(size_t)row*DM + n*DH + lane]      + rsb[n*DH + lane];
    const float v1 = q[(size_t)row*DM + n*DH + 32 + lane] + rsb[n*DH + 32 + lane];
    float s0 = v0*se[n*DH + lane] + v1*se[n*DH + 32 + lane];
    float s1 = v0*se[NH*DH + n*DH + lane] + v1*se[NH*DH + n*DH + 32 + lane];
#pragma unroll
    for (int o = 16; o; o >>= 1) {
        s0 += __shfl_xor_sync(0xffffffffu, s0, o);
        s1 += __shfl_xor_sync(0xffffffffu, s1, o);
    }
    if (!lane) { ef[gw*2] = s0; ef[gw*2 + 1] = s1; }
}

// ---------------- dense split-bf16 GEMM; z = stream ----------------
#define GSTAGE 65536
#define GSMEM_BYTES (2*GSTAGE)

__device__ __forceinline__ void g_load_stage(
    const __nv_bfloat16* __restrict__ Ah, const __nv_bfloat16* __restrict__ Al,
    const __nv_bfloat16* __restrict__ Bh, const __nv_bfloat16* __restrict__ Bl,
    uint32_t st, int m0, int n0, int K, int kc, int tid)
{
    const size_t ko = (size_t)kc * 64;
#pragma unroll
    for (int p = 0; p < 4; p++) {
        int c = p*256 + tid;
        int row = c >> 3, kcol = c & 7;
        uint32_t sw = (uint32_t)(row*128 + kcol*16) ^ ((row & 7) << 4);
        const size_t ga = (size_t)(m0 + row)*K + ko + kcol*8;
        const size_t gb = (size_t)(n0 + row)*K + ko + kcol*8;
        cp16(st + sw,         Ah + ga);
        cp16(st + 16384 + sw, Al + ga);
        cp16(st + 32768 + sw, Bh + gb);
        cp16(st + 49152 + sw, Bl + gb);
    }
    cp_commit();
}

template<int EPI, int OUT>   // OUT: 0 fp32, 1 bf16 hi/lo row-major, 2 fp32 + head-major bf16
__global__ void __launch_bounds__(256, 1) gemm_mma(
    const __nv_bfloat16* __restrict__ Ah, const __nv_bfloat16* __restrict__ Al,
    const __nv_bfloat16* __restrict__ Bh, const __nv_bfloat16* __restrict__ Bl,
    const float* __restrict__ bias, float* __restrict__ C,
    __nv_bfloat16* __restrict__ Chi, __nv_bfloat16* __restrict__ Clo,
    size_t zsA, size_t zsC, int rowsPerB, int K, int ldc)
{
    extern __shared__ char dsm[];
    const uint32_t sbase = smem_u32(dsm);
    const int tid = threadIdx.x, lane = tid & 31, warp = tid >> 5;
    const size_t zo = blockIdx.z;
    Ah += zo*zsA; Al += zo*zsA;
    if (OUT != 1) C += zo*zsC;
    if (OUT >= 1) { Chi += zo*zsC; Clo += zo*zsC; }
    const int m0 = blockIdx.y * 128, n0 = blockIdx.x * 128;
    const int wm = (warp & 1) * 64, wn = (warp >> 1) * 32;
    const int NC = K >> 6;

    float acc[4][4][4] = {};
    g_load_stage(Ah, Al, Bh, Bl, sbase,          m0, n0, K, 0, tid);
    g_load_stage(Ah, Al, Bh, Bl, sbase + GSTAGE, m0, n0, K, 1, tid);
    asm volatile("cp.async.wait_group 1;" ::: "memory");
    __syncthreads();

    const int arow = wm + (lane & 15), akb = lane & 16;
    const int brow = wn + ((lane & 16) >> 1) + (lane & 7), bkb = (lane & 8) << 1;

    for (int kc = 0; kc < NC; kc++) {
        const uint32_t st = sbase + (kc & 1) * GSTAGE;
#pragma unroll
        for (int ks = 0; ks < 4; ks++) {
            const int kb = ks*32;
            uint32_t ah[4][4], al[4][4], bh[2][4], bl[2][4];
#pragma unroll
            for (int im = 0; im < 4; im++) {
                int row = arow + im*16;
                uint32_t off = (uint32_t)(row*128 + kb + akb) ^ ((row & 7) << 4);
                ldsm4(ah[im], st + off);
                ldsm4(al[im], st + 16384 + off);
            }
#pragma unroll
            for (int np = 0; np < 2; np++) {
                int row = brow + np*16;
                uint32_t off = (uint32_t)(row*128 + kb + bkb) ^ ((row & 7) << 4);
                ldsm4(bh[np], st + 32768 + off);
                ldsm4(bl[np], st + 49152 + off);
            }
#pragma unroll
            for (int im = 0; im < 4; im++)
#pragma unroll
                for (int in = 0; in < 4; in++) {
                    const int np = in >> 1, hf = (in & 1) * 2;
                    mma16816(acc[im][in], ah[im], bh[np][hf], bh[np][hf+1]);
                    mma16816(acc[im][in], ah[im], bl[np][hf], bl[np][hf+1]);
                    mma16816(acc[im][in], al[im], bh[np][hf], bh[np][hf+1]);
                }
        }
        __syncthreads();
        if (kc + 2 < NC) {
            g_load_stage(Ah, Al, Bh, Bl, sbase + (kc & 1)*GSTAGE, m0, n0, K, kc + 2, tid);
            asm volatile("cp.async.wait_group 1;" ::: "memory");
        } else {
            asm volatile("cp.async.wait_group 0;" ::: "memory");
        }
        __syncthreads();
    }

    const int rbase = m0 + wm + (lane >> 2);
    const int cbase = n0 + wn + 2*(lane & 3);
#pragma unroll
    for (int im = 0; im < 4; im++) {
#pragma unroll
        for (int in = 0; in < 4; in++) {
            int col = cbase + in*8;
            float v0 = acc[im][in][0], v1 = acc[im][in][1];
            float v2 = acc[im][in][2], v3 = acc[im][in][3];
            if (EPI >= 1) {
                float b0 = bias[col], b1 = bias[col+1];
                v0 += b0; v1 += b1; v2 += b0; v3 += b1;
            }
            if (EPI == 2) {
                v0 = 0.5f*v0*(1.0f + erff(v0*0.7071067811865476f));
                v1 = 0.5f*v1*(1.0f + erff(v1*0.7071067811865476f));
                v2 = 0.5f*v2*(1.0f + erff(v2*0.7071067811865476f));
                v3 = 0.5f*v3*(1.0f + erff(v3*0.7071067811865476f));
            }
            int r0 = rbase + im*16, r1 = r0 + 8;
            if (OUT != 1) {
                *(float2*)(C + (size_t)r0*ldc + col) = make_float2(v0, v1);
                *(float2*)(C + (size_t)r1*ldc + col) = make_float2(v2, v3);
            }
            if (OUT >= 1) {
                __nv_bfloat16 h0,h1,h2,h3,l0,l1,l2,l3;
                bsplit(v0,h0,l0); bsplit(v1,h1,l1); bsplit(v2,h2,l2); bsplit(v3,h3,l3);
                size_t d0, d1;
                if (OUT == 1) { d0 = (size_t)r0*ldc + col; d1 = (size_t)r1*ldc + col; }
                else {
                    int nh = col >> 6, d = col & 63;
                    d0 = (((size_t)(r0 & 1)*NH + nh)*rowsPerB + (r0 >> 1))*DH + d;
                    d1 = (((size_t)(r1 & 1)*NH + nh)*rowsPerB + (r1 >> 1))*DH + d;
                }
                *(__nv_bfloat162*)(Chi + d0) = __nv_bfloat162(h0, h1);
                *(__nv_bfloat162*)(Chi + d1) = __nv_bfloat162(h2, h3);
                *(__nv_bfloat162*)(Clo + d0) = __nv_bfloat162(l0, l1);
                *(__nv_bfloat162*)(Clo + d1) = __nv_bfloat162(l2, l3);
            }
        }
    }
}

// ---------------- batched score GEMM (z = s*32+bn) ----------------
#define SC_SMEM 65536

__global__ void __launch_bounds__(256, 1) score_mma(
    const __nv_bfloat16* __restrict__ Q1h, const __nv_bfloat16* __restrict__ Q1l,
    const __nv_bfloat16* __restrict__ Q2h, const __nv_bfloat16* __restrict__ Q2l,
    const __nv_bfloat16* __restrict__ Kh, const __nv_bfloat16* __restrict__ Kl,
    const float* __restrict__ biasT, float* __restrict__ C,
    size_t zsC, int Ncols, int window)
{
    extern __shared__ char dsm[];
    const uint32_t st = smem_u32(dsm);
    const int tid = threadIdx.x, lane = tid & 31, warp = tid >> 5;
    const int zz = blockIdx.z, s = zz >> 5, bn = zz & 31;
    const __nv_bfloat16* Qh = s ? Q2h : Q1h;
    const __nv_bfloat16* Ql = s ? Q2l : Q1l;
    C += (size_t)s * zsC;
    const int i0 = blockIdx.y * 128;
    int ct = window ? (7 - (int)blockIdx.y + (int)blockIdx.x) : (int)blockIdx.x;
    const int j0 = ct * 128;

    const size_t qb = ((size_t)bn*QL + i0)*DH;
    const size_t kb = ((size_t)bn*Ncols + j0)*DH;
#pragma unroll
    for (int p = 0; p < 4; p++) {
        int c = p*256 + tid;
        int row = c >> 3, kcol = c & 7;
        uint32_t sw = (uint32_t)(row*128 + kcol*16) ^ ((row & 7) << 4);
        cp16(st + sw,         Qh + qb + (size_t)row*DH + kcol*8);
        cp16(st + 16384 + sw, Ql + qb + (size_t)row*DH + kcol*8);
        cp16(st + 32768 + sw, Kh + kb + (size_t)row*DH + kcol*8);
        cp16(st + 49152 + sw, Kl + kb + (size_t)row*DH + kcol*8);
    }
    cp_commit();
    asm volatile("cp.async.wait_group 0;" ::: "memory");
    __syncthreads();

    const int wm = (warp & 1) * 64, wn = (warp >> 1) * 32;
    const int arow = wm + (lane & 15), akb = lane & 16;
    const int brow = wn + ((lane & 16) >> 1) + (lane & 7), bkb = (lane & 8) << 1;

    float acc[4][4][4] = {};
#pragma unroll
    for (int ks = 0; ks < 4; ks++) {
        const int kbyte = ks*32;
        uint32_t ah[4][4], al[4][4], bh[2][4], bl[2][4];
#pragma unroll
        for (int im = 0; im < 4; im++) {
            int row = arow + im*16;
            uint32_t off = (uint32_t)(row*128 + kbyte + akb) ^ ((row & 7) << 4);
            ldsm4(ah[im], st + off);
            ldsm4(al[im], st + 16384 + off);
        }
#pragma unroll
        for (int np = 0; np < 2; np++) {
            int row = brow + np*16;
            uint32_t off = (uint32_t)(row*128 + kbyte + bkb) ^ ((row & 7) << 4);
            ldsm4(bh[np], st + 32768 + off);
            ldsm4(bl[np], st + 49152 + off);
        }
#pragma unroll
        for (int im = 0; im < 4; im++)
#pragma unroll
            for (int in = 0; in < 4; in++) {
                const int np = in >> 1, hf = (in & 1) * 2;
                mma16816(acc[im][in], ah[im], bh[np][hf], bh[np][hf+1]);
                mma16816(acc[im][in], ah[im], bl[np][hf], bl[np][hf+1]);
                mma16816(acc[im][in], al[im], bh[np][hf], bh[np][hf+1]);
            }
    }

    float* Cb = C + (size_t)bn*QL*Ncols;
    const float* bt = biasT + (size_t)bn*Ncols;
    const int rbase = i0 + wm + (lane >> 2);
    const int cbase = j0 + wn + 2*(lane & 3);
#pragma unroll
    for (int im = 0; im < 4; im++)
#pragma unroll
        for (int in = 0; in < 4; in++) {
            int col = cbase + in*8;
            float b0 = bt[col], b1 = bt[col+1];
            int r0 = rbase + im*16, r1 = r0 + 8;
            *(float2*)(Cb + (size_t)r0*Ncols + col) =
                make_float2(acc[im][in][0] + b0, acc[im][in][1] + b1);
            *(float2*)(Cb + (size_t)r1*Ncols + col) =
                make_float2(acc[im][in][2] + b0, acc[im][in][3] + b1);
        }
}

// ---------------- fused combine + softmax (analytic mask) + bf16-split P ----------------
__global__ void __launch_bounds__(256) softmax_fused(
    const float* __restrict__ S, const float* __restrict__ BD,
    const __nv_bfloat16* __restrict__ diff, const float* __restrict__ ef,
    __nv_bfloat16* __restrict__ Ph, __nv_bfloat16* __restrict__ Pl)
{
    __shared__ float red[8];
    const int i = blockIdx.x;
    const int zz = blockIdx.y, s = zz >> 5, bn = zz & 31, b = bn >> 4, n = bn & 15;
    const float* Sr = S    + (size_t)s*SSTR + ((size_t)bn << 20) + ((size_t)i << 10);
    const float* Br = BD   + (size_t)s*BSTR + ((size_t)bn << 21) + ((size_t)i << 11) + (QL - i);
    const __nv_bfloat16* Dr = diff + ((size_t)b << 20) + ((size_t)i << 10);
    const float* efs = ef + (size_t)s*M2*NH*2;
    const float e0 = efs[(((size_t)i*2 + b)*NH + n)*2];
    const float de = efs[(((size_t)i*2 + b)*NH + n)*2 + 1] - e0;
    const int t = threadIdx.x, lane = t & 31, w = t >> 5;

    float v[4];
#pragma unroll
    for (int p = 0; p < 4; p++) {
        int j = t + p*256;
        float sc = (Sr[j] + Br[j] + e0 + de*__bfloat162float(Dr[j])) * ATT_SCALE;
        bool blocked = s ? (j >= i) : (j > i);
        v[p] = blocked ? sc - 1e30f : sc;
    }
    float m = fmaxf(fmaxf(v[0], v[1]), fmaxf(v[2], v[3]));
#pragma unroll
    for (int o = 16; o; o >>= 1) m = fmaxf(m, __shfl_xor_sync(0xffffffffu, m, o));
    if (!lane) red[w] = m;
    __syncthreads();
    m = red[lane & 7];
#pragma unroll
    for (int o = 4; o; o >>= 1) m = fmaxf(m, __shfl_xor_sync(0xffffffffu, m, o));
    float sum = 0.f;
#pragma unroll
    for (int p = 0; p < 4; p++) { v[p] = expf(v[p] - m); sum += v[p]; }
#pragma unroll
    for (int o = 16; o; o >>= 1) sum += __shfl_xor_sync(0xffffffffu, sum, o);
    __syncthreads();
    if (!lane) red[w] = sum;
    __syncthreads();
    sum = red[lane & 7];
#pragma unroll
    for (int o = 4; o; o >>= 1) sum += __shfl_xor_sync(0xffffffffu, sum, o);
    const float inv = 1.0f / sum;
    const size_t base = (size_t)s*SSTR + ((size_t)bn << 20) + ((size_t)i << 10);
#pragma unroll
    for (int p = 0; p < 4; p++) {
        int j = t + p*256;
        __nv_bfloat16 ph, pl;
        bsplit(v[p] * inv, ph, pl);
        Ph[base + j] = ph;
        Pl[base + j] = pl;
    }
}

// ---------------- batched PV GEMM -> bf16 hi/lo attn ----------------
#define PV_STAGE 49152
#define PV_SMEM (2*PV_STAGE)

__device__ __forceinline__ void pv_load(
    const __nv_bfloat16* __restrict__ Ph, const __nv_bfloat16* __restrict__ Pl,
    const __nv_bfloat16* __restrict__ Vh, const __nv_bfloat16* __restrict__ Vl,
    uint32_t st, size_t pbase, size_t vbase, int kc, int tid)
{
    const size_t ko = (size_t)kc * 64;
#pragma unroll
    for (int p = 0; p < 4; p++) {
        int c = p*256 + tid;
        int row = c >> 3, kcol = c & 7;
        uint32_t sw = (uint32_t)(row*128 + kcol*16) ^ ((row & 7) << 4);
        cp16(st + sw,         Ph + pbase + (size_t)row*QL + ko + kcol*8);
        cp16(st + 16384 + sw, Pl + pbase + (size_t)row*QL + ko + kcol*8);
    }
#pragma unroll
    for (int p = 0; p < 2; p++) {
        int c = p*256 + tid;
        int row = c >> 3, kcol = c & 7;
        uint32_t sw = (uint32_t)(row*128 + kcol*16) ^ ((row & 7) << 4);
        cp16(st + 32768 + sw, Vh + vbase + (size_t)row*QL + ko + kcol*8);
        cp16(st + 40960 + sw, Vl + vbase + (size_t)row*QL + ko + kcol*8);
    }
    cp_commit();
}

__global__ void __launch_bounds__(256, 1) pv_mma(
    const __nv_bfloat16* __restrict__ Ph, const __nv_bfloat16* __restrict__ Pl,
    const __nv_bfloat16* __restrict__ Vh, const __nv_bfloat16* __restrict__ Vl,
    __nv_bfloat16* __restrict__ Oh, __nv_bfloat16* __restrict__ Ol)
{
    extern __shared__ char dsm[];
    const uint32_t sbase = smem_u32(dsm);
    const int tid = threadIdx.x, lane = tid & 31, warp = tid >> 5;
    const int zz = blockIdx.y, s = zz >> 5, bn = zz & 31, b = bn >> 4, n = bn & 15;
    const int i0 = blockIdx.x * 128;
    const size_t pbase = (size_t)s*SSTR + ((size_t)bn << 20) + (size_t)i0*QL;
    const size_t vbase = (size_t)bn * DH * QL;
    const size_t obase = (size_t)s * M2 * DM;

    float acc[2][4][4] = {};
    pv_load(Ph, Pl, Vh, Vl, sbase,            pbase, vbase, 0, tid);
    pv_load(Ph, Pl, Vh, Vl, sbase + PV_STAGE, pbase, vbase, 1, tid);
    asm volatile("cp.async.wait_group 1;" ::: "memory");
    __syncthreads();

    const int wm = (warp & 3) * 32, wn = (warp >> 2) * 32;
    const int arow = wm + (lane & 15), akb = lane & 16;
    const int brow = wn + ((lane & 16) >> 1) + (lane & 7), bkb = (lane & 8) << 1;

    for (int kc = 0; kc < 16; kc++) {
        const uint32_t st = sbase + (kc & 1) * PV_STAGE;
#pragma unroll
        for (int ks = 0; ks < 4; ks++) {
            const int kb = ks*32;
            uint32_t ah[2][4], al[2][4], bh[2][4], bl[2][4];
#pragma unroll
            for (int im = 0; im < 2; im++) {
                int row = arow + im*16;
                uint32_t off = (uint32_t)(row*128 + kb + akb) ^ ((row & 7) << 4);
                ldsm4(ah[im], st + off);
                ldsm4(al[im], st + 16384 + off);
            }
#pragma unroll
            for (int np = 0; np < 2; np++) {
                int row = brow + np*16;
                uint32_t off = (uint32_t)(row*128 + kb + bkb) ^ ((row & 7) << 4);
                ldsm4(bh[np], st + 32768 + off);
                ldsm4(bl[np], st + 40960 + off);
            }
#pragma unroll
            for (int im = 0; im < 2; im++)
#pragma unroll
                for (int in = 0; in < 4; in++) {
                    const int np = in >> 1, hf = (in & 1) * 2;
                    mma16816(acc[im][in], ah[im], bh[np][hf], bh[np][hf+1]);
                    mma16816(acc[im][in], ah[im], bl[np][hf], bl[np][hf+1]);
                    mma16816(acc[im][in], al[im], bh[np][hf], bh[np][hf+1]);
                }
        }
        __syncthreads();
        if (kc + 2 < 16) {
            pv_load(Ph, Pl, Vh, Vl, sbase + (kc & 1)*PV_STAGE, pbase, vbase, kc + 2, tid);
            asm volatile("cp.async.wait_group 1;" ::: "memory");
        } else {
            asm volatile("cp.async.wait_group 0;" ::: "memory");
        }
        __syncthreads();
    }

    const int rl = wm + (lane >> 2);
    const int cb = wn + 2*(lane & 3);
#pragma unroll
    for (int im = 0; im < 2; im++)
#pragma unroll
        for (int in = 0; in < 4; in++) {
            int col = cb + in*8;
            int r0 = i0 + rl + im*16, r1 = r0 + 8;
            size_t d0 = obase + ((size_t)r0*2 + b)*DM + n*DH + col;
            size_t d1 = obase + ((size_t)r1*2 + b)*DM + n*DH + col;
            __nv_bfloat16 h0,h1,h2,h3,l0,l1,l2,l3;
            bsplit(acc[im][in][0],h0,l0); bsplit(acc[im][in][1],h1,l1);
            bsplit(acc[im][in][2],h2,l2); bsplit(acc[im][in][3],h3,l3);
            *(__nv_bfloat162*)(Oh + d0) = __nv_bfloat162(h0, h1);
            *(__nv_bfloat162*)(Oh + d1) = __nv_bfloat162(h2, h3);
            *(__nv_bfloat162*)(Ol + d0) = __nv_bfloat162(l0, l1);
            *(__nv_bfloat162*)(Ol + d1) = __nv_bfloat162(l2, l3);
        }
}

// ---------------- residual + LayerNorm (merged streams) ----------------
template<int WB16>
__global__ void __launch_bounds__(256) add_ln(
    const float* __restrict__ a, const float* __restrict__ x0, const float* __restrict__ x1,
    const float* __restrict__ gamma, const float* __restrict__ beta,
    float* __restrict__ out, __nv_bfloat16* __restrict__ oh, __nv_bfloat16* __restrict__ ol)
{
    __shared__ float buf[1024];
    __shared__ float red[8];
    __shared__ float s_stat;
    const size_t base = (size_t)blockIdx.x << 10;
    const int str = blockIdx.x >> 11;
    const size_t lbase = (size_t)(blockIdx.x & 2047) << 10;
    const float* x = str ? x1 : x0;
    const int t = threadIdx.x, lane = t & 31, w = t >> 5;
    float sum = 0.f;
#pragma unroll
    for (int p = 0; p < 4; p++) {
        float v = a[base + t + p*256] + x[lbase + t + p*256];
        buf[t + p*256] = v; sum += v;
    }
#pragma unroll
    for (int o = 16; o; o >>= 1) sum += __shfl_xor_sync(0xffffffffu, sum, o);
    if (!lane) red[w] = sum;
    __syncthreads();
    if (t == 0) { float s = 0; for (int i = 0; i < 8; i++) s += red[i]; s_stat = s * (1.0f/1024.0f); }
    __syncthreads();
    const float mean = s_stat;
    float vs = 0.f;
#pragma unroll
    for (int p = 0; p < 4; p++) { float d = buf[t + p*256] - mean; vs += d*d; }
#pragma unroll
    for (int o = 16; o; o >>= 1) vs += __shfl_xor_sync(0xffffffffu, vs, o);
    __syncthreads();
    if (!lane) red[w] = vs;
    __syncthreads();
    if (t == 0) { float s = 0; for (int i = 0; i < 8; i++) s += red[i]; s_stat = s * (1.0f/1024.0f); }
    __syncthreads();
    const float r = rsqrtf(s_stat + 1e-12f);
#pragma unroll
    for (int p = 0; p < 4; p++) {
        int c = t + p*256;
        float val = (buf[c] - mean) * r * gamma[c] + beta[c];
        out[base + c] = val;
        if (WB16) {
            __nv_bfloat16 hh, ll;
            bsplit(val, hh, ll);
            oh[base + c] = hh;
            ol[base + c] = ll;
        }
    }
}

// ---------------- host ----------------
extern "C" void kernel_launch(void* const* d_in, const int* in_sizes, int n_in,
                              void* d_out, int out_size)
{
    (void)in_sizes; (void)n_in; (void)out_size;
    const float* h       = (const float*)d_in[0];
    const float* g       = (const float*)d_in[1];
    const float* r       = (const float*)d_in[2];
    const float* seg_mat = (const float*)d_in[5];
    const float* wq      = (const float*)d_in[6];
    const float* wk      = (const float*)d_in[7];
    const float* wv      = (const float*)d_in[8];
    const float* wo      = (const float*)d_in[9];
    const float* wr      = (const float*)d_in[10];
    const float* rwb     = (const float*)d_in[11];
    const float* rrb     = (const float*)d_in[12];
    const float* rsb     = (const float*)d_in[13];
    const float* se      = (const float*)d_in[14];
    const float* lnga    = (const float*)d_in[15];
    const float* lnba    = (const float*)d_in[16];
    const float* w1      = (const float*)d_in[17];
    const float* b1      = (const float*)d_in[18];
    const float* w2      = (const float*)d_in[19];
    const float* b2      = (const float*)d_in[20];
    const float* lngf    = (const float*)d_in[21];
    const float* lnbf    = (const float*)d_in[22];

    cudaFuncSetAttribute(gemm_mma<0,0>, cudaFuncAttributeMaxDynamicSharedMemorySize, GSMEM_BYTES);
    cudaFuncSetAttribute(gemm_mma<0,2>, cudaFuncAttributeMaxDynamicSharedMemorySize, GSMEM_BYTES);
    cudaFuncSetAttribute(gemm_mma<2,1>, cudaFuncAttributeMaxDynamicSharedMemorySize, GSMEM_BYTES);
    cudaFuncSetAttribute(gemm_mma<1,0>, cudaFuncAttributeMaxDynamicSharedMemorySize, GSMEM_BYTES);
    cudaFuncSetAttribute(score_mma,     cudaFuncAttributeMaxDynamicSharedMemorySize, SC_SMEM);
    cudaFuncSetAttribute(pv_mma,        cudaFuncAttributeMaxDynamicSharedMemorySize, PV_SMEM);

    float *q,*q2,*k,*v,*kr,*ef,*o,*y,*z,*bkT,*bkrT,*S,*BD;
    __nv_bfloat16 *Ah,*Al,*wqT,*wkT,*wvT,*wrT,*woC,*w1T,*w2T,*diffb;
    __nv_bfloat16 *q1h,*q1l,*q2h,*q2l,*khh,*khl,*krh,*krl,*vth,*vtl,*Ph,*Pl,*ath,*atl,*yh,*yl,*th,*tl;
    cudaGetSymbolAddress((void**)&q,    g_q);
    cudaGetSymbolAddress((void**)&q2,   g_q2);
    cudaGetSymbolAddress((void**)&k,    g_k);
    cudaGetSymbolAddress((void**)&v,    g_v);
    cudaGetSymbolAddress((void**)&kr,   g_kr);
    cudaGetSymbolAddress((void**)&ef,   g_ef);
    cudaGetSymbolAddress((void**)&o,    g_o);
    cudaGetSymbolAddress((void**)&y,    g_y);
    cudaGetSymbolAddress((void**)&z,    g_z);
    cudaGetSymbolAddress((void**)&bkT,  g_bkT);
    cudaGetSymbolAddress((void**)&bkrT, g_bkrT);
    cudaGetSymbolAddress((void**)&S,    g_S);
    cudaGetSymbolAddress((void**)&BD,   g_BD);
    cudaGetSymbolAddress((void**)&diffb,g_diffb);
    cudaGetSymbolAddress((void**)&Ah,   g_Ah);
    cudaGetSymbolAddress((void**)&Al,   g_Al);
    cudaGetSymbolAddress((void**)&wqT,  g_wqT);
    cudaGetSymbolAddress((void**)&wkT,  g_wkT);
    cudaGetSymbolAddress((void**)&wvT,  g_wvT);
    cudaGetSymbolAddress((void**)&wrT,  g_wrT);
    cudaGetSymbolAddress((void**)&woC,  g_woC);
    cudaGetSymbolAddress((void**)&w1T,  g_w1T);
    cudaGetSymbolAddress((void**)&w2T,  g_w2T);
    cudaGetSymbolAddress((void**)&q1h,  g_q1h);
    cudaGetSymbolAddress((void**)&q1l,  g_q1l);
    cudaGetSymbolAddress((void**)&q2h,  g_q2h);
    cudaGetSymbolAddress((void**)&q2l,  g_q2l);
    cudaGetSymbolAddress((void**)&khh,  g_khh);
    cudaGetSymbolAddress((void**)&khl,  g_khl);
    cudaGetSymbolAddress((void**)&krh,  g_krh);
    cudaGetSymbolAddress((void**)&krl,  g_krl);
    cudaGetSymbolAddress((void**)&vth,  g_vth);
    cudaGetSymbolAddress((void**)&vtl,  g_vtl);
    cudaGetSymbolAddress((void**)&Ph,   g_Ph);
    cudaGetSymbolAddress((void**)&Pl,   g_Pl);
    cudaGetSymbolAddress((void**)&ath,  g_ath);
    cudaGetSymbolAddress((void**)&atl,  g_atl);
    cudaGetSymbolAddress((void**)&yh,   g_yh);
    cudaGetSymbolAddress((void**)&yl,   g_yl);
    cudaGetSymbolAddress((void**)&th,   g_th);
    cudaGetSymbolAddress((void**)&tl,   g_tl);

    dim3 tb(32, 8);
    convT_split<<<dim3(DM/32, DM/32), tb>>>(wq, wqT, wqT + (size_t)DM*DM, DM, DM);
    convT_split<<<dim3(DM/32, DM/32), tb>>>(wk, wkT, wkT + (size_t)DM*DM, DM, DM);
    convT_split<<<dim3(DM/32, DM/32), tb>>>(wv, wvT, wvT + (size_t)DM*DM, DM, DM);
    convT_split<<<dim3(DM/32, DM/32), tb>>>(wr, wrT, wrT + (size_t)DM*DM, DM, DM);
    conv_split<<<(DM*DM/4 + 255)/256, 256>>>(wo, woC, woC + (size_t)DM*DM, DM*DM/4);
    convT_split<<<dim3(DI/32, DM/32), tb>>>(w1, w1T, w1T + (size_t)DM*DI, DM, DI);
    convT_split<<<dim3(DM/32, DI/32), tb>>>(w2, w2T, w2T + (size_t)DI*DM, DI, DM);
    prep_diff<<<(2*QL*QL + 255)/256, 256>>>(seg_mat, diffb);

    // projections
    conv_split<<<(M2*DM/4 + 255)/256, 256>>>(h, Ah, Al, M2*DM/4);
    gemm_mma<0,2><<<dim3(8,16,1), 256, GSMEM_BYTES>>>(Ah, Al, wkT, wkT+(size_t)DM*DM, nullptr, k,  khh, khl, 0, 0, QL, DM, DM);
    gemm_mma<0,0><<<dim3(8,16,1), 256, GSMEM_BYTES>>>(Ah, Al, wvT, wvT+(size_t)DM*DM, nullptr, v,  nullptr, nullptr, 0, 0, QL, DM, DM);
    repack_vT<<<dim3(QL/32, DH/32, 32), tb>>>(v, vth, vtl);
    gemm_mma<0,2><<<dim3(8,16,1), 256, GSMEM_BYTES>>>(Ah, Al, wqT, wqT+(size_t)DM*DM, nullptr, q,  q1h, q1l, 0, 0, QL, DM, DM);
    conv_split<<<(MR*DM/4 + 255)/256, 256>>>(r, Ah, Al, MR*DM/4);
    gemm_mma<0,2><<<dim3(8,32,1), 256, GSMEM_BYTES>>>(Ah, Al, wrT, wrT+(size_t)DM*DM, nullptr, kr, krh, krl, 0, 0, RL, DM, DM);
    conv_split<<<(M2*DM/4 + 255)/256, 256>>>(g, Ah, Al, M2*DM/4);
    gemm_mma<0,2><<<dim3(8,16,1), 256, GSMEM_BYTES>>>(Ah, Al, wqT, wqT+(size_t)DM*DM, nullptr, q2, q2h, q2l, 0, 0, QL, DM, DM);

    bias_dotT<<<(M2*NH*32 + 255)/256, 256>>>(k,  rwb, bkT,  QL);
    bias_dotT<<<(MR*NH*32 + 255)/256, 256>>>(kr, rrb, bkrT, RL);
    ef_kernel<<<(M2*NH*32 + 255)/256, 256>>>(q,  rsb, se, ef);
    ef_kernel<<<(M2*NH*32 + 255)/256, 256>>>(q2, rsb, se, ef + (size_t)M2*NH*2);

    // attention (both streams merged via z)
    score_mma<<<dim3(8, 8, 64), 256, SC_SMEM>>>(q1h, q1l, q2h, q2l, khh, khl, bkT,  S,  SSTR, QL, 0);
    score_mma<<<dim3(9, 8, 64), 256, SC_SMEM>>>(q1h, q1l, q2h, q2l, krh, krl, bkrT, BD, BSTR, RL, 1);
    softmax_fused<<<dim3(QL, 64), 256>>>(S, BD, diffb, ef, Ph, Pl);
    pv_mma<<<dim3(8, 64), 256, PV_SMEM>>>(Ph, Pl, vth, vtl, ath, atl);

    // back half (both streams merged via z)
    gemm_mma<0,0><<<dim3(8,16,2), 256, GSMEM_BYTES>>>(ath, atl, woC, woC+(size_t)DM*DM,
        nullptr, o, nullptr, nullptr, (size_t)M2*DM, (size_t)M2*DM, QL, DM, DM);
    add_ln<1><<<2*M2, 256>>>(o, h, g, lnga, lnba, y, yh, yl);
    gemm_mma<2,1><<<dim3(32,16,2), 256, GSMEM_BYTES>>>(yh, yl, w1T, w1T+(size_t)DM*DI,
        b1, nullptr, th, tl, (size_t)M2*DM, (size_t)M2*DI, QL, DM, DI);
    gemm_mma<1,0><<<dim3(8,16,2), 256, GSMEM_BYTES>>>(th, tl, w2T, w2T+(size_t)DI*DM,
        b2, z, nullptr, nullptr, (size_t)M2*DI, (size_t)M2*DM, QL, DI, DM);
    add_ln<0><<<2*M2, 256>>>(z, y, y + (size_t)M2*DM, lngf, lnbf, (float*)d_out, nullptr, nullptr);
}

// round 8
// speedup vs baseline: 1.4171x; 1.0669x over previous
#include <cuda_runtime.h>
#include <cuda_bf16.h>
#include <math.h>
#include <stdint.h>

#define QL 1024
#define NH 16
#define DH 64
#define DM 1024
#define DI 4096
#define RL 2048
#define M2 (QL*2)
#define MR (RL*2)
#define ATT_SCALE 0.125f
#define SSTR ((size_t)32*QL*QL)
#define BSTR ((size_t)32*QL*RL)

__device__ __forceinline__ uint32_t smem_u32(const void* p) {
    uint32_t a;
    asm("{ .reg .u64 t; cvta.to.shared.u64 t, %1; cvt.u32.u64 %0, t; }" : "=r"(a) : "l"(p));
    return a;
}
__device__ __forceinline__ void cp16(uint32_t dst, const void* src) {
    asm volatile("cp.async.cg.shared.global [%0], [%1], 16;" :: "r"(dst), "l"(src));
}
__device__ __forceinline__ void cp_commit() { asm volatile("cp.async.commit_group;" ::: "memory"); }
__device__ __forceinline__ void ldsm4(uint32_t (&r)[4], uint32_t addr) {
    asm volatile("ldmatrix.sync.aligned.m8n8.x4.shared.b16 {%0,%1,%2,%3}, [%4];"
        : "=r"(r[0]), "=r"(r[1]), "=r"(r[2]), "=r"(r[3]) : "r"(addr));
}
__device__ __forceinline__ void mma16816(float (&d)[4], const uint32_t (&a)[4],
                                         uint32_t b0, uint32_t b1) {
    asm volatile("mma.sync.aligned.m16n8k16.row.col.f32.bf16.bf16.f32 "
        "{%0,%1,%2,%3},{%4,%5,%6,%7},{%8,%9},{%0,%1,%2,%3};"
        : "+f"(d[0]), "+f"(d[1]), "+f"(d[2]), "+f"(d[3])
        : "r"(a[0]), "r"(a[1]), "r"(a[2]), "r"(a[3]), "r"(b0), "r"(b1));
}
__device__ __forceinline__ void bsplit(float v, __nv_bfloat16& h, __nv_bfloat16& l) {
    h = __float2bfloat16(v);
    l = __float2bfloat16(v - __bfloat162float(h));
}

// ---------------- scratch ----------------
__device__ float g_q [M2*DM];
__device__ float g_q2[M2*DM];
__device__ float g_k [M2*DM];
__device__ float g_v [M2*DM];
__device__ float g_kr[MR*DM];
__device__ float g_ef[2*M2*NH*2];
__device__ float g_o [2*M2*DM];
__device__ float g_y [2*M2*DM];
__device__ float g_z [2*M2*DM];
__device__ float g_bkT [32*QL];
__device__ float g_bkrT[32*RL];
__device__ float g_S [2*SSTR];
__device__ float g_BD[2*BSTR];
__device__ __align__(256) __nv_bfloat16 g_diffb[(size_t)2*QL*QL];
__device__ __align__(256) __nv_bfloat16 g_Ah [MR*DM], g_Al [MR*DM];
__device__ __align__(256) __nv_bfloat16 g_wqT[2*DM*DM], g_wkT[2*DM*DM], g_wvT[2*DM*DM];
__device__ __align__(256) __nv_bfloat16 g_wrT[2*DM*DM], g_woC[2*DM*DM];
__device__ __align__(256) __nv_bfloat16 g_w1T[2*DM*DI], g_w2T[2*DI*DM];
__device__ __align__(256) __nv_bfloat16 g_q1h[32*QL*DH], g_q1l[32*QL*DH];
__device__ __align__(256) __nv_bfloat16 g_q2h[32*QL*DH], g_q2l[32*QL*DH];
__device__ __align__(256) __nv_bfloat16 g_khh[32*QL*DH], g_khl[32*QL*DH];
__device__ __align__(256) __nv_bfloat16 g_krh[32*RL*DH], g_krl[32*RL*DH];
__device__ __align__(256) __nv_bfloat16 g_vth[32*DH*QL], g_vtl[32*DH*QL];
__device__ __align__(256) __nv_bfloat16 g_Ph [2*SSTR], g_Pl [2*SSTR];
__device__ __align__(256) __nv_bfloat16 g_ath[2*M2*DM], g_atl[2*M2*DM];
__device__ __align__(256) __nv_bfloat16 g_yh [2*M2*DM], g_yl [2*M2*DM];
__device__ __align__(256) __nv_bfloat16 g_th [2*M2*DI], g_tl [2*M2*DI];

// ---------------- small kernels ----------------
__global__ void conv_split(const float* __restrict__ X, __nv_bfloat16* __restrict__ hi,
                           __nv_bfloat16* __restrict__ lo, int n4)
{
    int i = blockIdx.x * blockDim.x + threadIdx.x;
    if (i >= n4) return;
    float4 v = ((const float4*)X)[i];
    __nv_bfloat16 h0,h1,h2,h3,l0,l1,l2,l3;
    bsplit(v.x,h0,l0); bsplit(v.y,h1,l1); bsplit(v.z,h2,l2); bsplit(v.w,h3,l3);
    ((__nv_bfloat162*)hi)[2*i]   = __nv_bfloat162(h0,h1);
    ((__nv_bfloat162*)hi)[2*i+1] = __nv_bfloat162(h2,h3);
    ((__nv_bfloat162*)lo)[2*i]   = __nv_bfloat162(l0,l1);
    ((__nv_bfloat162*)lo)[2*i+1] = __nv_bfloat162(l2,l3);
}

__global__ void convT_split(const float* __restrict__ W, __nv_bfloat16* __restrict__ hi,
                            __nv_bfloat16* __restrict__ lo, int K, int N)
{
    __shared__ float t[32][33];
    int k0 = blockIdx.y * 32, n0 = blockIdx.x * 32;
    int tx = threadIdx.x, ty = threadIdx.y;
#pragma unroll
    for (int p = 0; p < 4; p++)
        t[ty + p*8][tx] = W[(size_t)(k0 + ty + p*8)*N + n0 + tx];
    __syncthreads();
#pragma unroll
    for (int p = 0; p < 4; p++) {
        __nv_bfloat16 h, l;
        bsplit(t[tx][ty + p*8], h, l);
        size_t o = (size_t)(n0 + ty + p*8)*K + k0 + tx;
        hi[o] = h; lo[o] = l;
    }
}

__global__ void repack_vT(const float* __restrict__ V, __nv_bfloat16* __restrict__ hi,
                          __nv_bfloat16* __restrict__ lo)
{
    __shared__ float tile[32][33];
    int j0 = blockIdx.x * 32, d0 = blockIdx.y * 32;
    int bn = blockIdx.z, b = bn >> 4, n = bn & 15;
    int tx = threadIdx.x, ty = threadIdx.y;
#pragma unroll
    for (int p = 0; p < 4; p++)
        tile[ty + p*8][tx] = V[((size_t)(j0 + ty + p*8)*2 + b)*DM + n*DH + d0 + tx];
    __syncthreads();
#pragma unroll
    for (int p = 0; p < 4; p++) {
        __nv_bfloat16 h, l;
        bsplit(tile[tx][ty + p*8], h, l);
        size_t o = ((size_t)bn*DH + d0 + ty + p*8)*QL + j0 + tx;
        hi[o] = h; lo[o] = l;
    }
}

__global__ void prep_diff(const float* __restrict__ seg_mat, __nv_bfloat16* __restrict__ diff)
{
    size_t idx = (size_t)blockIdx.x * blockDim.x + threadIdx.x;
    if (idx >= (size_t)2*QL*QL) return;
    int j = idx & 1023, i = (idx >> 10) & 1023, b = (int)(idx >> 20);
    diff[idx] = __float2bfloat16(seg_mat[(((size_t)i*QL + j)*2 + b)*2 + 1]);
}

__global__ void bias_dotT(const float* __restrict__ X, const float* __restrict__ bias,
                          float* __restrict__ outT, int rowsPerB)
{
    const int gw = (blockIdx.x * blockDim.x + threadIdx.x) >> 5;
    const int lane = threadIdx.x & 31;
    if (gw >= rowsPerB * 2 * NH) return;
    const int row = gw >> 4, n = gw & 15;
    const int j = row >> 1, b = row & 1;
    float s = bias[n*DH + lane]      * X[(size_t)row*DM + n*DH + lane]
            + bias[n*DH + 32 + lane] * X[(size_t)row*DM + n*DH + 32 + lane];
#pragma unroll
    for (int o = 16; o; o >>= 1) s += __shfl_xor_sync(0xffffffffu, s, o);
    if (!lane) outT[(size_t)(b*16 + n)*rowsPerB + j] = s;
}

__global__ void ef_kernel(const float* __restrict__ q, const float* __restrict__ rsb,
                          const float* __restrict__ se, float* __restrict__ ef)
{
    const int gw = (blockIdx.x * blockDim.x + threadIdx.x) >> 5;
    const int lane = threadIdx.x & 31;
    if (gw >= M2 * NH) return;
    const int row = gw >> 4, n = gw & 15;
    const float v0 = q[(size_t)row*DM + n*DH + lane]      + rsb[n*DH + lane];
    const float v1 = q[(size_t)row*DM + n*DH + 32 + lane] + rsb[n*DH + 32 + lane];
    float s0 = v0*se[n*DH + lane] + v1*se[n*DH + 32 + lane];
    float s1 = v0*se[NH*DH + n*DH + lane] + v1*se[NH*DH + n*DH + 32 + lane];
#pragma unroll
    for (int o = 16; o; o >>= 1) {
        s0 += __shfl_xor_sync(0xffffffffu, s0, o);
        s1 += __shfl_xor_sync(0xffffffffu, s1, o);
    }
    if (!lane) { ef[gw*2] = s0; ef[gw*2 + 1] = s1; }
}

// g-stream row i=0 is fully masked -> reference prob is exactly uniform 1/1024
// -> attn row = column mean of V. Overwrite PV output for that row.
__global__ void vmean_fix(const float* __restrict__ V,
                          __nv_bfloat16* __restrict__ Oh, __nv_bfloat16* __restrict__ Ol)
{
    int bn = blockIdx.x, b = bn >> 4, n = bn & 15;
    int d = threadIdx.x;   // 64
    float s = 0.f;
    for (int j = 0; j < QL; j++) s += V[((size_t)j*2 + b)*DM + n*DH + d];
    s *= (1.0f/1024.0f);
    __nv_bfloat16 hh, ll; bsplit(s, hh, ll);
    size_t o = (size_t)M2*DM + (size_t)b*DM + n*DH + d;   // stream 1, row i=0
    Oh[o] = hh; Ol[o] = ll;
}

// ---------------- dense split-bf16 GEMM; z = stream ----------------
#define GSTAGE 65536
#define GSMEM_BYTES (2*GSTAGE)

__device__ __forceinline__ void g_load_stage(
    const __nv_bfloat16* __restrict__ Ah, const __nv_bfloat16* __restrict__ Al,
    const __nv_bfloat16* __restrict__ Bh, const __nv_bfloat16* __restrict__ Bl,
    uint32_t st, int m0, int n0, int K, int kc, int tid)
{
    const size_t ko = (size_t)kc * 64;
#pragma unroll
    for (int p = 0; p < 4; p++) {
        int c = p*256 + tid;
        int row = c >> 3, kcol = c & 7;
        uint32_t sw = (uint32_t)(row*128 + kcol*16) ^ ((row & 7) << 4);
        const size_t ga = (size_t)(m0 + row)*K + ko + kcol*8;
        const size_t gb = (size_t)(n0 + row)*K + ko + kcol*8;
        cp16(st + sw,         Ah + ga);
        cp16(st + 16384 + sw, Al + ga);
        cp16(st + 32768 + sw, Bh + gb);
        cp16(st + 49152 + sw, Bl + gb);
    }
    cp_commit();
}

template<int EPI, int OUT>   // OUT: 0 fp32, 1 bf16 hi/lo row-major, 2 fp32 + head-major bf16
__global__ void __launch_bounds__(256, 1) gemm_mma(
    const __nv_bfloat16* __restrict__ Ah, const __nv_bfloat16* __restrict__ Al,
    const __nv_bfloat16* __restrict__ Bh, const __nv_bfloat16* __restrict__ Bl,
    const float* __restrict__ bias, float* __restrict__ C,
    __nv_bfloat16* __restrict__ Chi, __nv_bfloat16* __restrict__ Clo,
    size_t zsA, size_t zsC, int rowsPerB, int K, int ldc)
{
    extern __shared__ char dsm[];
    const uint32_t sbase = smem_u32(dsm);
    const int tid = threadIdx.x, lane = tid & 31, warp = tid >> 5;
    const size_t zo = blockIdx.z;
    Ah += zo*zsA; Al += zo*zsA;
    if (OUT != 1) C += zo*zsC;
    if (OUT >= 1) { Chi += zo*zsC; Clo += zo*zsC; }
    const int m0 = blockIdx.y * 128, n0 = blockIdx.x * 128;
    const int wm = (warp & 1) * 64, wn = (warp >> 1) * 32;
    const int NC = K >> 6;

    float acc[4][4][4] = {};
    g_load_stage(Ah, Al, Bh, Bl, sbase,          m0, n0, K, 0, tid);
    g_load_stage(Ah, Al, Bh, Bl, sbase + GSTAGE, m0, n0, K, 1, tid);
    asm volatile("cp.async.wait_group 1;" ::: "memory");
    __syncthreads();

    const int arow = wm + (lane & 15), akb = lane & 16;
    const int brow = wn + ((lane & 16) >> 1) + (lane & 7), bkb = (lane & 8) << 1;

    for (int kc = 0; kc < NC; kc++) {
        const uint32_t st = sbase + (kc & 1) * GSTAGE;
#pragma unroll
        for (int ks = 0; ks < 4; ks++) {
            const int kb = ks*32;
            uint32_t ah[4][4], al[4][4], bh[2][4], bl[2][4];
#pragma unroll
            for (int im = 0; im < 4; im++) {
                int row = arow + im*16;
                uint32_t off = (uint32_t)(row*128 + kb + akb) ^ ((row & 7) << 4);
                ldsm4(ah[im], st + off);
                ldsm4(al[im], st + 16384 + off);
            }
#pragma unroll
            for (int np = 0; np < 2; np++) {
                int row = brow + np*16;
                uint32_t off = (uint32_t)(row*128 + kb + bkb) ^ ((row & 7) << 4);
                ldsm4(bh[np], st + 32768 + off);
                ldsm4(bl[np], st + 49152 + off);
            }
#pragma unroll
            for (int im = 0; im < 4; im++)
#pragma unroll
                for (int in = 0; in < 4; in++) {
                    const int np = in >> 1, hf = (in & 1) * 2;
                    mma16816(acc[im][in], ah[im], bh[np][hf], bh[np][hf+1]);
                    mma16816(acc[im][in], ah[im], bl[np][hf], bl[np][hf+1]);
                    mma16816(acc[im][in], al[im], bh[np][hf], bh[np][hf+1]);
                }
        }
        __syncthreads();
        if (kc + 2 < NC) {
            g_load_stage(Ah, Al, Bh, Bl, sbase + (kc & 1)*GSTAGE, m0, n0, K, kc + 2, tid);
            asm volatile("cp.async.wait_group 1;" ::: "memory");
        } else {
            asm volatile("cp.async.wait_group 0;" ::: "memory");
        }
        __syncthreads();
    }

    const int rbase = m0 + wm + (lane >> 2);
    const int cbase = n0 + wn + 2*(lane & 3);
#pragma unroll
    for (int im = 0; im < 4; im++) {
#pragma unroll
        for (int in = 0; in < 4; in++) {
            int col = cbase + in*8;
            float v0 = acc[im][in][0], v1 = acc[im][in][1];
            float v2 = acc[im][in][2], v3 = acc[im][in][3];
            if (EPI >= 1) {
                float b0 = bias[col], b1 = bias[col+1];
                v0 += b0; v1 += b1; v2 += b0; v3 += b1;
            }
            if (EPI == 2) {
                v0 = 0.5f*v0*(1.0f + erff(v0*0.7071067811865476f));
                v1 = 0.5f*v1*(1.0f + erff(v1*0.7071067811865476f));
                v2 = 0.5f*v2*(1.0f + erff(v2*0.7071067811865476f));
                v3 = 0.5f*v3*(1.0f + erff(v3*0.7071067811865476f));
            }
            int r0 = rbase + im*16, r1 = r0 + 8;
            if (OUT != 1) {
                *(float2*)(C + (size_t)r0*ldc + col) = make_float2(v0, v1);
                *(float2*)(C + (size_t)r1*ldc + col) = make_float2(v2, v3);
            }
            if (OUT >= 1) {
                __nv_bfloat16 h0,h1,h2,h3,l0,l1,l2,l3;
                bsplit(v0,h0,l0); bsplit(v1,h1,l1); bsplit(v2,h2,l2); bsplit(v3,h3,l3);
                size_t d0, d1;
                if (OUT == 1) { d0 = (size_t)r0*ldc + col; d1 = (size_t)r1*ldc + col; }
                else {
                    int nh = col >> 6, d = col & 63;
                    d0 = (((size_t)(r0 & 1)*NH + nh)*rowsPerB + (r0 >> 1))*DH + d;
                    d1 = (((size_t)(r1 & 1)*NH + nh)*rowsPerB + (r1 >> 1))*DH + d;
                }
                *(__nv_bfloat162*)(Chi + d0) = __nv_bfloat162(h0, h1);
                *(__nv_bfloat162*)(Chi + d1) = __nv_bfloat162(h2, h3);
                *(__nv_bfloat162*)(Clo + d0) = __nv_bfloat162(l0, l1);
                *(__nv_bfloat162*)(Clo + d1) = __nv_bfloat162(l2, l3);
            }
        }
    }
}

// ---------------- batched score GEMM (z = s*32+bn), causal-pruned ----------------
#define SC_SMEM 65536

__global__ void __launch_bounds__(256, 1) score_mma(
    const __nv_bfloat16* __restrict__ Q1h, const __nv_bfloat16* __restrict__ Q1l,
    const __nv_bfloat16* __restrict__ Q2h, const __nv_bfloat16* __restrict__ Q2l,
    const __nv_bfloat16* __restrict__ Kh, const __nv_bfloat16* __restrict__ Kl,
    const float* __restrict__ biasT, float* __restrict__ C,
    size_t zsC, int Ncols, int window)
{
    extern __shared__ char dsm[];
    const uint32_t st = smem_u32(dsm);
    const int tid = threadIdx.x, lane = tid & 31, warp = tid >> 5;
    const int zz = blockIdx.z, s = zz >> 5, bn = zz & 31;
    const __nv_bfloat16* Qh = s ? Q2h : Q1h;
    const __nv_bfloat16* Ql = s ? Q2l : Q1l;
    C += (size_t)s * zsC;

    int i0, j0;
    if (!window) {
        // triangular decode: blockIdx.x -> (it, jt) with jt <= it (36 tiles)
        int t = blockIdx.x;
        int it = (int)((sqrtf(8.f*t + 1.f) - 1.f) * 0.5f);
        if ((it + 1)*(it + 2)/2 <= t) it++;
        else if (it*(it + 1)/2 > t) it--;
        int jt = t - it*(it + 1)/2;
        i0 = it * 128; j0 = jt * 128;
    } else {
        int it = blockIdx.y;
        int bx = blockIdx.x;
        if (bx > it + 1) return;          // only ct in [7-it, 8] needed under causality
        i0 = it * 128;
        j0 = (7 - it + bx) * 128;
    }

    const size_t qb = ((size_t)bn*QL + i0)*DH;
    const size_t kb = ((size_t)bn*Ncols + j0)*DH;
#pragma unroll
    for (int p = 0; p < 4; p++) {
        int c = p*256 + tid;
        int row = c >> 3, kcol = c & 7;
        uint32_t sw = (uint32_t)(row*128 + kcol*16) ^ ((row & 7) << 4);
        cp16(st + sw,         Qh + qb + (size_t)row*DH + kcol*8);
        cp16(st + 16384 + sw, Ql + qb + (size_t)row*DH + kcol*8);
        cp16(st + 32768 + sw, Kh + kb + (size_t)row*DH + kcol*8);
        cp16(st + 49152 + sw, Kl + kb + (size_t)row*DH + kcol*8);
    }
    cp_commit();
    asm volatile("cp.async.wait_group 0;" ::: "memory");
    __syncthreads();

    const int wm = (warp & 1) * 64, wn = (warp >> 1) * 32;
    const int arow = wm + (lane & 15), akb = lane & 16;
    const int brow = wn + ((lane & 16) >> 1) + (lane & 7), bkb = (lane & 8) << 1;

    float acc[4][4][4] = {};
#pragma unroll
    for (int ks = 0; ks < 4; ks++) {
        const int kbyte = ks*32;
        uint32_t ah[4][4], al[4][4], bh[2][4], bl[2][4];
#pragma unroll
        for (int im = 0; im < 4; im++) {
            int row = arow + im*16;
            uint32_t off = (uint32_t)(row*128 + kbyte + akb) ^ ((row & 7) << 4);
            ldsm4(ah[im], st + off);
            ldsm4(al[im], st + 16384 + off);
        }
#pragma unroll
        for (int np = 0; np < 2; np++) {
            int row = brow + np*16;
            uint32_t off = (uint32_t)(row*128 + kbyte + bkb) ^ ((row & 7) << 4);
            ldsm4(bh[np], st + 32768 + off);
            ldsm4(bl[np], st + 49152 + off);
        }
#pragma unroll
        for (int im = 0; im < 4; im++)
#pragma unroll
            for (int in = 0; in < 4; in++) {
                const int np = in >> 1, hf = (in & 1) * 2;
                mma16816(acc[im][in], ah[im], bh[np][hf], bh[np][hf+1]);
                mma16816(acc[im][in], ah[im], bl[np][hf], bl[np][hf+1]);
                mma16816(acc[im][in], al[im], bh[np][hf], bh[np][hf+1]);
            }
    }

    float* Cb = C + (size_t)bn*QL*Ncols;
    const float* bt = biasT + (size_t)bn*Ncols;
    const int rbase = i0 + wm + (lane >> 2);
    const int cbase = j0 + wn + 2*(lane & 3);
#pragma unroll
    for (int im = 0; im < 4; im++)
#pragma unroll
        for (int in = 0; in < 4; in++) {
            int col = cbase + in*8;
            float b0 = bt[col], b1 = bt[col+1];
            int r0 = rbase + im*16, r1 = r0 + 8;
            *(float2*)(Cb + (size_t)r0*Ncols + col) =
                make_float2(acc[im][in][0] + b0, acc[im][in][1] + b1);
            *(float2*)(Cb + (size_t)r1*Ncols + col) =
                make_float2(acc[im][in][2] + b0, acc[im][in][3] + b1);
        }
}

// ---------------- fused combine + softmax (causal-bounded) + bf16-split P ----------------
__global__ void __launch_bounds__(256) softmax_fused(
    const float* __restrict__ S, const float* __restrict__ BD,
    const __nv_bfloat16* __restrict__ diff, const float* __restrict__ ef,
    __nv_bfloat16* __restrict__ Ph, __nv_bfloat16* __restrict__ Pl)
{
    __shared__ float red[8];
    const int i = blockIdx.x;
    const int zz = blockIdx.y, s = zz >> 5, bn = zz & 31, b = bn >> 4, n = bn & 15;
    const int jmax = ((i >> 7) + 1) << 7;    // only tiles jt <= it contain unmasked entries
    const float* Sr = S    + (size_t)s*SSTR + ((size_t)bn << 20) + ((size_t)i << 10);
    const float* Br = BD   + (size_t)s*BSTR + ((size_t)bn << 21) + ((size_t)i << 11) + (QL - i);
    const __nv_bfloat16* Dr = diff + ((size_t)b << 20) + ((size_t)i << 10);
    const float* efs = ef + (size_t)s*M2*NH*2;
    const float e0 = efs[(((size_t)i*2 + b)*NH + n)*2];
    const float de = efs[(((size_t)i*2 + b)*NH + n)*2 + 1] - e0;
    const int t = threadIdx.x, lane = t & 31, w = t >> 5;

    float v[4];
#pragma unroll
    for (int p = 0; p < 4; p++) {
        int j = t + p*256;
        if (j < jmax) {
            float sc = (Sr[j] + Br[j] + e0 + de*__bfloat162float(Dr[j])) * ATT_SCALE;
            bool blocked = s ? (j >= i) : (j > i);
            v[p] = blocked ? sc - 1e30f : sc;
        } else v[p] = -1e30f;
    }
    float m = fmaxf(fmaxf(v[0], v[1]), fmaxf(v[2], v[3]));
#pragma unroll
    for (int o = 16; o; o >>= 1) m = fmaxf(m, __shfl_xor_sync(0xffffffffu, m, o));
    if (!lane) red[w] = m;
    __syncthreads();
    m = red[lane & 7];
#pragma unroll
    for (int o = 4; o; o >>= 1) m = fmaxf(m, __shfl_xor_sync(0xffffffffu, m, o));
    float sum = 0.f;
#pragma unroll
    for (int p = 0; p < 4; p++) { v[p] = expf(v[p] - m); sum += v[p]; }
#pragma unroll
    for (int o = 16; o; o >>= 1) sum += __shfl_xor_sync(0xffffffffu, sum, o);
    __syncthreads();
    if (!lane) red[w] = sum;
    __syncthreads();
    sum = red[lane & 7];
#pragma unroll
    for (int o = 4; o; o >>= 1) sum += __shfl_xor_sync(0xffffffffu, sum, o);
    const float inv = 1.0f / sum;
    const size_t base = (size_t)s*SSTR + ((size_t)bn << 20) + ((size_t)i << 10);
#pragma unroll
    for (int p = 0; p < 4; p++) {
        int j = t + p*256;
        if (j < jmax) {
            __nv_bfloat16 ph, pl;
            bsplit(v[p] * inv, ph, pl);
            Ph[base + j] = ph;
            Pl[base + j] = pl;
        }
    }
}

// ---------------- batched PV GEMM (causal K bound) -> bf16 hi/lo attn ----------------
#define PV_STAGE 49152
#define PV_SMEM (2*PV_STAGE)

__device__ __forceinline__ void pv_load(
    const __nv_bfloat16* __restrict__ Ph, const __nv_bfloat16* __restrict__ Pl,
    const __nv_bfloat16* __restrict__ Vh, const __nv_bfloat16* __restrict__ Vl,
    uint32_t st, size_t pbase, size_t vbase, int kc, int tid)
{
    const size_t ko = (size_t)kc * 64;
#pragma unroll
    for (int p = 0; p < 4; p++) {
        int c = p*256 + tid;
        int row = c >> 3, kcol = c & 7;
        uint32_t sw = (uint32_t)(row*128 + kcol*16) ^ ((row & 7) << 4);
        cp16(st + sw,         Ph + pbase + (size_t)row*QL + ko + kcol*8);
        cp16(st + 16384 + sw, Pl + pbase + (size_t)row*QL + ko + kcol*8);
    }
#pragma unroll
    for (int p = 0; p < 2; p++) {
        int c = p*256 + tid;
        int row = c >> 3, kcol = c & 7;
        uint32_t sw = (uint32_t)(row*128 + kcol*16) ^ ((row & 7) << 4);
        cp16(st + 32768 + sw, Vh + vbase + (size_t)row*QL + ko + kcol*8);
        cp16(st + 40960 + sw, Vl + vbase + (size_t)row*QL + ko + kcol*8);
    }
    cp_commit();
}

__global__ void __launch_bounds__(256, 1) pv_mma(
    const __nv_bfloat16* __restrict__ Ph, const __nv_bfloat16* __restrict__ Pl,
    const __nv_bfloat16* __restrict__ Vh, const __nv_bfloat16* __restrict__ Vl,
    __nv_bfloat16* __restrict__ Oh, __nv_bfloat16* __restrict__ Ol)
{
    extern __shared__ char dsm[];
    const uint32_t sbase = smem_u32(dsm);
    const int tid = threadIdx.x, lane = tid & 31, warp = tid >> 5;
    const int zz = blockIdx.y, s = zz >> 5, bn = zz & 31, b = bn >> 4, n = bn & 15;
    const int it = blockIdx.x;
    const int i0 = it * 128;
    const int NC = 2*it + 2;            // causal: only j < 128*(it+1)
    const size_t pbase = (size_t)s*SSTR + ((size_t)bn << 20) + (size_t)i0*QL;
    const size_t vbase = (size_t)bn * DH * QL;
    const size_t obase = (size_t)s * M2 * DM;

    float acc[2][4][4] = {};
    pv_load(Ph, Pl, Vh, Vl, sbase,            pbase, vbase, 0, tid);
    pv_load(Ph, Pl, Vh, Vl, sbase + PV_STAGE, pbase, vbase, 1, tid);
    asm volatile("cp.async.wait_group 1;" ::: "memory");
    __syncthreads();

    const int wm = (warp & 3) * 32, wn = (warp >> 2) * 32;
    const int arow = wm + (lane & 15), akb = lane & 16;
    const int brow = wn + ((lane & 16) >> 1) + (lane & 7), bkb = (lane & 8) << 1;

    for (int kc = 0; kc < NC; kc++) {
        const uint32_t st = sbase + (kc & 1) * PV_STAGE;
#pragma unroll
        for (int ks = 0; ks < 4; ks++) {
            const int kb = ks*32;
            uint32_t ah[2][4], al[2][4], bh[2][4], bl[2][4];
#pragma unroll
            for (int im = 0; im < 2; im++) {
                int row = arow + im*16;
                uint32_t off = (uint32_t)(row*128 + kb + akb) ^ ((row & 7) << 4);
                ldsm4(ah[im], st + off);
                ldsm4(al[im], st + 16384 + off);
            }
#pragma unroll
            for (int np = 0; np < 2; np++) {
                int row = brow + np*16;
                uint32_t off = (uint32_t)(row*128 + kb + bkb) ^ ((row & 7) << 4);
                ldsm4(bh[np], st + 32768 + off);
                ldsm4(bl[np], st + 40960 + off);
            }
#pragma unroll
            for (int im = 0; im < 2; im++)
#pragma unroll
                for (int in = 0; in < 4; in++) {
                    const int np = in >> 1, hf = (in & 1) * 2;
                    mma16816(acc[im][in], ah[im], bh[np][hf], bh[np][hf+1]);
                    mma16816(acc[im][in], ah[im], bl[np][hf], bl[np][hf+1]);
                    mma16816(acc[im][in], al[im], bh[np][hf], bh[np][hf+1]);
                }
        }
        __syncthreads();
        if (kc + 2 < NC) {
            pv_load(Ph, Pl, Vh, Vl, sbase + (kc & 1)*PV_STAGE, pbase, vbase, kc + 2, tid);
            asm volatile("cp.async.wait_group 1;" ::: "memory");
        } else {
            asm volatile("cp.async.wait_group 0;" ::: "memory");
        }
        __syncthreads();
    }

    const int rl = wm + (lane >> 2);
    const int cb = wn + 2*(lane & 3);
#pragma unroll
    for (int im = 0; im < 2; im++)
#pragma unroll
        for (int in = 0; in < 4; in++) {
            int col = cb + in*8;
            int r0 = i0 + rl + im*16, r1 = r0 + 8;
            size_t d0 = obase + ((size_t)r0*2 + b)*DM + n*DH + col;
            size_t d1 = obase + ((size_t)r1*2 + b)*DM + n*DH + col;
            __nv_bfloat16 h0,h1,h2,h3,l0,l1,l2,l3;
            bsplit(acc[im][in][0],h0,l0); bsplit(acc[im][in][1],h1,l1);
            bsplit(acc[im][in][2],h2,l2); bsplit(acc[im][in][3],h3,l3);
            *(__nv_bfloat162*)(Oh + d0) = __nv_bfloat162(h0, h1);
            *(__nv_bfloat162*)(Oh + d1) = __nv_bfloat162(h2, h3);
            *(__nv_bfloat162*)(Ol + d0) = __nv_bfloat162(l0, l1);
            *(__nv_bfloat162*)(Ol + d1) = __nv_bfloat162(l2, l3);
        }
}

// ---------------- residual + LayerNorm (merged streams) ----------------
template<int WB16>
__global__ void __launch_bounds__(256) add_ln(
    const float* __restrict__ a, const float* __restrict__ x0, const float* __restrict__ x1,
    const float* __restrict__ gamma, const float* __restrict__ beta,
    float* __restrict__ out, __nv_bfloat16* __restrict__ oh, __nv_bfloat16* __restrict__ ol)
{
    __shared__ float buf[1024];
    __shared__ float red[8];
    __shared__ float s_stat;
    const size_t base = (size_t)blockIdx.x << 10;
    const int str = blockIdx.x >> 11;
    const size_t lbase = (size_t)(blockIdx.x & 2047) << 10;
    const float* x = str ? x1 : x0;
    const int t = threadIdx.x, lane = t & 31, w = t >> 5;
    float sum = 0.f;
#pragma unroll
    for (int p = 0; p < 4; p++) {
        float v = a[base + t + p*256] + x[lbase + t + p*256];
        buf[t + p*256] = v; sum += v;
    }
#pragma unroll
    for (int o = 16; o; o >>= 1) sum += __shfl_xor_sync(0xffffffffu, sum, o);
    if (!lane) red[w] = sum;
    __syncthreads();
    if (t == 0) { float s = 0; for (int i = 0; i < 8; i++) s += red[i]; s_stat = s * (1.0f/1024.0f); }
    __syncthreads();
    const float mean = s_stat;
    float vs = 0.f;
#pragma unroll
    for (int p = 0; p < 4; p++) { float d = buf[t + p*256] - mean; vs += d*d; }
#pragma unroll
    for (int o = 16; o; o >>= 1) vs += __shfl_xor_sync(0xffffffffu, vs, o);
    __syncthreads();
    if (!lane) red[w] = vs;
    __syncthreads();
    if (t == 0) { float s = 0; for (int i = 0; i < 8; i++) s += red[i]; s_stat = s * (1.0f/1024.0f); }
    __syncthreads();
    const float r = rsqrtf(s_stat + 1e-12f);
#pragma unroll
    for (int p = 0; p < 4; p++) {
        int c = t + p*256;
        float val = (buf[c] - mean) * r * gamma[c] + beta[c];
        out[base + c] = val;
        if (WB16) {
            __nv_bfloat16 hh, ll;
            bsplit(val, hh, ll);
            oh[base + c] = hh;
            ol[base + c] = ll;
        }
    }
}

// ---------------- host ----------------
extern "C" void kernel_launch(void* const* d_in, const int* in_sizes, int n_in,
                              void* d_out, int out_size)
{
    (void)in_sizes; (void)n_in; (void)out_size;
    const float* h       = (const float*)d_in[0];
    const float* g       = (const float*)d_in[1];
    const float* r       = (const float*)d_in[2];
    const float* seg_mat = (const float*)d_in[5];
    const float* wq      = (const float*)d_in[6];
    const float* wk      = (const float*)d_in[7];
    const float* wv      = (const float*)d_in[8];
    const float* wo      = (const float*)d_in[9];
    const float* wr      = (const float*)d_in[10];
    const float* rwb     = (const float*)d_in[11];
    const float* rrb     = (const float*)d_in[12];
    const float* rsb     = (const float*)d_in[13];
    const float* se      = (const float*)d_in[14];
    const float* lnga    = (const float*)d_in[15];
    const float* lnba    = (const float*)d_in[16];
    const float* w1      = (const float*)d_in[17];
    const float* b1      = (const float*)d_in[18];
    const float* w2      = (const float*)d_in[19];
    const float* b2      = (const float*)d_in[20];
    const float* lngf    = (const float*)d_in[21];
    const float* lnbf    = (const float*)d_in[22];

    cudaFuncSetAttribute(gemm_mma<0,0>, cudaFuncAttributeMaxDynamicSharedMemorySize, GSMEM_BYTES);
    cudaFuncSetAttribute(gemm_mma<0,2>, cudaFuncAttributeMaxDynamicSharedMemorySize, GSMEM_BYTES);
    cudaFuncSetAttribute(gemm_mma<2,1>, cudaFuncAttributeMaxDynamicSharedMemorySize, GSMEM_BYTES);
    cudaFuncSetAttribute(gemm_mma<1,0>, cudaFuncAttributeMaxDynamicSharedMemorySize, GSMEM_BYTES);
    cudaFuncSetAttribute(score_mma,     cudaFuncAttributeMaxDynamicSharedMemorySize, SC_SMEM);
    cudaFuncSetAttribute(pv_mma,        cudaFuncAttributeMaxDynamicSharedMemorySize, PV_SMEM);

    float *q,*q2,*k,*v,*kr,*ef,*o,*y,*z,*bkT,*bkrT,*S,*BD;
    __nv_bfloat16 *Ah,*Al,*wqT,*wkT,*wvT,*wrT,*woC,*w1T,*w2T,*diffb;
    __nv_bfloat16 *q1h,*q1l,*q2h,*q2l,*khh,*khl,*krh,*krl,*vth,*vtl,*Ph,*Pl,*ath,*atl,*yh,*yl,*th,*tl;
    cudaGetSymbolAddress((void**)&q,    g_q);
    cudaGetSymbolAddress((void**)&q2,   g_q2);
    cudaGetSymbolAddress((void**)&k,    g_k);
    cudaGetSymbolAddress((void**)&v,    g_v);
    cudaGetSymbolAddress((void**)&kr,   g_kr);
    cudaGetSymbolAddress((void**)&ef,   g_ef);
    cudaGetSymbolAddress((void**)&o,    g_o);
    cudaGetSymbolAddress((void**)&y,    g_y);
    cudaGetSymbolAddress((void**)&z,    g_z);
    cudaGetSymbolAddress((void**)&bkT,  g_bkT);
    cudaGetSymbolAddress((void**)&bkrT, g_bkrT);
    cudaGetSymbolAddress((void**)&S,    g_S);
    cudaGetSymbolAddress((void**)&BD,   g_BD);
    cudaGetSymbolAddress((void**)&diffb,g_diffb);
    cudaGetSymbolAddress((void**)&Ah,   g_Ah);
    cudaGetSymbolAddress((void**)&Al,   g_Al);
    cudaGetSymbolAddress((void**)&wqT,  g_wqT);
    cudaGetSymbolAddress((void**)&wkT,  g_wkT);
    cudaGetSymbolAddress((void**)&wvT,  g_wvT);
    cudaGetSymbolAddress((void**)&wrT,  g_wrT);
    cudaGetSymbolAddress((void**)&woC,  g_woC);
    cudaGetSymbolAddress((void**)&w1T,  g_w1T);
    cudaGetSymbolAddress((void**)&w2T,  g_w2T);
    cudaGetSymbolAddress((void**)&q1h,  g_q1h);
    cudaGetSymbolAddress((void**)&q1l,  g_q1l);
    cudaGetSymbolAddress((void**)&q2h,  g_q2h);
    cudaGetSymbolAddress((void**)&q2l,  g_q2l);
    cudaGetSymbolAddress((void**)&khh,  g_khh);
    cudaGetSymbolAddress((void**)&khl,  g_khl);
    cudaGetSymbolAddress((void**)&krh,  g_krh);
    cudaGetSymbolAddress((void**)&krl,  g_krl);
    cudaGetSymbolAddress((void**)&vth,  g_vth);
    cudaGetSymbolAddress((void**)&vtl,  g_vtl);
    cudaGetSymbolAddress((void**)&Ph,   g_Ph);
    cudaGetSymbolAddress((void**)&Pl,   g_Pl);
    cudaGetSymbolAddress((void**)&ath,  g_ath);
    cudaGetSymbolAddress((void**)&atl,  g_atl);
    cudaGetSymbolAddress((void**)&yh,   g_yh);
    cudaGetSymbolAddress((void**)&yl,   g_yl);
    cudaGetSymbolAddress((void**)&th,   g_th);
    cudaGetSymbolAddress((void**)&tl,   g_tl);

    dim3 tb(32, 8);
    convT_split<<<dim3(DM/32, DM/32), tb>>>(wq, wqT, wqT + (size_t)DM*DM, DM, DM);
    convT_split<<<dim3(DM/32, DM/32), tb>>>(wk, wkT, wkT + (size_t)DM*DM, DM, DM);
    convT_split<<<dim3(DM/32, DM/32), tb>>>(wv, wvT, wvT + (size_t)DM*DM, DM, DM);
    convT_split<<<dim3(DM/32, DM/32), tb>>>(wr, wrT, wrT + (size_t)DM*DM, DM, DM);
    conv_split<<<(DM*DM/4 + 255)/256, 256>>>(wo, woC, woC + (size_t)DM*DM, DM*DM/4);
    convT_split<<<dim3(DI/32, DM/32), tb>>>(w1, w1T, w1T + (size_t)DM*DI, DM, DI);
    convT_split<<<dim3(DM/32, DI/32), tb>>>(w2, w2T, w2T + (size_t)DI*DM, DI, DM);
    prep_diff<<<(2*QL*QL + 255)/256, 256>>>(seg_mat, diffb);

    // projections
    conv_split<<<(M2*DM/4 + 255)/256, 256>>>(h, Ah, Al, M2*DM/4);
    gemm_mma<0,2><<<dim3(8,16,1), 256, GSMEM_BYTES>>>(Ah, Al, wkT, wkT+(size_t)DM*DM, nullptr, k,  khh, khl, 0, 0, QL, DM, DM);
    gemm_mma<0,0><<<dim3(8,16,1), 256, GSMEM_BYTES>>>(Ah, Al, wvT, wvT+(size_t)DM*DM, nullptr, v,  nullptr, nullptr, 0, 0, QL, DM, DM);
    repack_vT<<<dim3(QL/32, DH/32, 32), tb>>>(v, vth, vtl);
    gemm_mma<0,2><<<dim3(8,16,1), 256, GSMEM_BYTES>>>(Ah, Al, wqT, wqT+(size_t)DM*DM, nullptr, q,  q1h, q1l, 0, 0, QL, DM, DM);
    conv_split<<<(MR*DM/4 + 255)/256, 256>>>(r, Ah, Al, MR*DM/4);
    gemm_mma<0,2><<<dim3(8,32,1), 256, GSMEM_BYTES>>>(Ah, Al, wrT, wrT+(size_t)DM*DM, nullptr, kr, krh, krl, 0, 0, RL, DM, DM);
    conv_split<<<(M2*DM/4 + 255)/256, 256>>>(g, Ah, Al, M2*DM/4);
    gemm_mma<0,2><<<dim3(8,16,1), 256, GSMEM_BYTES>>>(Ah, Al, wqT, wqT+(size_t)DM*DM, nullptr, q2, q2h, q2l, 0, 0, QL, DM, DM);

    bias_dotT<<<(M2*NH*32 + 255)/256, 256>>>(k,  rwb, bkT,  QL);
    bias_dotT<<<(MR*NH*32 + 255)/256, 256>>>(kr, rrb, bkrT, RL);
    ef_kernel<<<(M2*NH*32 + 255)/256, 256>>>(q,  rsb, se, ef);
    ef_kernel<<<(M2*NH*32 + 255)/256, 256>>>(q2, rsb, se, ef + (size_t)M2*NH*2);

    // attention (both streams merged; causal-pruned)
    score_mma<<<dim3(36, 1, 64), 256, SC_SMEM>>>(q1h, q1l, q2h, q2l, khh, khl, bkT,  S,  SSTR, QL, 0);
    score_mma<<<dim3(9, 8, 64), 256, SC_SMEM>>>(q1h, q1l, q2h, q2l, krh, krl, bkrT, BD, BSTR, RL, 1);
    softmax_fused<<<dim3(QL, 64), 256>>>(S, BD, diffb, ef, Ph, Pl);
    pv_mma<<<dim3(8, 64), 256, PV_SMEM>>>(Ph, Pl, vth, vtl, ath, atl);
    vmean_fix<<<32, 64>>>(v, ath, atl);

    // back half (both streams merged via z)
    gemm_mma<0,0><<<dim3(8,16,2), 256, GSMEM_BYTES>>>(ath, atl, woC, woC+(size_t)DM*DM,
        nullptr, o, nullptr, nullptr, (size_t)M2*DM, (size_t)M2*DM, QL, DM, DM);
    add_ln<1><<<2*M2, 256>>>(o, h, g, lnga, lnba, y, yh, yl);
    gemm_mma<2,1><<<dim3(32,16,2), 256, GSMEM_BYTES>>>(yh, yl, w1T, w1T+(size_t)DM*DI,
        b1, nullptr, th, tl, (size_t)M2*DM, (size_t)M2*DI, QL, DM, DI);
    gemm_mma<1,0><<<dim3(8,16,2), 256, GSMEM_BYTES>>>(th, tl, w2T, w2T+(size_t)DI*DM,
        b2, z, nullptr, nullptr, (size_t)M2*DI, (size_t)M2*DM, QL, DI, DM);
    add_ln<0><<<2*M2, 256>>>(z, y, y + (size_t)M2*DM, lngf, lnbf, (float*)d_out, nullptr, nullptr);
}

// round 9
// speedup vs baseline: 1.4229x; 1.0041x over previous
#include <cuda_runtime.h>
#include <cuda_bf16.h>
#include <math.h>
#include <stdint.h>

#define QL 1024
#define NH 16
#define DH 64
#define DM 1024
#define DI 4096
#define RL 2048
#define M2 (QL*2)
#define MR (RL*2)
#define ATT_SCALE 0.125f
#define SSTR ((size_t)32*QL*QL)
#define BSTR ((size_t)32*QL*RL)

__device__ __forceinline__ uint32_t smem_u32(const void* p) {
    uint32_t a;
    asm("{ .reg .u64 t; cvta.to.shared.u64 t, %1; cvt.u32.u64 %0, t; }" : "=r"(a) : "l"(p));
    return a;
}
__device__ __forceinline__ void cp16(uint32_t dst, const void* src) {
    asm volatile("cp.async.cg.shared.global [%0], [%1], 16;" :: "r"(dst), "l"(src));
}
__device__ __forceinline__ void cp_commit() { asm volatile("cp.async.commit_group;" ::: "memory"); }
__device__ __forceinline__ void ldsm4(uint32_t (&r)[4], uint32_t addr) {
    asm volatile("ldmatrix.sync.aligned.m8n8.x4.shared.b16 {%0,%1,%2,%3}, [%4];"
        : "=r"(r[0]), "=r"(r[1]), "=r"(r[2]), "=r"(r[3]) : "r"(addr));
}
__device__ __forceinline__ void mma16816(float (&d)[4], const uint32_t (&a)[4],
                                         uint32_t b0, uint32_t b1) {
    asm volatile("mma.sync.aligned.m16n8k16.row.col.f32.bf16.bf16.f32 "
        "{%0,%1,%2,%3},{%4,%5,%6,%7},{%8,%9},{%0,%1,%2,%3};"
        : "+f"(d[0]), "+f"(d[1]), "+f"(d[2]), "+f"(d[3])
        : "r"(a[0]), "r"(a[1]), "r"(a[2]), "r"(a[3]), "r"(b0), "r"(b1));
}
__device__ __forceinline__ void bsplit(float v, __nv_bfloat16& h, __nv_bfloat16& l) {
    h = __float2bfloat16(v);
    l = __float2bfloat16(v - __bfloat162float(h));
}

// ---------------- scratch ----------------
__device__ float g_q [M2*DM];
__device__ float g_q2[M2*DM];
__device__ float g_k [M2*DM];
__device__ float g_v [M2*DM];
__device__ float g_kr[MR*DM];
__device__ float g_ef[2*M2*NH*2];
__device__ float g_o [2*M2*DM];
__device__ float g_y [2*M2*DM];
__device__ float g_z [2*M2*DM];
__device__ float g_bkT [32*QL];
__device__ float g_bkrT[32*RL];
__device__ float g_S [2*SSTR];
__device__ float g_BD[2*BSTR];
__device__ __align__(256) __nv_bfloat16 g_diffb[(size_t)2*QL*QL];
__device__ __align__(256) __nv_bfloat16 g_hbh[M2*DM], g_hbl[M2*DM];
__device__ __align__(256) __nv_bfloat16 g_rbh[MR*DM], g_rbl[MR*DM];
__device__ __align__(256) __nv_bfloat16 g_gbh[M2*DM], g_gbl[M2*DM];
__device__ __align__(256) __nv_bfloat16 g_wqT[2*DM*DM], g_wkT[2*DM*DM], g_wvT[2*DM*DM];
__device__ __align__(256) __nv_bfloat16 g_wrT[2*DM*DM], g_woC[2*DM*DM];
__device__ __align__(256) __nv_bfloat16 g_w1T[2*DM*DI], g_w2T[2*DI*DM];
__device__ __align__(256) __nv_bfloat16 g_q1h[32*QL*DH], g_q1l[32*QL*DH];
__device__ __align__(256) __nv_bfloat16 g_q2h[32*QL*DH], g_q2l[32*QL*DH];
__device__ __align__(256) __nv_bfloat16 g_khh[32*QL*DH], g_khl[32*QL*DH];
__device__ __align__(256) __nv_bfloat16 g_krh[32*RL*DH], g_krl[32*RL*DH];
__device__ __align__(256) __nv_bfloat16 g_vth[32*DH*QL], g_vtl[32*DH*QL];
__device__ __align__(256) __nv_bfloat16 g_Ph [2*SSTR], g_Pl [2*SSTR];
__device__ __align__(256) __nv_bfloat16 g_ath[2*M2*DM], g_atl[2*M2*DM];
__device__ __align__(256) __nv_bfloat16 g_yh [2*M2*DM], g_yl [2*M2*DM];
__device__ __align__(256) __nv_bfloat16 g_th [2*M2*DI], g_tl [2*M2*DI];

// ---------------- small kernels ----------------
__global__ void conv_split(const float* __restrict__ X, __nv_bfloat16* __restrict__ hi,
                           __nv_bfloat16* __restrict__ lo, int n4)
{
    int i = blockIdx.x * blockDim.x + threadIdx.x;
    if (i >= n4) return;
    float4 v = ((const float4*)X)[i];
    __nv_bfloat16 h0,h1,h2,h3,l0,l1,l2,l3;
    bsplit(v.x,h0,l0); bsplit(v.y,h1,l1); bsplit(v.z,h2,l2); bsplit(v.w,h3,l3);
    ((__nv_bfloat162*)hi)[2*i]   = __nv_bfloat162(h0,h1);
    ((__nv_bfloat162*)hi)[2*i+1] = __nv_bfloat162(h2,h3);
    ((__nv_bfloat162*)lo)[2*i]   = __nv_bfloat162(l0,l1);
    ((__nv_bfloat162*)lo)[2*i+1] = __nv_bfloat162(l2,l3);
}

__global__ void convT_split(const float* __restrict__ W, __nv_bfloat16* __restrict__ hi,
                            __nv_bfloat16* __restrict__ lo, int K, int N)
{
    __shared__ float t[32][33];
    int k0 = blockIdx.y * 32, n0 = blockIdx.x * 32;
    int tx = threadIdx.x, ty = threadIdx.y;
#pragma unroll
    for (int p = 0; p < 4; p++)
        t[ty + p*8][tx] = W[(size_t)(k0 + ty + p*8)*N + n0 + tx];
    __syncthreads();
#pragma unroll
    for (int p = 0; p < 4; p++) {
        __nv_bfloat16 h, l;
        bsplit(t[tx][ty + p*8], h, l);
        size_t o = (size_t)(n0 + ty + p*8)*K + k0 + tx;
        hi[o] = h; lo[o] = l;
    }
}

__global__ void repack_vT(const float* __restrict__ V, __nv_bfloat16* __restrict__ hi,
                          __nv_bfloat16* __restrict__ lo)
{
    __shared__ float tile[32][33];
    int j0 = blockIdx.x * 32, d0 = blockIdx.y * 32;
    int bn = blockIdx.z, b = bn >> 4, n = bn & 15;
    int tx = threadIdx.x, ty = threadIdx.y;
#pragma unroll
    for (int p = 0; p < 4; p++)
        tile[ty + p*8][tx] = V[((size_t)(j0 + ty + p*8)*2 + b)*DM + n*DH + d0 + tx];
    __syncthreads();
#pragma unroll
    for (int p = 0; p < 4; p++) {
        __nv_bfloat16 h, l;
        bsplit(tile[tx][ty + p*8], h, l);
        size_t o = ((size_t)bn*DH + d0 + ty + p*8)*QL + j0 + tx;
        hi[o] = h; lo[o] = l;
    }
}

__global__ void prep_diff(const float* __restrict__ seg_mat, __nv_bfloat16* __restrict__ diff)
{
    size_t idx = (size_t)blockIdx.x * blockDim.x + threadIdx.x;
    if (idx >= (size_t)2*QL*QL) return;
    int j = idx & 1023, i = (idx >> 10) & 1023, b = (int)(idx >> 20);
    diff[idx] = __float2bfloat16(seg_mat[(((size_t)i*QL + j)*2 + b)*2 + 1]);
}

__global__ void bias_dotT(const float* __restrict__ X, const float* __restrict__ bias,
                          float* __restrict__ outT, int rowsPerB)
{
    const int gw = (blockIdx.x * blockDim.x + threadIdx.x) >> 5;
    const int lane = threadIdx.x & 31;
    if (gw >= rowsPerB * 2 * NH) return;
    const int row = gw >> 4, n = gw & 15;
    const int j = row >> 1, b = row & 1;
    float s = bias[n*DH + lane]      * X[(size_t)row*DM + n*DH + lane]
            + bias[n*DH + 32 + lane] * X[(size_t)row*DM + n*DH + 32 + lane];
#pragma unroll
    for (int o = 16; o; o >>= 1) s += __shfl_xor_sync(0xffffffffu, s, o);
    if (!lane) outT[(size_t)(b*16 + n)*rowsPerB + j] = s;
}

// z selects stream (0: q from g_q, 1: q2 from g_q2)
__global__ void ef_kernel(const float* __restrict__ rsb, const float* __restrict__ se)
{
    const int gw = (blockIdx.x * blockDim.x + threadIdx.x) >> 5;
    const int lane = threadIdx.x & 31;
    if (gw >= M2 * NH) return;
    const float* q = blockIdx.y ? g_q2 : g_q;
    float* ef = g_ef + (size_t)blockIdx.y * M2 * NH * 2;
    const int row = gw >> 4, n = gw & 15;
    const float v0 = q[(size_t)row*DM + n*DH + lane]      + rsb[n*DH + lane];
    const float v1 = q[(size_t)row*DM + n*DH + 32 + lane] + rsb[n*DH + 32 + lane];
    float s0 = v0*se[n*DH + lane] + v1*se[n*DH + 32 + lane];
    float s1 = v0*se[NH*DH + n*DH + lane] + v1*se[NH*DH + n*DH + 32 + lane];
#pragma unroll
    for (int o = 16; o; o >>= 1) {
        s0 += __shfl_xor_sync(0xffffffffu, s0, o);
        s1 += __shfl_xor_sync(0xffffffffu, s1, o);
    }
    if (!lane) { ef[gw*2] = s0; ef[gw*2 + 1] = s1; }
}

// g-stream row i=0 fully masked -> exactly uniform 1/1024 -> column mean of V
__global__ void vmean_fix(const float* __restrict__ V,
                          __nv_bfloat16* __restrict__ Oh, __nv_bfloat16* __restrict__ Ol)
{
    int bn = blockIdx.x, b = bn >> 4, n = bn & 15;
    int d = threadIdx.x;
    float s = 0.f;
    for (int j = 0; j < QL; j++) s += V[((size_t)j*2 + b)*DM + n*DH + d];
    s *= (1.0f/1024.0f);
    __nv_bfloat16 hh, ll; bsplit(s, hh, ll);
    size_t o = (size_t)M2*DM + (size_t)b*DM + n*DH + d;
    Oh[o] = hh; Ol[o] = ll;
}

// ---------------- shared 3-stage GEMM core ----------------
#define GSTAGE 65536
#define GSMEM_BYTES (3*GSTAGE)

__device__ __forceinline__ void g_load_stage(
    const __nv_bfloat16* __restrict__ Ah, const __nv_bfloat16* __restrict__ Al,
    const __nv_bfloat16* __restrict__ Bh, const __nv_bfloat16* __restrict__ Bl,
    uint32_t st, int m0, int n0, int K, int kc, int tid)
{
    const size_t ko = (size_t)kc * 64;
#pragma unroll
    for (int p = 0; p < 4; p++) {
        int c = p*256 + tid;
        int row = c >> 3, kcol = c & 7;
        uint32_t sw = (uint32_t)(row*128 + kcol*16) ^ ((row & 7) << 4);
        const size_t ga = (size_t)(m0 + row)*K + ko + kcol*8;
        const size_t gb = (size_t)(n0 + row)*K + ko + kcol*8;
        cp16(st + sw,         Ah + ga);
        cp16(st + 16384 + sw, Al + ga);
        cp16(st + 32768 + sw, Bh + gb);
        cp16(st + 49152 + sw, Bl + gb);
    }
    cp_commit();
}

template<int EPI, int OUT>   // OUT: 0 fp32, 1 bf16 hi/lo row-major, 2 fp32 + head-major bf16
__device__ __forceinline__ void gemm_core(
    const __nv_bfloat16* __restrict__ Ah, const __nv_bfloat16* __restrict__ Al,
    const __nv_bfloat16* __restrict__ Bh, const __nv_bfloat16* __restrict__ Bl,
    const float* __restrict__ bias, float* __restrict__ C,
    __nv_bfloat16* __restrict__ Chi, __nv_bfloat16* __restrict__ Clo,
    int rowsPerB, int K, int ldc)
{
    extern __shared__ char dsm[];
    const uint32_t sbase = smem_u32(dsm);
    const int tid = threadIdx.x, lane = tid & 31, warp = tid >> 5;
    const int m0 = blockIdx.y * 128, n0 = blockIdx.x * 128;
    const int wm = (warp & 1) * 64, wn = (warp >> 1) * 32;
    const int NC = K >> 6;

    float acc[4][4][4] = {};
    g_load_stage(Ah, Al, Bh, Bl, sbase,            m0, n0, K, 0, tid);
    g_load_stage(Ah, Al, Bh, Bl, sbase + GSTAGE,   m0, n0, K, 1, tid);
    g_load_stage(Ah, Al, Bh, Bl, sbase + 2*GSTAGE, m0, n0, K, 2, tid);
    asm volatile("cp.async.wait_group 2;" ::: "memory");
    __syncthreads();

    const int arow = wm + (lane & 15), akb = lane & 16;
    const int brow = wn + ((lane & 16) >> 1) + (lane & 7), bkb = (lane & 8) << 1;

    int buf = 0;
    for (int kc = 0; kc < NC; kc++) {
        const uint32_t st = sbase + buf * GSTAGE;
#pragma unroll
        for (int ks = 0; ks < 4; ks++) {
            const int kb = ks*32;
            uint32_t ah[4][4], al[4][4], bh[2][4], bl[2][4];
#pragma unroll
            for (int im = 0; im < 4; im++) {
                int row = arow + im*16;
                uint32_t off = (uint32_t)(row*128 + kb + akb) ^ ((row & 7) << 4);
                ldsm4(ah[im], st + off);
                ldsm4(al[im], st + 16384 + off);
            }
#pragma unroll
            for (int np = 0; np < 2; np++) {
                int row = brow + np*16;
                uint32_t off = (uint32_t)(row*128 + kb + bkb) ^ ((row & 7) << 4);
                ldsm4(bh[np], st + 32768 + off);
                ldsm4(bl[np], st + 49152 + off);
            }
#pragma unroll
            for (int im = 0; im < 4; im++)
#pragma unroll
                for (int in = 0; in < 4; in++) {
                    const int np = in >> 1, hf = (in & 1) * 2;
                    mma16816(acc[im][in], ah[im], bh[np][hf], bh[np][hf+1]);
                    mma16816(acc[im][in], ah[im], bl[np][hf], bl[np][hf+1]);
                    mma16816(acc[im][in], al[im], bh[np][hf], bh[np][hf+1]);
                }
        }
        __syncthreads();
        if (kc + 3 < NC) {
            g_load_stage(Ah, Al, Bh, Bl, sbase + buf*GSTAGE, m0, n0, K, kc + 3, tid);
            asm volatile("cp.async.wait_group 2;" ::: "memory");
        } else if (kc + 2 < NC) {
            asm volatile("cp.async.wait_group 1;" ::: "memory");
        } else {
            asm volatile("cp.async.wait_group 0;" ::: "memory");
        }
        __syncthreads();
        buf++; if (buf == 3) buf = 0;
    }

    const int rbase = m0 + wm + (lane >> 2);
    const int cbase = n0 + wn + 2*(lane & 3);
#pragma unroll
    for (int im = 0; im < 4; im++) {
#pragma unroll
        for (int in = 0; in < 4; in++) {
            int col = cbase + in*8;
            float v0 = acc[im][in][0], v1 = acc[im][in][1];
            float v2 = acc[im][in][2], v3 = acc[im][in][3];
            if (EPI >= 1) {
                float b0 = bias[col], b1 = bias[col+1];
                v0 += b0; v1 += b1; v2 += b0; v3 += b1;
            }
            if (EPI == 2) {
                v0 = 0.5f*v0*(1.0f + erff(v0*0.7071067811865476f));
                v1 = 0.5f*v1*(1.0f + erff(v1*0.7071067811865476f));
                v2 = 0.5f*v2*(1.0f + erff(v2*0.7071067811865476f));
                v3 = 0.5f*v3*(1.0f + erff(v3*0.7071067811865476f));
            }
            int r0 = rbase + im*16, r1 = r0 + 8;
            if (OUT != 1) {
                *(float2*)(C + (size_t)r0*ldc + col) = make_float2(v0, v1);
                *(float2*)(C + (size_t)r1*ldc + col) = make_float2(v2, v3);
            }
            if (OUT >= 1) {
                __nv_bfloat16 h0,h1,h2,h3,l0,l1,l2,l3;
                bsplit(v0,h0,l0); bsplit(v1,h1,l1); bsplit(v2,h2,l2); bsplit(v3,h3,l3);
                size_t d0, d1;
                if (OUT == 1) { d0 = (size_t)r0*ldc + col; d1 = (size_t)r1*ldc + col; }
                else {
                    int nh = col >> 6, d = col & 63;
                    d0 = (((size_t)(r0 & 1)*NH + nh)*rowsPerB + (r0 >> 1))*DH + d;
                    d1 = (((size_t)(r1 & 1)*NH + nh)*rowsPerB + (r1 >> 1))*DH + d;
                }
                *(__nv_bfloat162*)(Chi + d0) = __nv_bfloat162(h0, h1);
                *(__nv_bfloat162*)(Chi + d1) = __nv_bfloat162(h2, h3);
                *(__nv_bfloat162*)(Clo + d0) = __nv_bfloat162(l0, l1);
                *(__nv_bfloat162*)(Clo + d1) = __nv_bfloat162(l2, l3);
            }
        }
    }
}

template<int EPI, int OUT>
__global__ void __launch_bounds__(256, 1) gemm_mma(
    const __nv_bfloat16* __restrict__ Ah, const __nv_bfloat16* __restrict__ Al,
    const __nv_bfloat16* __restrict__ Bh, const __nv_bfloat16* __restrict__ Bl,
    const float* __restrict__ bias, float* __restrict__ C,
    __nv_bfloat16* __restrict__ Chi, __nv_bfloat16* __restrict__ Clo,
    size_t zsA, size_t zsC, int rowsPerB, int K, int ldc)
{
    const size_t zo = blockIdx.z;
    gemm_core<EPI, OUT>(Ah + zo*zsA, Al + zo*zsA, Bh, Bl, bias,
                        (OUT != 1) ? C + zo*zsC : C,
                        (OUT >= 1) ? Chi + zo*zsC : Chi,
                        (OUT >= 1) ? Clo + zo*zsC : Clo,
                        rowsPerB, K, ldc);
}

// merged k/v/q projections from h (z: 0=k OUT2, 1=v OUT0, 2=q OUT2)
__global__ void __launch_bounds__(256, 1) projHKV()
{
    switch (blockIdx.z) {
    case 0: gemm_core<0,2>(g_hbh, g_hbl, g_wkT, g_wkT + (size_t)DM*DM,
                           nullptr, g_k, g_khh, g_khl, QL, DM, DM); break;
    case 1: gemm_core<0,0>(g_hbh, g_hbl, g_wvT, g_wvT + (size_t)DM*DM,
                           nullptr, g_v, nullptr, nullptr, QL, DM, DM); break;
    default: gemm_core<0,2>(g_hbh, g_hbl, g_wqT, g_wqT + (size_t)DM*DM,
                            nullptr, g_q, g_q1h, g_q1l, QL, DM, DM); break;
    }
}

// ---------------- batched score GEMM (z = s*32+bn), causal-pruned ----------------
#define SC_SMEM 65536

__global__ void __launch_bounds__(256, 1) score_mma(
    const __nv_bfloat16* __restrict__ Q1h, const __nv_bfloat16* __restrict__ Q1l,
    const __nv_bfloat16* __restrict__ Q2h, const __nv_bfloat16* __restrict__ Q2l,
    const __nv_bfloat16* __restrict__ Kh, const __nv_bfloat16* __restrict__ Kl,
    const float* __restrict__ biasT, float* __restrict__ C,
    size_t zsC, int Ncols, int window)
{
    extern __shared__ char dsm[];
    const uint32_t st = smem_u32(dsm);
    const int tid = threadIdx.x, lane = tid & 31, warp = tid >> 5;
    const int zz = blockIdx.z, s = zz >> 5, bn = zz & 31;
    const __nv_bfloat16* Qh = s ? Q2h : Q1h;
    const __nv_bfloat16* Ql = s ? Q2l : Q1l;
    C += (size_t)s * zsC;

    int i0, j0;
    if (!window) {
        int t = blockIdx.x;
        int it = (int)((sqrtf(8.f*t + 1.f) - 1.f) * 0.5f);
        if ((it + 1)*(it + 2)/2 <= t) it++;
        else if (it*(it + 1)/2 > t) it--;
        int jt = t - it*(it + 1)/2;
        i0 = it * 128; j0 = jt * 128;
    } else {
        int it = blockIdx.y;
        int bx = blockIdx.x;
        if (bx > it + 1) return;
        i0 = it * 128;
        j0 = (7 - it + bx) * 128;
    }

    const size_t qb = ((size_t)bn*QL + i0)*DH;
    const size_t kb = ((size_t)bn*Ncols + j0)*DH;
#pragma unroll
    for (int p = 0; p < 4; p++) {
        int c = p*256 + tid;
        int row = c >> 3, kcol = c & 7;
        uint32_t sw = (uint32_t)(row*128 + kcol*16) ^ ((row & 7) << 4);
        cp16(st + sw,         Qh + qb + (size_t)row*DH + kcol*8);
        cp16(st + 16384 + sw, Ql + qb + (size_t)row*DH + kcol*8);
        cp16(st + 32768 + sw, Kh + kb + (size_t)row*DH + kcol*8);
        cp16(st + 49152 + sw, Kl + kb + (size_t)row*DH + kcol*8);
    }
    cp_commit();
    asm volatile("cp.async.wait_group 0;" ::: "memory");
    __syncthreads();

    const int wm = (warp & 1) * 64, wn = (warp >> 1) * 32;
    const int arow = wm + (lane & 15), akb = lane & 16;
    const int brow = wn + ((lane & 16) >> 1) + (lane & 7), bkb = (lane & 8) << 1;

    float acc[4][4][4] = {};
#pragma unroll
    for (int ks = 0; ks < 4; ks++) {
        const int kbyte = ks*32;
        uint32_t ah[4][4], al[4][4], bh[2][4], bl[2][4];
#pragma unroll
        for (int im = 0; im < 4; im++) {
            int row = arow + im*16;
            uint32_t off = (uint32_t)(row*128 + kbyte + akb) ^ ((row & 7) << 4);
            ldsm4(ah[im], st + off);
            ldsm4(al[im], st + 16384 + off);
        }
#pragma unroll
        for (int np = 0; np < 2; np++) {
            int row = brow + np*16;
            uint32_t off = (uint32_t)(row*128 + kbyte + bkb) ^ ((row & 7) << 4);
            ldsm4(bh[np], st + 32768 + off);
            ldsm4(bl[np], st + 49152 + off);
        }
#pragma unroll
        for (int im = 0; im < 4; im++)
#pragma unroll
            for (int in = 0; in < 4; in++) {
                const int np = in >> 1, hf = (in & 1) * 2;
                mma16816(acc[im][in], ah[im], bh[np][hf], bh[np][hf+1]);
                mma16816(acc[im][in], ah[im], bl[np][hf], bl[np][hf+1]);
                mma16816(acc[im][in], al[im], bh[np][hf], bh[np][hf+1]);
            }
    }

    float* Cb = C + (size_t)bn*QL*Ncols;
    const float* bt = biasT + (size_t)bn*Ncols;
    const int rbase = i0 + wm + (lane >> 2);
    const int cbase = j0 + wn + 2*(lane & 3);
#pragma unroll
    for (int im = 0; im < 4; im++)
#pragma unroll
        for (int in = 0; in < 4; in++) {
            int col = cbase + in*8;
            float b0 = bt[col], b1 = bt[col+1];
            int r0 = rbase + im*16, r1 = r0 + 8;
            *(float2*)(Cb + (size_t)r0*Ncols + col) =
                make_float2(acc[im][in][0] + b0, acc[im][in][1] + b1);
            *(float2*)(Cb + (size_t)r1*Ncols + col) =
                make_float2(acc[im][in][2] + b0, acc[im][in][3] + b1);
        }
}

// ---------------- fused combine + softmax (causal-bounded) + bf16-split P ----------------
__global__ void __launch_bounds__(256) softmax_fused(
    const float* __restrict__ S, const float* __restrict__ BD,
    const __nv_bfloat16* __restrict__ diff, const float* __restrict__ ef,
    __nv_bfloat16* __restrict__ Ph, __nv_bfloat16* __restrict__ Pl)
{
    __shared__ float red[8];
    const int i = blockIdx.x;
    const int zz = blockIdx.y, s = zz >> 5, bn = zz & 31, b = bn >> 4, n = bn & 15;
    const int jmax = ((i >> 7) + 1) << 7;
    const float* Sr = S    + (size_t)s*SSTR + ((size_t)bn << 20) + ((size_t)i << 10);
    const float* Br = BD   + (size_t)s*BSTR + ((size_t)bn << 21) + ((size_t)i << 11) + (QL - i);
    const __nv_bfloat16* Dr = diff + ((size_t)b << 20) + ((size_t)i << 10);
    const float* efs = ef + (size_t)s*M2*NH*2;
    const float e0 = efs[(((size_t)i*2 + b)*NH + n)*2];
    const float de = efs[(((size_t)i*2 + b)*NH + n)*2 + 1] - e0;
    const int t = threadIdx.x, lane = t & 31, w = t >> 5;

    float v[4];
#pragma unroll
    for (int p = 0; p < 4; p++) {
        int j = t + p*256;
        if (j < jmax) {
            float sc = (Sr[j] + Br[j] + e0 + de*__bfloat162float(Dr[j])) * ATT_SCALE;
            bool blocked = s ? (j >= i) : (j > i);
            v[p] = blocked ? sc - 1e30f : sc;
        } else v[p] = -1e30f;
    }
    float m = fmaxf(fmaxf(v[0], v[1]), fmaxf(v[2], v[3]));
#pragma unroll
    for (int o = 16; o; o >>= 1) m = fmaxf(m, __shfl_xor_sync(0xffffffffu, m, o));
    if (!lane) red[w] = m;
    __syncthreads();
    m = red[lane & 7];
#pragma unroll
    for (int o = 4; o; o >>= 1) m = fmaxf(m, __shfl_xor_sync(0xffffffffu, m, o));
    float sum = 0.f;
#pragma unroll
    for (int p = 0; p < 4; p++) { v[p] = expf(v[p] - m); sum += v[p]; }
#pragma unroll
    for (int o = 16; o; o >>= 1) sum += __shfl_xor_sync(0xffffffffu, sum, o);
    __syncthreads();
    if (!lane) red[w] = sum;
    __syncthreads();
    sum = red[lane & 7];
#pragma unroll
    for (int o = 4; o; o >>= 1) sum += __shfl_xor_sync(0xffffffffu, sum, o);
    const float inv = 1.0f / sum;
    const size_t base = (size_t)s*SSTR + ((size_t)bn << 20) + ((size_t)i << 10);
#pragma unroll
    for (int p = 0; p < 4; p++) {
        int j = t + p*256;
        if (j < jmax) {
            __nv_bfloat16 ph, pl;
            bsplit(v[p] * inv, ph, pl);
            Ph[base + j] = ph;
            Pl[base + j] = pl;
        }
    }
}

// ---------------- batched PV GEMM (causal K bound) -> bf16 hi/lo attn ----------------
#define PV_STAGE 49152
#define PV_SMEM (2*PV_STAGE)

__device__ __forceinline__ void pv_load(
    const __nv_bfloat16* __restrict__ Ph, const __nv_bfloat16* __restrict__ Pl,
    const __nv_bfloat16* __restrict__ Vh, const __nv_bfloat16* __restrict__ Vl,
    uint32_t st, size_t pbase, size_t vbase, int kc, int tid)
{
    const size_t ko = (size_t)kc * 64;
#pragma unroll
    for (int p = 0; p < 4; p++) {
        int c = p*256 + tid;
        int row = c >> 3, kcol = c & 7;
        uint32_t sw = (uint32_t)(row*128 + kcol*16) ^ ((row & 7) << 4);
        cp16(st + sw,         Ph + pbase + (size_t)row*QL + ko + kcol*8);
        cp16(st + 16384 + sw, Pl + pbase + (size_t)row*QL + ko + kcol*8);
    }
#pragma unroll
    for (int p = 0; p < 2; p++) {
        int c = p*256 + tid;
        int row = c >> 3, kcol = c & 7;
        uint32_t sw = (uint32_t)(row*128 + kcol*16) ^ ((row & 7) << 4);
        cp16(st + 32768 + sw, Vh + vbase + (size_t)row*QL + ko + kcol*8);
        cp16(st + 40960 + sw, Vl + vbase + (size_t)row*QL + ko + kcol*8);
    }
    cp_commit();
}

__global__ void __launch_bounds__(256, 1) pv_mma(
    const __nv_bfloat16* __restrict__ Ph, const __nv_bfloat16* __restrict__ Pl,
    const __nv_bfloat16* __restrict__ Vh, const __nv_bfloat16* __restrict__ Vl,
    __nv_bfloat16* __restrict__ Oh, __nv_bfloat16* __restrict__ Ol)
{
    extern __shared__ char dsm[];
    const uint32_t sbase = smem_u32(dsm);
    const int tid = threadIdx.x, lane = tid & 31, warp = tid >> 5;
    const int zz = blockIdx.y, s = zz >> 5, bn = zz & 31, b = bn >> 4, n = bn & 15;
    const int it = blockIdx.x;
    const int i0 = it * 128;
    const int NC = 2*it + 2;
    const size_t pbase = (size_t)s*SSTR + ((size_t)bn << 20) + (size_t)i0*QL;
    const size_t vbase = (size_t)bn * DH * QL;
    const size_t obase = (size_t)s * M2 * DM;

    float acc[2][4][4] = {};
    pv_load(Ph, Pl, Vh, Vl, sbase,            pbase, vbase, 0, tid);
    pv_load(Ph, Pl, Vh, Vl, sbase + PV_STAGE, pbase, vbase, 1, tid);
    asm volatile("cp.async.wait_group 1;" ::: "memory");
    __syncthreads();

    const int wm = (warp & 3) * 32, wn = (warp >> 2) * 32;
    const int arow = wm + (lane & 15), akb = lane & 16;
    const int brow = wn + ((lane & 16) >> 1) + (lane & 7), bkb = (lane & 8) << 1;

    for (int kc = 0; kc < NC; kc++) {
        const uint32_t st = sbase + (kc & 1) * PV_STAGE;
#pragma unroll
        for (int ks = 0; ks < 4; ks++) {
            const int kb = ks*32;
            uint32_t ah[2][4], al[2][4], bh[2][4], bl[2][4];
#pragma unroll
            for (int im = 0; im < 2; im++) {
                int row = arow + im*16;
                uint32_t off = (uint32_t)(row*128 + kb + akb) ^ ((row & 7) << 4);
                ldsm4(ah[im], st + off);
                ldsm4(al[im], st + 16384 + off);
            }
#pragma unroll
            for (int np = 0; np < 2; np++) {
                int row = brow + np*16;
                uint32_t off = (uint32_t)(row*128 + kb + bkb) ^ ((row & 7) << 4);
                ldsm4(bh[np], st + 32768 + off);
                ldsm4(bl[np], st + 40960 + off);
            }
#pragma unroll
            for (int im = 0; im < 2; im++)
#pragma unroll
                for (int in = 0; in < 4; in++) {
                    const int np = in >> 1, hf = (in & 1) * 2;
                    mma16816(acc[im][in], ah[im], bh[np][hf], bh[np][hf+1]);
                    mma16816(acc[im][in], ah[im], bl[np][hf], bl[np][hf+1]);
                    mma16816(acc[im][in], al[im], bh[np][hf], bh[np][hf+1]);
                }
        }
        __syncthreads();
        if (kc + 2 < NC) {
            pv_load(Ph, Pl, Vh, Vl, sbase + (kc & 1)*PV_STAGE, pbase, vbase, kc + 2, tid);
            asm volatile("cp.async.wait_group 1;" ::: "memory");
        } else {
            asm volatile("cp.async.wait_group 0;" ::: "memory");
        }
        __syncthreads();
    }

    const int rl = wm + (lane >> 2);
    const int cb = wn + 2*(lane & 3);
#pragma unroll
    for (int im = 0; im < 2; im++)
#pragma unroll
        for (int in = 0; in < 4; in++) {
            int col = cb + in*8;
            int r0 = i0 + rl + im*16, r1 = r0 + 8;
            size_t d0 = obase + ((size_t)r0*2 + b)*DM + n*DH + col;
            size_t d1 = obase + ((size_t)r1*2 + b)*DM + n*DH + col;
            __nv_bfloat16 h0,h1,h2,h3,l0,l1,l2,l3;
            bsplit(acc[im][in][0],h0,l0); bsplit(acc[im][in][1],h1,l1);
            bsplit(acc[im][in][2],h2,l2); bsplit(acc[im][in][3],h3,l3);
            *(__nv_bfloat162*)(Oh + d0) = __nv_bfloat162(h0, h1);
            *(__nv_bfloat162*)(Oh + d1) = __nv_bfloat162(h2, h3);
            *(__nv_bfloat162*)(Ol + d0) = __nv_bfloat162(l0, l1);
            *(__nv_bfloat162*)(Ol + d1) = __nv_bfloat162(l2, l3);
        }
}

// ---------------- residual + LayerNorm (merged streams) ----------------
template<int WB16>
__global__ void __launch_bounds__(256) add_ln(
    const float* __restrict__ a, const float* __restrict__ x0, const float* __restrict__ x1,
    const float* __restrict__ gamma, const float* __restrict__ beta,
    float* __restrict__ out, __nv_bfloat16* __restrict__ oh, __nv_bfloat16* __restrict__ ol)
{
    __shared__ float buf[1024];
    __shared__ float red[8];
    __shared__ float s_stat;
    const size_t base = (size_t)blockIdx.x << 10;
    const int str = blockIdx.x >> 11;
    const size_t lbase = (size_t)(blockIdx.x & 2047) << 10;
    const float* x = str ? x1 : x0;
    const int t = threadIdx.x, lane = t & 31, w = t >> 5;
    float sum = 0.f;
#pragma unroll
    for (int p = 0; p < 4; p++) {
        float v = a[base + t + p*256] + x[lbase + t + p*256];
        buf[t + p*256] = v; sum += v;
    }
#pragma unroll
    for (int o = 16; o; o >>= 1) sum += __shfl_xor_sync(0xffffffffu, sum, o);
    if (!lane) red[w] = sum;
    __syncthreads();
    if (t == 0) { float s = 0; for (int i = 0; i < 8; i++) s += red[i]; s_stat = s * (1.0f/1024.0f); }
    __syncthreads();
    const float mean = s_stat;
    float vs = 0.f;
#pragma unroll
    for (int p = 0; p < 4; p++) { float d = buf[t + p*256] - mean; vs += d*d; }
#pragma unroll
    for (int o = 16; o; o >>= 1) vs += __shfl_xor_sync(0xffffffffu, vs, o);
    __syncthreads();
    if (!lane) red[w] = vs;
    __syncthreads();
    if (t == 0) { float s = 0; for (int i = 0; i < 8; i++) s += red[i]; s_stat = s * (1.0f/1024.0f); }
    __syncthreads();
    const float r = rsqrtf(s_stat + 1e-12f);
#pragma unroll
    for (int p = 0; p < 4; p++) {
        int c = t + p*256;
        float val = (buf[c] - mean) * r * gamma[c] + beta[c];
        out[base + c] = val;
        if (WB16) {
            __nv_bfloat16 hh, ll;
            bsplit(val, hh, ll);
            oh[base + c] = hh;
            ol[base + c] = ll;
        }
    }
}

// ---------------- host ----------------
extern "C" void kernel_launch(void* const* d_in, const int* in_sizes, int n_in,
                              void* d_out, int out_size)
{
    (void)in_sizes; (void)n_in; (void)out_size;
    const float* h       = (const float*)d_in[0];
    const float* g       = (const float*)d_in[1];
    const float* r       = (const float*)d_in[2];
    const float* seg_mat = (const float*)d_in[5];
    const float* wq      = (const float*)d_in[6];
    const float* wk      = (const float*)d_in[7];
    const float* wv      = (const float*)d_in[8];
    const float* wo      = (const float*)d_in[9];
    const float* wr      = (const float*)d_in[10];
    const float* rwb     = (const float*)d_in[11];
    const float* rrb     = (const float*)d_in[12];
    const float* rsb     = (const float*)d_in[13];
    const float* se      = (const float*)d_in[14];
    const float* lnga    = (const float*)d_in[15];
    const float* lnba    = (const float*)d_in[16];
    const float* w1      = (const float*)d_in[17];
    const float* b1      = (const float*)d_in[18];
    const float* w2      = (const float*)d_in[19];
    const float* b2      = (const float*)d_in[20];
    const float* lngf    = (const float*)d_in[21];
    const float* lnbf    = (const float*)d_in[22];

    cudaFuncSetAttribute(projHKV,       cudaFuncAttributeMaxDynamicSharedMemorySize, GSMEM_BYTES);
    cudaFuncSetAttribute(gemm_mma<0,0>, cudaFuncAttributeMaxDynamicSharedMemorySize, GSMEM_BYTES);
    cudaFuncSetAttribute(gemm_mma<0,2>, cudaFuncAttributeMaxDynamicSharedMemorySize, GSMEM_BYTES);
    cudaFuncSetAttribute(gemm_mma<2,1>, cudaFuncAttributeMaxDynamicSharedMemorySize, GSMEM_BYTES);
    cudaFuncSetAttribute(gemm_mma<1,0>, cudaFuncAttributeMaxDynamicSharedMemorySize, GSMEM_BYTES);
    cudaFuncSetAttribute(score_mma,     cudaFuncAttributeMaxDynamicSharedMemorySize, SC_SMEM);
    cudaFuncSetAttribute(pv_mma,        cudaFuncAttributeMaxDynamicSharedMemorySize, PV_SMEM);

    float *q2f,*k,*v,*kr,*ef,*o,*y,*z,*bkT,*bkrT,*S,*BD;
    __nv_bfloat16 *hbh,*hbl,*rbh,*rbl,*gbh,*gbl,*wqT,*wkT,*wvT,*wrT,*woC,*w1T,*w2T,*diffb;
    __nv_bfloat16 *q1h,*q1l,*q2h,*q2l,*khh,*khl,*krh,*krl,*vth,*vtl,*Ph,*Pl,*ath,*atl,*yh,*yl,*th,*tl;
    cudaGetSymbolAddress((void**)&q2f,  g_q2);
    cudaGetSymbolAddress((void**)&k,    g_k);
    cudaGetSymbolAddress((void**)&v,    g_v);
    cudaGetSymbolAddress((void**)&kr,   g_kr);
    cudaGetSymbolAddress((void**)&ef,   g_ef);
    cudaGetSymbolAddress((void**)&o,    g_o);
    cudaGetSymbolAddress((void**)&y,    g_y);
    cudaGetSymbolAddress((void**)&z,    g_z);
    cudaGetSymbolAddress((void**)&bkT,  g_bkT);
    cudaGetSymbolAddress((void**)&bkrT, g_bkrT);
    cudaGetSymbolAddress((void**)&S,    g_S);
    cudaGetSymbolAddress((void**)&BD,   g_BD);
    cudaGetSymbolAddress((void**)&diffb,g_diffb);
    cudaGetSymbolAddress((void**)&hbh,  g_hbh);
    cudaGetSymbolAddress((void**)&hbl,  g_hbl);
    cudaGetSymbolAddress((void**)&rbh,  g_rbh);
    cudaGetSymbolAddress((void**)&rbl,  g_rbl);
    cudaGetSymbolAddress((void**)&gbh,  g_gbh);
    cudaGetSymbolAddress((void**)&gbl,  g_gbl);
    cudaGetSymbolAddress((void**)&wqT,  g_wqT);
    cudaGetSymbolAddress((void**)&wkT,  g_wkT);
    cudaGetSymbolAddress((void**)&wvT,  g_wvT);
    cudaGetSymbolAddress((void**)&wrT,  g_wrT);
    cudaGetSymbolAddress((void**)&woC,  g_woC);
    cudaGetSymbolAddress((void**)&w1T,  g_w1T);
    cudaGetSymbolAddress((void**)&w2T,  g_w2T);
    cudaGetSymbolAddress((void**)&q1h,  g_q1h);
    cudaGetSymbolAddress((void**)&q1l,  g_q1l);
    cudaGetSymbolAddress((void**)&q2h,  g_q2h);
    cudaGetSymbolAddress((void**)&q2l,  g_q2l);
    cudaGetSymbolAddress((void**)&khh,  g_khh);
    cudaGetSymbolAddress((void**)&khl,  g_khl);
    cudaGetSymbolAddress((void**)&krh,  g_krh);
    cudaGetSymbolAddress((void**)&krl,  g_krl);
    cudaGetSymbolAddress((void**)&vth,  g_vth);
    cudaGetSymbolAddress((void**)&vtl,  g_vtl);
    cudaGetSymbolAddress((void**)&Ph,   g_Ph);
    cudaGetSymbolAddress((void**)&Pl,   g_Pl);
    cudaGetSymbolAddress((void**)&ath,  g_ath);
    cudaGetSymbolAddress((void**)&atl,  g_atl);
    cudaGetSymbolAddress((void**)&yh,   g_yh);
    cudaGetSymbolAddress((void**)&yl,   g_yl);
    cudaGetSymbolAddress((void**)&th,   g_th);
    cudaGetSymbolAddress((void**)&tl,   g_tl);

    dim3 tb(32, 8);
    // launches 1-4: deps for projHKV; launch 5 = projHKV (ncu profile target)
    convT_split<<<dim3(DM/32, DM/32), tb>>>(wk, wkT, wkT + (size_t)DM*DM, DM, DM);
    convT_split<<<dim3(DM/32, DM/32), tb>>>(wv, wvT, wvT + (size_t)DM*DM, DM, DM);
    convT_split<<<dim3(DM/32, DM/32), tb>>>(wq, wqT, wqT + (size_t)DM*DM, DM, DM);
    conv_split<<<(M2*DM/4 + 255)/256, 256>>>(h, hbh, hbl, M2*DM/4);
    projHKV<<<dim3(8, 16, 3), 256, GSMEM_BYTES>>>();

    convT_split<<<dim3(DM/32, DM/32), tb>>>(wr, wrT, wrT + (size_t)DM*DM, DM, DM);
    conv_split<<<(MR*DM/4 + 255)/256, 256>>>(r, rbh, rbl, MR*DM/4);
    conv_split<<<(M2*DM/4 + 255)/256, 256>>>(g, gbh, gbl, M2*DM/4);
    conv_split<<<(DM*DM/4 + 255)/256, 256>>>(wo, woC, woC + (size_t)DM*DM, DM*DM/4);
    convT_split<<<dim3(DI/32, DM/32), tb>>>(w1, w1T, w1T + (size_t)DM*DI, DM, DI);
    convT_split<<<dim3(DM/32, DI/32), tb>>>(w2, w2T, w2T + (size_t)DI*DM, DI, DM);
    prep_diff<<<(2*QL*QL + 255)/256, 256>>>(seg_mat, diffb);

    gemm_mma<0,2><<<dim3(8,32,1), 256, GSMEM_BYTES>>>(rbh, rbl, wrT, wrT+(size_t)DM*DM,
        nullptr, kr, krh, krl, 0, 0, RL, DM, DM);
    gemm_mma<0,2><<<dim3(8,16,1), 256, GSMEM_BYTES>>>(gbh, gbl, wqT, wqT+(size_t)DM*DM,
        nullptr, q2f, q2h, q2l, 0, 0, QL, DM, DM);
    repack_vT<<<dim3(QL/32, DH/32, 32), tb>>>(v, vth, vtl);

    bias_dotT<<<(M2*NH*32 + 255)/256, 256>>>(k,  rwb, bkT,  QL);
    bias_dotT<<<(MR*NH*32 + 255)/256, 256>>>(kr, rrb, bkrT, RL);
    ef_kernel<<<dim3((M2*NH*32 + 255)/256, 2), 256>>>(rsb, se);

    // attention (both streams merged; causal-pruned)
    score_mma<<<dim3(36, 1, 64), 256, SC_SMEM>>>(q1h, q1l, q2h, q2l, khh, khl, bkT,  S,  SSTR, QL, 0);
    score_mma<<<dim3(9, 8, 64), 256, SC_SMEM>>>(q1h, q1l, q2h, q2l, krh, krl, bkrT, BD, BSTR, RL, 1);
    softmax_fused<<<dim3(QL, 64), 256>>>(S, BD, diffb, ef, Ph, Pl);
    pv_mma<<<dim3(8, 64), 256, PV_SMEM>>>(Ph, Pl, vth, vtl, ath, atl);
    vmean_fix<<<32, 64>>>(v, ath, atl);

    // back half (both streams merged via z)
    gemm_mma<0,0><<<dim3(8,16,2), 256, GSMEM_BYTES>>>(ath, atl, woC, woC+(size_t)DM*DM,
        nullptr, o, nullptr, nullptr, (size_t)M2*DM, (size_t)M2*DM, QL, DM, DM);
    add_ln<1><<<2*M2, 256>>>(o, h, g, lnga, lnba, y, yh, yl);
    gemm_mma<2,1><<<dim3(32,16,2), 256, GSMEM_BYTES>>>(yh, yl, w1T, w1T+(size_t)DM*DI,
        b1, nullptr, th, tl, (size_t)M2*DM, (size_t)M2*DI, QL, DM, DI);
    gemm_mma<1,0><<<dim3(8,16,2), 256, GSMEM_BYTES>>>(th, tl, w2T, w2T+(size_t)DI*DM,
        b2, z, nullptr, nullptr, (size_t)M2*DI, (size_t)M2*DM, QL, DI, DM);
    add_ln<0><<<2*M2, 256>>>(z, y, y + (size_t)M2*DM, lngf, lnbf, (float*)d_out, nullptr, nullptr);
}

// round 10
// speedup vs baseline: 1.7206x; 1.2092x over previous
#include <cuda_runtime.h>
#include <cuda_fp16.h>
#include <math.h>
#include <stdint.h>

#define QL 1024
#define NH 16
#define DH 64
#define DM 1024
#define DI 4096
#define RL 2048
#define M2 (QL*2)
#define MR (RL*2)
#define ATT_SCALE 0.125f
#define SSTR ((size_t)32*QL*QL)
#define BSTR ((size_t)32*QL*RL)

__device__ __forceinline__ uint32_t smem_u32(const void* p) {
    uint32_t a;
    asm("{ .reg .u64 t; cvta.to.shared.u64 t, %1; cvt.u32.u64 %0, t; }" : "=r"(a) : "l"(p));
    return a;
}
__device__ __forceinline__ void cp16(uint32_t dst, const void* src) {
    asm volatile("cp.async.cg.shared.global [%0], [%1], 16;" :: "r"(dst), "l"(src));
}
__device__ __forceinline__ void cp_commit() { asm volatile("cp.async.commit_group;" ::: "memory"); }
__device__ __forceinline__ void ldsm4(uint32_t (&r)[4], uint32_t addr) {
    asm volatile("ldmatrix.sync.aligned.m8n8.x4.shared.b16 {%0,%1,%2,%3}, [%4];"
        : "=r"(r[0]), "=r"(r[1]), "=r"(r[2]), "=r"(r[3]) : "r"(addr));
}
__device__ __forceinline__ void mma16816(float (&d)[4], const uint32_t (&a)[4],
                                         uint32_t b0, uint32_t b1) {
    asm volatile("mma.sync.aligned.m16n8k16.row.col.f32.f16.f16.f32 "
        "{%0,%1,%2,%3},{%4,%5,%6,%7},{%8,%9},{%0,%1,%2,%3};"
        : "+f"(d[0]), "+f"(d[1]), "+f"(d[2]), "+f"(d[3])
        : "r"(a[0]), "r"(a[1]), "r"(a[2]), "r"(a[3]), "r"(b0), "r"(b1));
}
__device__ __forceinline__ void hsplit(float v, __half& h, __half& l) {
    h = __float2half_rn(v);
    l = __float2half_rn(v - __half2float(h));
}

// ---------------- scratch ----------------
__device__ float g_q [M2*DM];
__device__ float g_q2[M2*DM];
__device__ float g_k [M2*DM];
__device__ float g_v [M2*DM];
__device__ float g_kr[MR*DM];
__device__ float g_ef[2*M2*NH*2];
__device__ float g_o [2*M2*DM];
__device__ float g_y [2*M2*DM];
__device__ float g_z [2*M2*DM];
__device__ float g_bkT [32*QL];
__device__ float g_bkrT[32*RL];
__device__ float g_S [2*SSTR];
__device__ float g_BD[2*BSTR];
__device__ __align__(256) __half g_diffb[(size_t)2*QL*QL];
__device__ __align__(256) __half g_hb[M2*DM], g_rb[MR*DM], g_gb[M2*DM];   // single-A
__device__ __align__(256) __half g_wqT[2*DM*DM], g_wkT[2*DM*DM], g_wvT[2*DM*DM];
__device__ __align__(256) __half g_wrT[2*DM*DM], g_woC[2*DM*DM];
__device__ __align__(256) __half g_w1T[2*DM*DI], g_w2T[2*DI*DM];
__device__ __align__(256) __half g_q1h[32*QL*DH], g_q1l[32*QL*DH];
__device__ __align__(256) __half g_q2h[32*QL*DH], g_q2l[32*QL*DH];
__device__ __align__(256) __half g_khh[32*QL*DH], g_khl[32*QL*DH];
__device__ __align__(256) __half g_krh[32*RL*DH], g_krl[32*RL*DH];
__device__ __align__(256) __half g_vth[32*DH*QL], g_vtl[32*DH*QL];
__device__ __align__(256) __half g_Ph [2*SSTR], g_Pl [2*SSTR];
__device__ __align__(256) __half g_at [2*M2*DM];    // single
__device__ __align__(256) __half g_yh [2*M2*DM];    // single
__device__ __align__(256) __half g_th [2*M2*DI];    // single

// ---------------- small kernels ----------------
__global__ void conv_half(const float* __restrict__ X, __half* __restrict__ out, int n4)
{
    int i = blockIdx.x * blockDim.x + threadIdx.x;
    if (i >= n4) return;
    float4 v = ((const float4*)X)[i];
    ((__half2*)out)[2*i]   = __halves2half2(__float2half_rn(v.x), __float2half_rn(v.y));
    ((__half2*)out)[2*i+1] = __halves2half2(__float2half_rn(v.z), __float2half_rn(v.w));
}

__global__ void conv_split(const float* __restrict__ X, __half* __restrict__ hi,
                           __half* __restrict__ lo, int n4)
{
    int i = blockIdx.x * blockDim.x + threadIdx.x;
    if (i >= n4) return;
    float4 v = ((const float4*)X)[i];
    __half h0,h1,h2,h3,l0,l1,l2,l3;
    hsplit(v.x,h0,l0); hsplit(v.y,h1,l1); hsplit(v.z,h2,l2); hsplit(v.w,h3,l3);
    ((__half2*)hi)[2*i]   = __halves2half2(h0,h1);
    ((__half2*)hi)[2*i+1] = __halves2half2(h2,h3);
    ((__half2*)lo)[2*i]   = __halves2half2(l0,l1);
    ((__half2*)lo)[2*i+1] = __halves2half2(l2,l3);
}

__global__ void convT_split(const float* __restrict__ W, __half* __restrict__ hi,
                            __half* __restrict__ lo, int K, int N)
{
    __shared__ float t[32][33];
    int k0 = blockIdx.y * 32, n0 = blockIdx.x * 32;
    int tx = threadIdx.x, ty = threadIdx.y;
#pragma unroll
    for (int p = 0; p < 4; p++)
        t[ty + p*8][tx] = W[(size_t)(k0 + ty + p*8)*N + n0 + tx];
    __syncthreads();
#pragma unroll
    for (int p = 0; p < 4; p++) {
        __half h, l;
        hsplit(t[tx][ty + p*8], h, l);
        size_t o = (size_t)(n0 + ty + p*8)*K + k0 + tx;
        hi[o] = h; lo[o] = l;
    }
}

__global__ void repack_vT(const float* __restrict__ V, __half* __restrict__ hi,
                          __half* __restrict__ lo)
{
    __shared__ float tile[32][33];
    int j0 = blockIdx.x * 32, d0 = blockIdx.y * 32;
    int bn = blockIdx.z, b = bn >> 4, n = bn & 15;
    int tx = threadIdx.x, ty = threadIdx.y;
#pragma unroll
    for (int p = 0; p < 4; p++)
        tile[ty + p*8][tx] = V[((size_t)(j0 + ty + p*8)*2 + b)*DM + n*DH + d0 + tx];
    __syncthreads();
#pragma unroll
    for (int p = 0; p < 4; p++) {
        __half h, l;
        hsplit(tile[tx][ty + p*8], h, l);
        size_t o = ((size_t)bn*DH + d0 + ty + p*8)*QL + j0 + tx;
        hi[o] = h; lo[o] = l;
    }
}

__global__ void prep_diff(const float* __restrict__ seg_mat, __half* __restrict__ diff)
{
    size_t idx = (size_t)blockIdx.x * blockDim.x + threadIdx.x;
    if (idx >= (size_t)2*QL*QL) return;
    int j = idx & 1023, i = (idx >> 10) & 1023, b = (int)(idx >> 20);
    diff[idx] = __float2half_rn(seg_mat[(((size_t)i*QL + j)*2 + b)*2 + 1]);
}

__global__ void bias_dotT(const float* __restrict__ X, const float* __restrict__ bias,
                          float* __restrict__ outT, int rowsPerB)
{
    const int gw = (blockIdx.x * blockDim.x + threadIdx.x) >> 5;
    const int lane = threadIdx.x & 31;
    if (gw >= rowsPerB * 2 * NH) return;
    const int row = gw >> 4, n = gw & 15;
    const int j = row >> 1, b = row & 1;
    float s = bias[n*DH + lane]      * X[(size_t)row*DM + n*DH + lane]
            + bias[n*DH + 32 + lane] * X[(size_t)row*DM + n*DH + 32 + lane];
#pragma unroll
    for (int o = 16; o; o >>= 1) s += __shfl_xor_sync(0xffffffffu, s, o);
    if (!lane) outT[(size_t)(b*16 + n)*rowsPerB + j] = s;
}

__global__ void ef_kernel(const float* __restrict__ rsb, const float* __restrict__ se)
{
    const int gw = (blockIdx.x * blockDim.x + threadIdx.x) >> 5;
    const int lane = threadIdx.x & 31;
    if (gw >= M2 * NH) return;
    const float* q = blockIdx.y ? g_q2 : g_q;
    float* ef = g_ef + (size_t)blockIdx.y * M2 * NH * 2;
    const int row = gw >> 4, n = gw & 15;
    const float v0 = q[(size_t)row*DM + n*DH + lane]      + rsb[n*DH + lane];
    const float v1 = q[(size_t)row*DM + n*DH + 32 + lane] + rsb[n*DH + 32 + lane];
    float s0 = v0*se[n*DH + lane] + v1*se[n*DH + 32 + lane];
    float s1 = v0*se[NH*DH + n*DH + lane] + v1*se[NH*DH + n*DH + 32 + lane];
#pragma unroll
    for (int o = 16; o; o >>= 1) {
        s0 += __shfl_xor_sync(0xffffffffu, s0, o);
        s1 += __shfl_xor_sync(0xffffffffu, s1, o);
    }
    if (!lane) { ef[gw*2] = s0; ef[gw*2 + 1] = s1; }
}

// g-stream row i=0 fully masked -> exactly uniform 1/1024 -> column mean of V
__global__ void vmean_fix(const float* __restrict__ V, __half* __restrict__ O)
{
    int bn = blockIdx.x, b = bn >> 4, n = bn & 15;
    int d = threadIdx.x;
    float s = 0.f;
    for (int j = 0; j < QL; j++) s += V[((size_t)j*2 + b)*DM + n*DH + d];
    s *= (1.0f/1024.0f);
    O[(size_t)M2*DM + (size_t)b*DM + n*DH + d] = __float2half_rn(s);
}

// ---------------- dense GEMM: C = A(fp16 single) @ [Bh+Bl]^T, 2-pass, 3-stage ----------------
#define GSTAGE 49152
#define GSMEM_BYTES (3*GSTAGE)

__device__ __forceinline__ void g_load_stage(
    const __half* __restrict__ A, const __half* __restrict__ Bh, const __half* __restrict__ Bl,
    uint32_t st, int m0, int n0, int K, int kc, int tid)
{
    const size_t ko = (size_t)kc * 64;
#pragma unroll
    for (int p = 0; p < 4; p++) {
        int c = p*256 + tid;
        int row = c >> 3, kcol = c & 7;
        uint32_t sw = (uint32_t)(row*128 + kcol*16) ^ ((row & 7) << 4);
        cp16(st + sw,         A  + (size_t)(m0 + row)*K + ko + kcol*8);
        cp16(st + 16384 + sw, Bh + (size_t)(n0 + row)*K + ko + kcol*8);
        cp16(st + 32768 + sw, Bl + (size_t)(n0 + row)*K + ko + kcol*8);
    }
    cp_commit();
}

// OUT: 0 fp32 C; 1 single fp16 row-major; 2 fp32 C + head-major fp16 hi/lo
template<int EPI, int OUT>
__device__ __forceinline__ void gemm_core(
    const __half* __restrict__ A, const __half* __restrict__ Bh, const __half* __restrict__ Bl,
    const float* __restrict__ bias, float* __restrict__ C,
    __half* __restrict__ Chi, __half* __restrict__ Clo,
    int rowsPerB, int K, int ldc)
{
    extern __shared__ char dsm[];
    const uint32_t sbase = smem_u32(dsm);
    const int tid = threadIdx.x, lane = tid & 31, warp = tid >> 5;
    const int m0 = blockIdx.y * 128, n0 = blockIdx.x * 128;
    const int wm = (warp & 1) * 64, wn = (warp >> 1) * 32;
    const int NC = K >> 6;

    float acc[4][4][4] = {};
    g_load_stage(A, Bh, Bl, sbase,            m0, n0, K, 0, tid);
    g_load_stage(A, Bh, Bl, sbase + GSTAGE,   m0, n0, K, 1, tid);
    g_load_stage(A, Bh, Bl, sbase + 2*GSTAGE, m0, n0, K, 2, tid);
    asm volatile("cp.async.wait_group 2;" ::: "memory");
    __syncthreads();

    const int arow = wm + (lane & 15), akb = lane & 16;
    const int brow = wn + ((lane & 16) >> 1) + (lane & 7), bkb = (lane & 8) << 1;

    int buf = 0;
    for (int kc = 0; kc < NC; kc++) {
        const uint32_t st = sbase + buf * GSTAGE;
#pragma unroll
        for (int ks = 0; ks < 4; ks++) {
            const int kb = ks*32;
            uint32_t ah[4][4], bh[2][4], bl[2][4];
#pragma unroll
            for (int im = 0; im < 4; im++) {
                int row = arow + im*16;
                uint32_t off = (uint32_t)(row*128 + kb + akb) ^ ((row & 7) << 4);
                ldsm4(ah[im], st + off);
            }
#pragma unroll
            for (int np = 0; np < 2; np++) {
                int row = brow + np*16;
                uint32_t off = (uint32_t)(row*128 + kb + bkb) ^ ((row & 7) << 4);
                ldsm4(bh[np], st + 16384 + off);
                ldsm4(bl[np], st + 32768 + off);
            }
#pragma unroll
            for (int im = 0; im < 4; im++)
#pragma unroll
                for (int in = 0; in < 4; in++) {
                    const int np = in >> 1, hf = (in & 1) * 2;
                    mma16816(acc[im][in], ah[im], bh[np][hf], bh[np][hf+1]);
                    mma16816(acc[im][in], ah[im], bl[np][hf], bl[np][hf+1]);
                }
        }
        __syncthreads();
        if (kc + 3 < NC) {
            g_load_stage(A, Bh, Bl, sbase + buf*GSTAGE, m0, n0, K, kc + 3, tid);
            asm volatile("cp.async.wait_group 2;" ::: "memory");
        } else if (kc + 2 < NC) {
            asm volatile("cp.async.wait_group 1;" ::: "memory");
        } else {
            asm volatile("cp.async.wait_group 0;" ::: "memory");
        }
        __syncthreads();
        buf++; if (buf == 3) buf = 0;
    }

    const int rbase = m0 + wm + (lane >> 2);
    const int cbase = n0 + wn + 2*(lane & 3);
#pragma unroll
    for (int im = 0; im < 4; im++) {
#pragma unroll
        for (int in = 0; in < 4; in++) {
            int col = cbase + in*8;
            float v0 = acc[im][in][0], v1 = acc[im][in][1];
            float v2 = acc[im][in][2], v3 = acc[im][in][3];
            if (EPI >= 1) {
                float b0 = bias[col], b1 = bias[col+1];
                v0 += b0; v1 += b1; v2 += b0; v3 += b1;
            }
            if (EPI == 2) {
                v0 = 0.5f*v0*(1.0f + erff(v0*0.7071067811865476f));
                v1 = 0.5f*v1*(1.0f + erff(v1*0.7071067811865476f));
                v2 = 0.5f*v2*(1.0f + erff(v2*0.7071067811865476f));
                v3 = 0.5f*v3*(1.0f + erff(v3*0.7071067811865476f));
            }
            int r0 = rbase + im*16, r1 = r0 + 8;
            if (OUT != 1) {
                *(float2*)(C + (size_t)r0*ldc + col) = make_float2(v0, v1);
                *(float2*)(C + (size_t)r1*ldc + col) = make_float2(v2, v3);
            }
            if (OUT == 1) {
                *(__half2*)(Chi + (size_t)r0*ldc + col) =
                    __halves2half2(__float2half_rn(v0), __float2half_rn(v1));
                *(__half2*)(Chi + (size_t)r1*ldc + col) =
                    __halves2half2(__float2half_rn(v2), __float2half_rn(v3));
            }
            if (OUT == 2) {
                __half h0,h1,h2,h3,l0,l1,l2,l3;
                hsplit(v0,h0,l0); hsplit(v1,h1,l1); hsplit(v2,h2,l2); hsplit(v3,h3,l3);
                int nh = col >> 6, d = col & 63;
                size_t d0 = (((size_t)(r0 & 1)*NH + nh)*rowsPerB + (r0 >> 1))*DH + d;
                size_t d1 = (((size_t)(r1 & 1)*NH + nh)*rowsPerB + (r1 >> 1))*DH + d;
                *(__half2*)(Chi + d0) = __halves2half2(h0, h1);
                *(__half2*)(Chi + d1) = __halves2half2(h2, h3);
                *(__half2*)(Clo + d0) = __halves2half2(l0, l1);
                *(__half2*)(Clo + d1) = __halves2half2(l2, l3);
            }
        }
    }
}

template<int EPI, int OUT>
__global__ void __launch_bounds__(256, 1) gemm_mma(
    const __half* __restrict__ A, const __half* __restrict__ Bh, const __half* __restrict__ Bl,
    const float* __restrict__ bias, float* __restrict__ C,
    __half* __restrict__ Chi, __half* __restrict__ Clo,
    size_t zsA, size_t zsC, int rowsPerB, int K, int ldc)
{
    const size_t zo = blockIdx.z;
    gemm_core<EPI, OUT>(A + zo*zsA, Bh, Bl, bias,
                        (OUT != 1) ? C + zo*zsC : C,
                        (OUT >= 1) ? Chi + zo*zsC : Chi, Clo,
                        rowsPerB, K, ldc);
}

// merged k/v/q projections from h
__global__ void __launch_bounds__(256, 1) projHKV()
{
    switch (blockIdx.z) {
    case 0: gemm_core<0,2>(g_hb, g_wkT, g_wkT + (size_t)DM*DM,
                           nullptr, g_k, g_khh, g_khl, QL, DM, DM); break;
    case 1: gemm_core<0,0>(g_hb, g_wvT, g_wvT + (size_t)DM*DM,
                           nullptr, g_v, nullptr, nullptr, QL, DM, DM); break;
    default: gemm_core<0,2>(g_hb, g_wqT, g_wqT + (size_t)DM*DM,
                            nullptr, g_q, g_q1h, g_q1l, QL, DM, DM); break;
    }
}

// ---------------- batched score GEMM (fp16 3-pass), causal-pruned ----------------
#define SC_SMEM 65536

__global__ void __launch_bounds__(256, 1) score_mma(
    const __half* __restrict__ Q1h, const __half* __restrict__ Q1l,
    const __half* __restrict__ Q2h, const __half* __restrict__ Q2l,
    const __half* __restrict__ Kh, const __half* __restrict__ Kl,
    const float* __restrict__ biasT, float* __restrict__ C,
    size_t zsC, int Ncols, int window)
{
    extern __shared__ char dsm[];
    const uint32_t st = smem_u32(dsm);
    const int tid = threadIdx.x, lane = tid & 31, warp = tid >> 5;
    const int zz = blockIdx.z, s = zz >> 5, bn = zz & 31;
    const __half* Qh = s ? Q2h : Q1h;
    const __half* Ql = s ? Q2l : Q1l;
    C += (size_t)s * zsC;

    int i0, j0;
    if (!window) {
        int t = blockIdx.x;
        int it = (int)((sqrtf(8.f*t + 1.f) - 1.f) * 0.5f);
        if ((it + 1)*(it + 2)/2 <= t) it++;
        else if (it*(it + 1)/2 > t) it--;
        int jt = t - it*(it + 1)/2;
        i0 = it * 128; j0 = jt * 128;
    } else {
        int it = blockIdx.y;
        int bx = blockIdx.x;
        if (bx > it + 1) return;
        i0 = it * 128;
        j0 = (7 - it + bx) * 128;
    }

    const size_t qb = ((size_t)bn*QL + i0)*DH;
    const size_t kb = ((size_t)bn*Ncols + j0)*DH;
#pragma unroll
    for (int p = 0; p < 4; p++) {
        int c = p*256 + tid;
        int row = c >> 3, kcol = c & 7;
        uint32_t sw = (uint32_t)(row*128 + kcol*16) ^ ((row & 7) << 4);
        cp16(st + sw,         Qh + qb + (size_t)row*DH + kcol*8);
        cp16(st + 16384 + sw, Ql + qb + (size_t)row*DH + kcol*8);
        cp16(st + 32768 + sw, Kh + kb + (size_t)row*DH + kcol*8);
        cp16(st + 49152 + sw, Kl + kb + (size_t)row*DH + kcol*8);
    }
    cp_commit();
    asm volatile("cp.async.wait_group 0;" ::: "memory");
    __syncthreads();

    const int wm = (warp & 1) * 64, wn = (warp >> 1) * 32;
    const int arow = wm + (lane & 15), akb = lane & 16;
    const int brow = wn + ((lane & 16) >> 1) + (lane & 7), bkb = (lane & 8) << 1;

    float acc[4][4][4] = {};
#pragma unroll
    for (int ks = 0; ks < 4; ks++) {
        const int kbyte = ks*32;
        uint32_t ah[4][4], al[4][4], bh[2][4], bl[2][4];
#pragma unroll
        for (int im = 0; im < 4; im++) {
            int row = arow + im*16;
            uint32_t off = (uint32_t)(row*128 + kbyte + akb) ^ ((row & 7) << 4);
            ldsm4(ah[im], st + off);
            ldsm4(al[im], st + 16384 + off);
        }
#pragma unroll
        for (int np = 0; np < 2; np++) {
            int row = brow + np*16;
            uint32_t off = (uint32_t)(row*128 + kbyte + bkb) ^ ((row & 7) << 4);
            ldsm4(bh[np], st + 32768 + off);
            ldsm4(bl[np], st + 49152 + off);
        }
#pragma unroll
        for (int im = 0; im < 4; im++)
#pragma unroll
            for (int in = 0; in < 4; in++) {
                const int np = in >> 1, hf = (in & 1) * 2;
                mma16816(acc[im][in], ah[im], bh[np][hf], bh[np][hf+1]);
                mma16816(acc[im][in], ah[im], bl[np][hf], bl[np][hf+1]);
                mma16816(acc[im][in], al[im], bh[np][hf], bh[np][hf+1]);
            }
    }

    float* Cb = C + (size_t)bn*QL*Ncols;
    const float* bt = biasT + (size_t)bn*Ncols;
    const int rbase = i0 + wm + (lane >> 2);
    const int cbase = j0 + wn + 2*(lane & 3);
#pragma unroll
    for (int im = 0; im < 4; im++)
#pragma unroll
        for (int in = 0; in < 4; in++) {
            int col = cbase + in*8;
            float b0 = bt[col], b1 = bt[col+1];
            int r0 = rbase + im*16, r1 = r0 + 8;
            *(float2*)(Cb + (size_t)r0*Ncols + col) =
                make_float2(acc[im][in][0] + b0, acc[im][in][1] + b1);
            *(float2*)(Cb + (size_t)r1*Ncols + col) =
                make_float2(acc[im][in][2] + b0, acc[im][in][3] + b1);
        }
}

// ---------------- fused combine + softmax (causal-bounded) + fp16-split P ----------------
__global__ void __launch_bounds__(256) softmax_fused(
    const float* __restrict__ S, const float* __restrict__ BD,
    const __half* __restrict__ diff, const float* __restrict__ ef,
    __half* __restrict__ Ph, __half* __restrict__ Pl)
{
    __shared__ float red[8];
    const int i = blockIdx.x;
    const int zz = blockIdx.y, s = zz >> 5, bn = zz & 31, b = bn >> 4, n = bn & 15;
    const int jmax = ((i >> 7) + 1) << 7;
    const float* Sr = S    + (size_t)s*SSTR + ((size_t)bn << 20) + ((size_t)i << 10);
    const float* Br = BD   + (size_t)s*BSTR + ((size_t)bn << 21) + ((size_t)i << 11) + (QL - i);
    const __half* Dr = diff + ((size_t)b << 20) + ((size_t)i << 10);
    const float* efs = ef + (size_t)s*M2*NH*2;
    const float e0 = efs[(((size_t)i*2 + b)*NH + n)*2];
    const float de = efs[(((size_t)i*2 + b)*NH + n)*2 + 1] - e0;
    const int t = threadIdx.x, lane = t & 31, w = t >> 5;

    float v[4];
#pragma unroll
    for (int p = 0; p < 4; p++) {
        int j = t + p*256;
        if (j < jmax) {
            float sc = (Sr[j] + Br[j] + e0 + de*__half2float(Dr[j])) * ATT_SCALE;
            bool blocked = s ? (j >= i) : (j > i);
            v[p] = blocked ? sc - 1e30f : sc;
        } else v[p] = -1e30f;
    }
    float m = fmaxf(fmaxf(v[0], v[1]), fmaxf(v[2], v[3]));
#pragma unroll
    for (int o = 16; o; o >>= 1) m = fmaxf(m, __shfl_xor_sync(0xffffffffu, m, o));
    if (!lane) red[w] = m;
    __syncthreads();
    m = red[lane & 7];
#pragma unroll
    for (int o = 4; o; o >>= 1) m = fmaxf(m, __shfl_xor_sync(0xffffffffu, m, o));
    float sum = 0.f;
#pragma unroll
    for (int p = 0; p < 4; p++) { v[p] = expf(v[p] - m); sum += v[p]; }
#pragma unroll
    for (int o = 16; o; o >>= 1) sum += __shfl_xor_sync(0xffffffffu, sum, o);
    __syncthreads();
    if (!lane) red[w] = sum;
    __syncthreads();
    sum = red[lane & 7];
#pragma unroll
    for (int o = 4; o; o >>= 1) sum += __shfl_xor_sync(0xffffffffu, sum, o);
    const float inv = 1.0f / sum;
    const size_t base = (size_t)s*SSTR + ((size_t)bn << 20) + ((size_t)i << 10);
#pragma unroll
    for (int p = 0; p < 4; p++) {
        int j = t + p*256;
        if (j < jmax) {
            __half ph, pl;
            hsplit(v[p] * inv, ph, pl);
            Ph[base + j] = ph;
            Pl[base + j] = pl;
        }
    }
}

// ---------------- batched PV GEMM (fp16 3-pass, causal K bound) -> fp16 attn ----------------
#define PV_STAGE 49152
#define PV_SMEM (2*PV_STAGE)

__device__ __forceinline__ void pv_load(
    const __half* __restrict__ Ph, const __half* __restrict__ Pl,
    const __half* __restrict__ Vh, const __half* __restrict__ Vl,
    uint32_t st, size_t pbase, size_t vbase, int kc, int tid)
{
    const size_t ko = (size_t)kc * 64;
#pragma unroll
    for (int p = 0; p < 4; p++) {
        int c = p*256 + tid;
        int row = c >> 3, kcol = c & 7;
        uint32_t sw = (uint32_t)(row*128 + kcol*16) ^ ((row & 7) << 4);
        cp16(st + sw,         Ph + pbase + (size_t)row*QL + ko + kcol*8);
        cp16(st + 16384 + sw, Pl + pbase + (size_t)row*QL + ko + kcol*8);
    }
#pragma unroll
    for (int p = 0; p < 2; p++) {
        int c = p*256 + tid;
        int row = c >> 3, kcol = c & 7;
        uint32_t sw = (uint32_t)(row*128 + kcol*16) ^ ((row & 7) << 4);
        cp16(st + 32768 + sw, Vh + vbase + (size_t)row*QL + ko + kcol*8);
        cp16(st + 40960 + sw, Vl + vbase + (size_t)row*QL + ko + kcol*8);
    }
    cp_commit();
}

__global__ void __launch_bounds__(256, 1) pv_mma(
    const __half* __restrict__ Ph, const __half* __restrict__ Pl,
    const __half* __restrict__ Vh, const __half* __restrict__ Vl,
    __half* __restrict__ O)
{
    extern __shared__ char dsm[];
    const uint32_t sbase = smem_u32(dsm);
    const int tid = threadIdx.x, lane = tid & 31, warp = tid >> 5;
    const int zz = blockIdx.y, s = zz >> 5, bn = zz & 31, b = bn >> 4, n = bn & 15;
    const int it = blockIdx.x;
    const int i0 = it * 128;
    const int NC = 2*it + 2;
    const size_t pbase = (size_t)s*SSTR + ((size_t)bn << 20) + (size_t)i0*QL;
    const size_t vbase = (size_t)bn * DH * QL;
    const size_t obase = (size_t)s * M2 * DM;

    float acc[2][4][4] = {};
    pv_load(Ph, Pl, Vh, Vl, sbase,            pbase, vbase, 0, tid);
    pv_load(Ph, Pl, Vh, Vl, sbase + PV_STAGE, pbase, vbase, 1, tid);
    asm volatile("cp.async.wait_group 1;" ::: "memory");
    __syncthreads();

    const int wm = (warp & 3) * 32, wn = (warp >> 2) * 32;
    const int arow = wm + (lane & 15), akb = lane & 16;
    const int brow = wn + ((lane & 16) >> 1) + (lane & 7), bkb = (lane & 8) << 1;

    for (int kc = 0; kc < NC; kc++) {
        const uint32_t st = sbase + (kc & 1) * PV_STAGE;
#pragma unroll
        for (int ks = 0; ks < 4; ks++) {
            const int kb = ks*32;
            uint32_t ah[2][4], al[2][4], bh[2][4], bl[2][4];
#pragma unroll
            for (int im = 0; im < 2; im++) {
                int row = arow + im*16;
                uint32_t off = (uint32_t)(row*128 + kb + akb) ^ ((row & 7) << 4);
                ldsm4(ah[im], st + off);
                ldsm4(al[im], st + 16384 + off);
            }
#pragma unroll
            for (int np = 0; np < 2; np++) {
                int row = brow + np*16;
                uint32_t off = (uint32_t)(row*128 + kb + bkb) ^ ((row & 7) << 4);
                ldsm4(bh[np], st + 32768 + off);
                ldsm4(bl[np], st + 40960 + off);
            }
#pragma unroll
            for (int im = 0; im < 2; im++)
#pragma unroll
                for (int in = 0; in < 4; in++) {
                    const int np = in >> 1, hf = (in & 1) * 2;
                    mma16816(acc[im][in], ah[im], bh[np][hf], bh[np][hf+1]);
                    mma16816(acc[im][in], ah[im], bl[np][hf], bl[np][hf+1]);
                    mma16816(acc[im][in], al[im], bh[np][hf], bh[np][hf+1]);
                }
        }
        __syncthreads();
        if (kc + 2 < NC) {
            pv_load(Ph, Pl, Vh, Vl, sbase + (kc & 1)*PV_STAGE, pbase, vbase, kc + 2, tid);
            asm volatile("cp.async.wait_group 1;" ::: "memory");
        } else {
            asm volatile("cp.async.wait_group 0;" ::: "memory");
        }
        __syncthreads();
    }

    const int rl = wm + (lane >> 2);
    const int cb = wn + 2*(lane & 3);
#pragma unroll
    for (int im = 0; im < 2; im++)
#pragma unroll
        for (int in = 0; in < 4; in++) {
            int col = cb + in*8;
            int r0 = i0 + rl + im*16, r1 = r0 + 8;
            *(__half2*)(O + obase + ((size_t)r0*2 + b)*DM + n*DH + col) =
                __halves2half2(__float2half_rn(acc[im][in][0]), __float2half_rn(acc[im][in][1]));
            *(__half2*)(O + obase + ((size_t)r1*2 + b)*DM + n*DH + col) =
                __halves2half2(__float2half_rn(acc[im][in][2]), __float2half_rn(acc[im][in][3]));
        }
}

// ---------------- residual + LayerNorm (merged streams) ----------------
template<int WB16>
__global__ void __launch_bounds__(256) add_ln(
    const float* __restrict__ a, const float* __restrict__ x0, const float* __restrict__ x1,
    const float* __restrict__ gamma, const float* __restrict__ beta,
    float* __restrict__ out, __half* __restrict__ oh)
{
    __shared__ float buf[1024];
    __shared__ float red[8];
    __shared__ float s_stat;
    const size_t base = (size_t)blockIdx.x << 10;
    const int str = blockIdx.x >> 11;
    const size_t lbase = (size_t)(blockIdx.x & 2047) << 10;
    const float* x = str ? x1 : x0;
    const int t = threadIdx.x, lane = t & 31, w = t >> 5;
    float sum = 0.f;
#pragma unroll
    for (int p = 0; p < 4; p++) {
        float v = a[base + t + p*256] + x[lbase + t + p*256];
        buf[t + p*256] = v; sum += v;
    }
#pragma unroll
    for (int o = 16; o; o >>= 1) sum += __shfl_xor_sync(0xffffffffu, sum, o);
    if (!lane) red[w] = sum;
    __syncthreads();
    if (t == 0) { float s = 0; for (int i = 0; i < 8; i++) s += red[i]; s_stat = s * (1.0f/1024.0f); }
    __syncthreads();
    const float mean = s_stat;
    float vs = 0.f;
#pragma unroll
    for (int p = 0; p < 4; p++) { float d = buf[t + p*256] - mean; vs += d*d; }
#pragma unroll
    for (int o = 16; o; o >>= 1) vs += __shfl_xor_sync(0xffffffffu, vs, o);
    __syncthreads();
    if (!lane) red[w] = vs;
    __syncthreads();
    if (t == 0) { float s = 0; for (int i = 0; i < 8; i++) s += red[i]; s_stat = s * (1.0f/1024.0f); }
    __syncthreads();
    const float r = rsqrtf(s_stat + 1e-12f);
#pragma unroll
    for (int p = 0; p < 4; p++) {
        int c = t + p*256;
        float val = (buf[c] - mean) * r * gamma[c] + beta[c];
        out[base + c] = val;
        if (WB16) oh[base + c] = __float2half_rn(val);
    }
}

// ---------------- host ----------------
extern "C" void kernel_launch(void* const* d_in, const int* in_sizes, int n_in,
                              void* d_out, int out_size)
{
    (void)in_sizes; (void)n_in; (void)out_size;
    const float* h       = (const float*)d_in[0];
    const float* g       = (const float*)d_in[1];
    const float* r       = (const float*)d_in[2];
    const float* seg_mat = (const float*)d_in[5];
    const float* wq      = (const float*)d_in[6];
    const float* wk      = (const float*)d_in[7];
    const float* wv      = (const float*)d_in[8];
    const float* wo      = (const float*)d_in[9];
    const float* wr      = (const float*)d_in[10];
    const float* rwb     = (const float*)d_in[11];
    const float* rrb     = (const float*)d_in[12];
    const float* rsb     = (const float*)d_in[13];
    const float* se      = (const float*)d_in[14];
    const float* lnga    = (const float*)d_in[15];
    const float* lnba    = (const float*)d_in[16];
    const float* w1      = (const float*)d_in[17];
    const float* b1      = (const float*)d_in[18];
    const float* w2      = (const float*)d_in[19];
    const float* b2      = (const float*)d_in[20];
    const float* lngf    = (const float*)d_in[21];
    const float* lnbf    = (const float*)d_in[22];

    cudaFuncSetAttribute(projHKV,       cudaFuncAttributeMaxDynamicSharedMemorySize, GSMEM_BYTES);
    cudaFuncSetAttribute(gemm_mma<0,0>, cudaFuncAttributeMaxDynamicSharedMemorySize, GSMEM_BYTES);
    cudaFuncSetAttribute(gemm_mma<0,2>, cudaFuncAttributeMaxDynamicSharedMemorySize, GSMEM_BYTES);
    cudaFuncSetAttribute(gemm_mma<2,1>, cudaFuncAttributeMaxDynamicSharedMemorySize, GSMEM_BYTES);
    cudaFuncSetAttribute(gemm_mma<1,0>, cudaFuncAttributeMaxDynamicSharedMemorySize, GSMEM_BYTES);
    cudaFuncSetAttribute(score_mma,     cudaFuncAttributeMaxDynamicSharedMemorySize, SC_SMEM);
    cudaFuncSetAttribute(pv_mma,        cudaFuncAttributeMaxDynamicSharedMemorySize, PV_SMEM);

    float *q2f,*k,*v,*kr,*ef,*o,*y,*z,*bkT,*bkrT,*S,*BD;
    __half *hb,*rb,*gb,*wqT,*wkT,*wvT,*wrT,*woC,*w1T,*w2T,*diffb;
    __half *q1h,*q1l,*q2h,*q2l,*khh,*khl,*krh,*krl,*vth,*vtl,*Ph,*Pl,*at,*yh,*th;
    cudaGetSymbolAddress((void**)&q2f,  g_q2);
    cudaGetSymbolAddress((void**)&k,    g_k);
    cudaGetSymbolAddress((void**)&v,    g_v);
    cudaGetSymbolAddress((void**)&kr,   g_kr);
    cudaGetSymbolAddress((void**)&ef,   g_ef);
    cudaGetSymbolAddress((void**)&o,    g_o);
    cudaGetSymbolAddress((void**)&y,    g_y);
    cudaGetSymbolAddress((void**)&z,    g_z);
    cudaGetSymbolAddress((void**)&bkT,  g_bkT);
    cudaGetSymbolAddress((void**)&bkrT, g_bkrT);
    cudaGetSymbolAddress((void**)&S,    g_S);
    cudaGetSymbolAddress((void**)&BD,   g_BD);
    cudaGetSymbolAddress((void**)&diffb,g_diffb);
    cudaGetSymbolAddress((void**)&hb,   g_hb);
    cudaGetSymbolAddress((void**)&rb,   g_rb);
    cudaGetSymbolAddress((void**)&gb,   g_gb);
    cudaGetSymbolAddress((void**)&wqT,  g_wqT);
    cudaGetSymbolAddress((void**)&wkT,  g_wkT);
    cudaGetSymbolAddress((void**)&wvT,  g_wvT);
    cudaGetSymbolAddress((void**)&wrT,  g_wrT);
    cudaGetSymbolAddress((void**)&woC,  g_woC);
    cudaGetSymbolAddress((void**)&w1T,  g_w1T);
    cudaGetSymbolAddress((void**)&w2T,  g_w2T);
    cudaGetSymbolAddress((void**)&q1h,  g_q1h);
    cudaGetSymbolAddress((void**)&q1l,  g_q1l);
    cudaGetSymbolAddress((void**)&q2h,  g_q2h);
    cudaGetSymbolAddress((void**)&q2l,  g_q2l);
    cudaGetSymbolAddress((void**)&khh,  g_khh);
    cudaGetSymbolAddress((void**)&khl,  g_khl);
    cudaGetSymbolAddress((void**)&krh,  g_krh);
    cudaGetSymbolAddress((void**)&krl,  g_krl);
    cudaGetSymbolAddress((void**)&vth,  g_vth);
    cudaGetSymbolAddress((void**)&vtl,  g_vtl);
    cudaGetSymbolAddress((void**)&Ph,   g_Ph);
    cudaGetSymbolAddress((void**)&Pl,   g_Pl);
    cudaGetSymbolAddress((void**)&at,   g_at);
    cudaGetSymbolAddress((void**)&yh,   g_yh);
    cudaGetSymbolAddress((void**)&th,   g_th);

    dim3 tb(32, 8);
    convT_split<<<dim3(DM/32, DM/32), tb>>>(wk, wkT, wkT + (size_t)DM*DM, DM, DM);
    convT_split<<<dim3(DM/32, DM/32), tb>>>(wv, wvT, wvT + (size_t)DM*DM, DM, DM);
    convT_split<<<dim3(DM/32, DM/32), tb>>>(wq, wqT, wqT + (size_t)DM*DM, DM, DM);
    conv_half<<<(M2*DM/4 + 255)/256, 256>>>(h, hb, M2*DM/4);
    projHKV<<<dim3(8, 16, 3), 256, GSMEM_BYTES>>>();

    convT_split<<<dim3(DM/32, DM/32), tb>>>(wr, wrT, wrT + (size_t)DM*DM, DM, DM);
    conv_half<<<(MR*DM/4 + 255)/256, 256>>>(r, rb, MR*DM/4);
    conv_half<<<(M2*DM/4 + 255)/256, 256>>>(g, gb, M2*DM/4);
    conv_split<<<(DM*DM/4 + 255)/256, 256>>>(wo, woC, woC + (size_t)DM*DM, DM*DM/4);
    convT_split<<<dim3(DI/32, DM/32), tb>>>(w1, w1T, w1T + (size_t)DM*DI, DM, DI);
    convT_split<<<dim3(DM/32, DI/32), tb>>>(w2, w2T, w2T + (size_t)DI*DM, DI, DM);
    prep_diff<<<(2*QL*QL + 255)/256, 256>>>(seg_mat, diffb);

    gemm_mma<0,2><<<dim3(8,32,1), 256, GSMEM_BYTES>>>(rb, wrT, wrT+(size_t)DM*DM,
        nullptr, kr, krh, krl, 0, 0, RL, DM, DM);
    gemm_mma<0,2><<<dim3(8,16,1), 256, GSMEM_BYTES>>>(gb, wqT, wqT+(size_t)DM*DM,
        nullptr, q2f, q2h, q2l, 0, 0, QL, DM, DM);
    repack_vT<<<dim3(QL/32, DH/32, 32), tb>>>(v, vth, vtl);

    bias_dotT<<<(M2*NH*32 + 255)/256, 256>>>(k,  rwb, bkT,  QL);
    bias_dotT<<<(MR*NH*32 + 255)/256, 256>>>(kr, rrb, bkrT, RL);
    ef_kernel<<<dim3((M2*NH*32 + 255)/256, 2), 256>>>(rsb, se);

    // attention (both streams merged; causal-pruned)
    score_mma<<<dim3(36, 1, 64), 256, SC_SMEM>>>(q1h, q1l, q2h, q2l, khh, khl, bkT,  S,  SSTR, QL, 0);
    score_mma<<<dim3(9, 8, 64), 256, SC_SMEM>>>(q1h, q1l, q2h, q2l, krh, krl, bkrT, BD, BSTR, RL, 1);
    softmax_fused<<<dim3(QL, 64), 256>>>(S, BD, diffb, ef, Ph, Pl);
    pv_mma<<<dim3(8, 64), 256, PV_SMEM>>>(Ph, Pl, vth, vtl, at);
    vmean_fix<<<32, 64>>>(v, at);

    // back half (both streams merged via z)
    gemm_mma<0,0><<<dim3(8,16,2), 256, GSMEM_BYTES>>>(at, woC, woC+(size_t)DM*DM,
        nullptr, o, nullptr, nullptr, (size_t)M2*DM, (size_t)M2*DM, QL, DM, DM);
    add_ln<1><<<2*M2, 256>>>(o, h, g, lnga, lnba, y, yh);
    gemm_mma<2,1><<<dim3(32,16,2), 256, GSMEM_BYTES>>>(yh, w1T, w1T+(size_t)DM*DI,
        b1, nullptr, th, nullptr, (size_t)M2*DM, (size_t)M2*DI, QL, DM, DI);
    gemm_mma<1,0><<<dim3(8,16,2), 256, GSMEM_BYTES>>>(th, w2T, w2T+(size_t)DI*DM,
        b2, z, nullptr, nullptr, (size_t)M2*DI, (size_t)M2*DM, QL, DI, DM);
    add_ln<0><<<2*M2, 256>>>(z, y, y + (size_t)M2*DM, lngf, lnbf, (float*)d_out, nullptr);
}

// round 11
// speedup vs baseline: 1.8959x; 1.1019x over previous
#include <cuda_runtime.h>
#include <cuda_fp16.h>
#include <math.h>
#include <stdint.h>

#define QL 1024
#define NH 16
#define DH 64
#define DM 1024
#define DI 4096
#define RL 2048
#define M2 (QL*2)
#define MR (RL*2)
#define ATT_SCALE 0.125f
#define SSTR ((size_t)32*QL*QL)
#define BSTR ((size_t)32*QL*RL)

__device__ __forceinline__ uint32_t smem_u32(const void* p) {
    uint32_t a;
    asm("{ .reg .u64 t; cvta.to.shared.u64 t, %1; cvt.u32.u64 %0, t; }" : "=r"(a) : "l"(p));
    return a;
}
__device__ __forceinline__ void cp16(uint32_t dst, const void* src) {
    asm volatile("cp.async.cg.shared.global [%0], [%1], 16;" :: "r"(dst), "l"(src));
}
__device__ __forceinline__ void cp_commit() { asm volatile("cp.async.commit_group;" ::: "memory"); }
__device__ __forceinline__ void ldsm4(uint32_t (&r)[4], uint32_t addr) {
    asm volatile("ldmatrix.sync.aligned.m8n8.x4.shared.b16 {%0,%1,%2,%3}, [%4];"
        : "=r"(r[0]), "=r"(r[1]), "=r"(r[2]), "=r"(r[3]) : "r"(addr));
}
__device__ __forceinline__ void mma16816(float (&d)[4], const uint32_t (&a)[4],
                                         uint32_t b0, uint32_t b1) {
    asm volatile("mma.sync.aligned.m16n8k16.row.col.f32.f16.f16.f32 "
        "{%0,%1,%2,%3},{%4,%5,%6,%7},{%8,%9},{%0,%1,%2,%3};"
        : "+f"(d[0]), "+f"(d[1]), "+f"(d[2]), "+f"(d[3])
        : "r"(a[0]), "r"(a[1]), "r"(a[2]), "r"(a[3]), "r"(b0), "r"(b1));
}
__device__ __forceinline__ void hsplit(float v, __half& h, __half& l) {
    h = __float2half_rn(v);
    l = __float2half_rn(v - __half2float(h));
}

// ---------------- scratch ----------------
__device__ float g_q [M2*DM];
__device__ float g_q2[M2*DM];
__device__ float g_k [M2*DM];
__device__ float g_v [M2*DM];
__device__ float g_kr[MR*DM];
__device__ float g_ef[2*M2*NH*2];
__device__ float g_o [2*M2*DM];
__device__ float g_y [2*M2*DM];
__device__ float g_z [2*M2*DM];
__device__ float g_bkT [32*QL];
__device__ float g_bkrT[32*RL];
__device__ float g_S [2*SSTR];
__device__ float g_BD[2*BSTR];
__device__ __align__(256) __half g_diffb[(size_t)2*QL*QL];
__device__ __align__(256) __half g_hb[M2*DM], g_rb[MR*DM], g_gb[M2*DM];
__device__ __align__(256) __half g_wqT[2*DM*DM], g_wkT[2*DM*DM], g_wvT[2*DM*DM];
__device__ __align__(256) __half g_wrT[2*DM*DM], g_woC[2*DM*DM];
__device__ __align__(256) __half g_w1T[2*DM*DI], g_w2T[2*DI*DM];
__device__ __align__(256) __half g_q1h[32*QL*DH];            // Q single
__device__ __align__(256) __half g_q2h[32*QL*DH];
__device__ __align__(256) __half g_khh[32*QL*DH], g_khl[32*QL*DH];
__device__ __align__(256) __half g_krh[32*RL*DH], g_krl[32*RL*DH];
__device__ __align__(256) __half g_vth[32*DH*QL], g_vtl[32*DH*QL];
__device__ __align__(256) __half g_Ph [2*SSTR];              // P single
__device__ __align__(256) __half g_at [2*M2*DM];
__device__ __align__(256) __half g_yh [2*M2*DM];
__device__ __align__(256) __half g_th [2*M2*DI];

// ---------------- small kernels ----------------
__global__ void conv_half(const float* __restrict__ X, __half* __restrict__ out, int n4)
{
    int i = blockIdx.x * blockDim.x + threadIdx.x;
    if (i >= n4) return;
    float4 v = ((const float4*)X)[i];
    ((__half2*)out)[2*i]   = __halves2half2(__float2half_rn(v.x), __float2half_rn(v.y));
    ((__half2*)out)[2*i+1] = __halves2half2(__float2half_rn(v.z), __float2half_rn(v.w));
}

__global__ void conv_split(const float* __restrict__ X, __half* __restrict__ hi,
                           __half* __restrict__ lo, int n4)
{
    int i = blockIdx.x * blockDim.x + threadIdx.x;
    if (i >= n4) return;
    float4 v = ((const float4*)X)[i];
    __half h0,h1,h2,h3,l0,l1,l2,l3;
    hsplit(v.x,h0,l0); hsplit(v.y,h1,l1); hsplit(v.z,h2,l2); hsplit(v.w,h3,l3);
    ((__half2*)hi)[2*i]   = __halves2half2(h0,h1);
    ((__half2*)hi)[2*i+1] = __halves2half2(h2,h3);
    ((__half2*)lo)[2*i]   = __halves2half2(l0,l1);
    ((__half2*)lo)[2*i+1] = __halves2half2(l2,l3);
}

__global__ void convT_split(const float* __restrict__ W, __half* __restrict__ hi,
                            __half* __restrict__ lo, int K, int N)
{
    __shared__ float t[32][33];
    int k0 = blockIdx.y * 32, n0 = blockIdx.x * 32;
    int tx = threadIdx.x, ty = threadIdx.y;
#pragma unroll
    for (int p = 0; p < 4; p++)
        t[ty + p*8][tx] = W[(size_t)(k0 + ty + p*8)*N + n0 + tx];
    __syncthreads();
#pragma unroll
    for (int p = 0; p < 4; p++) {
        __half h, l;
        hsplit(t[tx][ty + p*8], h, l);
        size_t o = (size_t)(n0 + ty + p*8)*K + k0 + tx;
        hi[o] = h; lo[o] = l;
    }
}

__global__ void repack_vT(const float* __restrict__ V, __half* __restrict__ hi,
                          __half* __restrict__ lo)
{
    __shared__ float tile[32][33];
    int j0 = blockIdx.x * 32, d0 = blockIdx.y * 32;
    int bn = blockIdx.z, b = bn >> 4, n = bn & 15;
    int tx = threadIdx.x, ty = threadIdx.y;
#pragma unroll
    for (int p = 0; p < 4; p++)
        tile[ty + p*8][tx] = V[((size_t)(j0 + ty + p*8)*2 + b)*DM + n*DH + d0 + tx];
    __syncthreads();
#pragma unroll
    for (int p = 0; p < 4; p++) {
        __half h, l;
        hsplit(tile[tx][ty + p*8], h, l);
        size_t o = ((size_t)bn*DH + d0 + ty + p*8)*QL + j0 + tx;
        hi[o] = h; lo[o] = l;
    }
}

__global__ void prep_diff(const float* __restrict__ seg_mat, __half* __restrict__ diff)
{
    size_t idx = (size_t)blockIdx.x * blockDim.x + threadIdx.x;
    if (idx >= (size_t)2*QL*QL) return;
    int j = idx & 1023, i = (idx >> 10) & 1023, b = (int)(idx >> 20);
    diff[idx] = __float2half_rn(seg_mat[(((size_t)i*QL + j)*2 + b)*2 + 1]);
}

__global__ void bias_dotT(const float* __restrict__ X, const float* __restrict__ bias,
                          float* __restrict__ outT, int rowsPerB)
{
    const int gw = (blockIdx.x * blockDim.x + threadIdx.x) >> 5;
    const int lane = threadIdx.x & 31;
    if (gw >= rowsPerB * 2 * NH) return;
    const int row = gw >> 4, n = gw & 15;
    const int j = row >> 1, b = row & 1;
    float s = bias[n*DH + lane]      * X[(size_t)row*DM + n*DH + lane]
            + bias[n*DH + 32 + lane] * X[(size_t)row*DM + n*DH + 32 + lane];
#pragma unroll
    for (int o = 16; o; o >>= 1) s += __shfl_xor_sync(0xffffffffu, s, o);
    if (!lane) outT[(size_t)(b*16 + n)*rowsPerB + j] = s;
}

__global__ void ef_kernel(const float* __restrict__ rsb, const float* __restrict__ se)
{
    const int gw = (blockIdx.x * blockDim.x + threadIdx.x) >> 5;
    const int lane = threadIdx.x & 31;
    if (gw >= M2 * NH) return;
    const float* q = blockIdx.y ? g_q2 : g_q;
    float* ef = g_ef + (size_t)blockIdx.y * M2 * NH * 2;
    const int row = gw >> 4, n = gw & 15;
    const float v0 = q[(size_t)row*DM + n*DH + lane]      + rsb[n*DH + lane];
    const float v1 = q[(size_t)row*DM + n*DH + 32 + lane] + rsb[n*DH + 32 + lane];
    float s0 = v0*se[n*DH + lane] + v1*se[n*DH + 32 + lane];
    float s1 = v0*se[NH*DH + n*DH + lane] + v1*se[NH*DH + n*DH + 32 + lane];
#pragma unroll
    for (int o = 16; o; o >>= 1) {
        s0 += __shfl_xor_sync(0xffffffffu, s0, o);
        s1 += __shfl_xor_sync(0xffffffffu, s1, o);
    }
    if (!lane) { ef[gw*2] = s0; ef[gw*2 + 1] = s1; }
}

__global__ void vmean_fix(const float* __restrict__ V, __half* __restrict__ O)
{
    int bn = blockIdx.x, b = bn >> 4, n = bn & 15;
    int d = threadIdx.x;
    float s = 0.f;
    for (int j = 0; j < QL; j++) s += V[((size_t)j*2 + b)*DM + n*DH + d];
    s *= (1.0f/1024.0f);
    O[(size_t)M2*DM + (size_t)b*DM + n*DH + d] = __float2half_rn(s);
}

// ---------------- dense GEMM: 2-pass (A single fp16, B hi/lo), 3-stage ----------------
#define GSTAGE 49152
#define GSMEM_BYTES (3*GSTAGE)

__device__ __forceinline__ void g_load_stage(
    const __half* __restrict__ A, const __half* __restrict__ Bh, const __half* __restrict__ Bl,
    uint32_t st, int m0, int n0, int K, int kc, int tid)
{
    const size_t ko = (size_t)kc * 64;
#pragma unroll
    for (int p = 0; p < 4; p++) {
        int c = p*256 + tid;
        int row = c >> 3, kcol = c & 7;
        uint32_t sw = (uint32_t)(row*128 + kcol*16) ^ ((row & 7) << 4);
        cp16(st + sw,         A  + (size_t)(m0 + row)*K + ko + kcol*8);
        cp16(st + 16384 + sw, Bh + (size_t)(n0 + row)*K + ko + kcol*8);
        cp16(st + 32768 + sw, Bl + (size_t)(n0 + row)*K + ko + kcol*8);
    }
    cp_commit();
}

// OUT: 0 fp32 C; 1 fp16 single row-major; 2 fp32 + head-major fp16 hi/lo; 3 fp32 + head-major fp16 single
template<int EPI, int OUT>
__device__ __forceinline__ void gemm_core(
    const __half* __restrict__ A, const __half* __restrict__ Bh, const __half* __restrict__ Bl,
    const float* __restrict__ bias, float* __restrict__ C,
    __half* __restrict__ Chi, __half* __restrict__ Clo,
    int rowsPerB, int K, int ldc)
{
    extern __shared__ char dsm[];
    const uint32_t sbase = smem_u32(dsm);
    const int tid = threadIdx.x, lane = tid & 31, warp = tid >> 5;
    const int m0 = blockIdx.y * 128, n0 = blockIdx.x * 128;
    const int wm = (warp & 1) * 64, wn = (warp >> 1) * 32;
    const int NC = K >> 6;

    float acc[4][4][4] = {};
    g_load_stage(A, Bh, Bl, sbase,            m0, n0, K, 0, tid);
    g_load_stage(A, Bh, Bl, sbase + GSTAGE,   m0, n0, K, 1, tid);
    g_load_stage(A, Bh, Bl, sbase + 2*GSTAGE, m0, n0, K, 2, tid);
    asm volatile("cp.async.wait_group 2;" ::: "memory");
    __syncthreads();

    const int arow = wm + (lane & 15), akb = lane & 16;
    const int brow = wn + ((lane & 16) >> 1) + (lane & 7), bkb = (lane & 8) << 1;

    int buf = 0;
    for (int kc = 0; kc < NC; kc++) {
        const uint32_t st = sbase + buf * GSTAGE;
#pragma unroll
        for (int ks = 0; ks < 4; ks++) {
            const int kb = ks*32;
            uint32_t ah[4][4], bh[2][4], bl[2][4];
#pragma unroll
            for (int im = 0; im < 4; im++) {
                int row = arow + im*16;
                uint32_t off = (uint32_t)(row*128 + kb + akb) ^ ((row & 7) << 4);
                ldsm4(ah[im], st + off);
            }
#pragma unroll
            for (int np = 0; np < 2; np++) {
                int row = brow + np*16;
                uint32_t off = (uint32_t)(row*128 + kb + bkb) ^ ((row & 7) << 4);
                ldsm4(bh[np], st + 16384 + off);
                ldsm4(bl[np], st + 32768 + off);
            }
#pragma unroll
            for (int im = 0; im < 4; im++)
#pragma unroll
                for (int in = 0; in < 4; in++) {
                    const int np = in >> 1, hf = (in & 1) * 2;
                    mma16816(acc[im][in], ah[im], bh[np][hf], bh[np][hf+1]);
                    mma16816(acc[im][in], ah[im], bl[np][hf], bl[np][hf+1]);
                }
        }
        __syncthreads();
        if (kc + 3 < NC) {
            g_load_stage(A, Bh, Bl, sbase + buf*GSTAGE, m0, n0, K, kc + 3, tid);
            asm volatile("cp.async.wait_group 2;" ::: "memory");
        } else if (kc + 2 < NC) {
            asm volatile("cp.async.wait_group 1;" ::: "memory");
        } else {
            asm volatile("cp.async.wait_group 0;" ::: "memory");
        }
        __syncthreads();
        buf++; if (buf == 3) buf = 0;
    }

    const int rbase = m0 + wm + (lane >> 2);
    const int cbase = n0 + wn + 2*(lane & 3);
#pragma unroll
    for (int im = 0; im < 4; im++) {
#pragma unroll
        for (int in = 0; in < 4; in++) {
            int col = cbase + in*8;
            float v0 = acc[im][in][0], v1 = acc[im][in][1];
            float v2 = acc[im][in][2], v3 = acc[im][in][3];
            if (EPI >= 1) {
                float b0 = bias[col], b1 = bias[col+1];
                v0 += b0; v1 += b1; v2 += b0; v3 += b1;
            }
            if (EPI == 2) {
                v0 = 0.5f*v0*(1.0f + erff(v0*0.7071067811865476f));
                v1 = 0.5f*v1*(1.0f + erff(v1*0.7071067811865476f));
                v2 = 0.5f*v2*(1.0f + erff(v2*0.7071067811865476f));
                v3 = 0.5f*v3*(1.0f + erff(v3*0.7071067811865476f));
            }
            int r0 = rbase + im*16, r1 = r0 + 8;
            if (OUT != 1) {
                *(float2*)(C + (size_t)r0*ldc + col) = make_float2(v0, v1);
                *(float2*)(C + (size_t)r1*ldc + col) = make_float2(v2, v3);
            }
            if (OUT == 1) {
                *(__half2*)(Chi + (size_t)r0*ldc + col) =
                    __halves2half2(__float2half_rn(v0), __float2half_rn(v1));
                *(__half2*)(Chi + (size_t)r1*ldc + col) =
                    __halves2half2(__float2half_rn(v2), __float2half_rn(v3));
            }
            if (OUT >= 2) {
                int nh = col >> 6, d = col & 63;
                size_t d0 = (((size_t)(r0 & 1)*NH + nh)*rowsPerB + (r0 >> 1))*DH + d;
                size_t d1 = (((size_t)(r1 & 1)*NH + nh)*rowsPerB + (r1 >> 1))*DH + d;
                if (OUT == 2) {
                    __half h0,h1,h2,h3,l0,l1,l2,l3;
                    hsplit(v0,h0,l0); hsplit(v1,h1,l1); hsplit(v2,h2,l2); hsplit(v3,h3,l3);
                    *(__half2*)(Chi + d0) = __halves2half2(h0, h1);
                    *(__half2*)(Chi + d1) = __halves2half2(h2, h3);
                    *(__half2*)(Clo + d0) = __halves2half2(l0, l1);
                    *(__half2*)(Clo + d1) = __halves2half2(l2, l3);
                } else {
                    *(__half2*)(Chi + d0) =
                        __halves2half2(__float2half_rn(v0), __float2half_rn(v1));
                    *(__half2*)(Chi + d1) =
                        __halves2half2(__float2half_rn(v2), __float2half_rn(v3));
                }
            }
        }
    }
}

template<int EPI, int OUT>
__global__ void __launch_bounds__(256, 1) gemm_mma(
    const __half* __restrict__ A, const __half* __restrict__ Bh, const __half* __restrict__ Bl,
    const float* __restrict__ bias, float* __restrict__ C,
    __half* __restrict__ Chi, __half* __restrict__ Clo,
    size_t zsA, size_t zsC, int rowsPerB, int K, int ldc)
{
    const size_t zo = blockIdx.z;
    gemm_core<EPI, OUT>(A + zo*zsA, Bh, Bl, bias,
                        (OUT != 1) ? C + zo*zsC : C,
                        (OUT >= 1) ? Chi + zo*zsC : Chi, Clo,
                        rowsPerB, K, ldc);
}

__global__ void __launch_bounds__(256, 1) projHKV()
{
    switch (blockIdx.z) {
    case 0: gemm_core<0,2>(g_hb, g_wkT, g_wkT + (size_t)DM*DM,
                           nullptr, g_k, g_khh, g_khl, QL, DM, DM); break;
    case 1: gemm_core<0,0>(g_hb, g_wvT, g_wvT + (size_t)DM*DM,
                           nullptr, g_v, nullptr, nullptr, QL, DM, DM); break;
    default: gemm_core<0,3>(g_hb, g_wqT, g_wqT + (size_t)DM*DM,
                            nullptr, g_q, g_q1h, nullptr, QL, DM, DM); break;
    }
}

// ---------------- batched score GEMM (2-pass: Q single x K hi/lo), causal-pruned ----------------
#define SC_SMEM 49152

__global__ void __launch_bounds__(256, 1) score_mma(
    const __half* __restrict__ Q1, const __half* __restrict__ Q2,
    const __half* __restrict__ Kh, const __half* __restrict__ Kl,
    const float* __restrict__ biasT, float* __restrict__ C,
    size_t zsC, int Ncols, int window)
{
    extern __shared__ char dsm[];
    const uint32_t st = smem_u32(dsm);
    const int tid = threadIdx.x, lane = tid & 31, warp = tid >> 5;
    const int zz = blockIdx.z, s = zz >> 5, bn = zz & 31;
    const __half* Q = s ? Q2 : Q1;
    C += (size_t)s * zsC;

    int i0, j0;
    if (!window) {
        int t = blockIdx.x;
        int it = (int)((sqrtf(8.f*t + 1.f) - 1.f) * 0.5f);
        if ((it + 1)*(it + 2)/2 <= t) it++;
        else if (it*(it + 1)/2 > t) it--;
        int jt = t - it*(it + 1)/2;
        i0 = it * 128; j0 = jt * 128;
    } else {
        int it = blockIdx.y;
        int bx = blockIdx.x;
        if (bx > it + 1) return;
        i0 = it * 128;
        j0 = (7 - it + bx) * 128;
    }

    const size_t qb = ((size_t)bn*QL + i0)*DH;
    const size_t kb = ((size_t)bn*Ncols + j0)*DH;
#pragma unroll
    for (int p = 0; p < 4; p++) {
        int c = p*256 + tid;
        int row = c >> 3, kcol = c & 7;
        uint32_t sw = (uint32_t)(row*128 + kcol*16) ^ ((row & 7) << 4);
        cp16(st + sw,         Q  + qb + (size_t)row*DH + kcol*8);
        cp16(st + 16384 + sw, Kh + kb + (size_t)row*DH + kcol*8);
        cp16(st + 32768 + sw, Kl + kb + (size_t)row*DH + kcol*8);
    }
    cp_commit();
    asm volatile("cp.async.wait_group 0;" ::: "memory");
    __syncthreads();

    const int wm = (warp & 1) * 64, wn = (warp >> 1) * 32;
    const int arow = wm + (lane & 15), akb = lane & 16;
    const int brow = wn + ((lane & 16) >> 1) + (lane & 7), bkb = (lane & 8) << 1;

    float acc[4][4][4] = {};
#pragma unroll
    for (int ks = 0; ks < 4; ks++) {
        const int kbyte = ks*32;
        uint32_t ah[4][4], bh[2][4], bl[2][4];
#pragma unroll
        for (int im = 0; im < 4; im++) {
            int row = arow + im*16;
            uint32_t off = (uint32_t)(row*128 + kbyte + akb) ^ ((row & 7) << 4);
            ldsm4(ah[im], st + off);
        }
#pragma unroll
        for (int np = 0; np < 2; np++) {
            int row = brow + np*16;
            uint32_t off = (uint32_t)(row*128 + kbyte + bkb) ^ ((row & 7) << 4);
            ldsm4(bh[np], st + 16384 + off);
            ldsm4(bl[np], st + 32768 + off);
        }
#pragma unroll
        for (int im = 0; im < 4; im++)
#pragma unroll
            for (int in = 0; in < 4; in++) {
                const int np = in >> 1, hf = (in & 1) * 2;
                mma16816(acc[im][in], ah[im], bh[np][hf], bh[np][hf+1]);
                mma16816(acc[im][in], ah[im], bl[np][hf], bl[np][hf+1]);
            }
    }

    float* Cb = C + (size_t)bn*QL*Ncols;
    const float* bt = biasT + (size_t)bn*Ncols;
    const int rbase = i0 + wm + (lane >> 2);
    const int cbase = j0 + wn + 2*(lane & 3);
#pragma unroll
    for (int im = 0; im < 4; im++)
#pragma unroll
        for (int in = 0; in < 4; in++) {
            int col = cbase + in*8;
            float b0 = bt[col], b1 = bt[col+1];
            int r0 = rbase + im*16, r1 = r0 + 8;
            *(float2*)(Cb + (size_t)r0*Ncols + col) =
                make_float2(acc[im][in][0] + b0, acc[im][in][1] + b1);
            *(float2*)(Cb + (size_t)r1*Ncols + col) =
                make_float2(acc[im][in][2] + b0, acc[im][in][3] + b1);
        }
}

// ---------------- fused combine + softmax + fp16 P (single) ----------------
__global__ void __launch_bounds__(256) softmax_fused(
    const float* __restrict__ S, const float* __restrict__ BD,
    const __half* __restrict__ diff, const float* __restrict__ ef,
    __half* __restrict__ Ph)
{
    __shared__ float red[8];
    const int i = blockIdx.x;
    const int zz = blockIdx.y, s = zz >> 5, bn = zz & 31, b = bn >> 4, n = bn & 15;
    const int jmax = ((i >> 7) + 1) << 7;
    const float* Sr = S    + (size_t)s*SSTR + ((size_t)bn << 20) + ((size_t)i << 10);
    const float* Br = BD   + (size_t)s*BSTR + ((size_t)bn << 21) + ((size_t)i << 11) + (QL - i);
    const __half* Dr = diff + ((size_t)b << 20) + ((size_t)i << 10);
    const float* efs = ef + (size_t)s*M2*NH*2;
    const float e0 = efs[(((size_t)i*2 + b)*NH + n)*2];
    const float de = efs[(((size_t)i*2 + b)*NH + n)*2 + 1] - e0;
    const int t = threadIdx.x, lane = t & 31, w = t >> 5;

    float v[4];
#pragma unroll
    for (int p = 0; p < 4; p++) {
        int j = t + p*256;
        if (j < jmax) {
            float sc = (Sr[j] + Br[j] + e0 + de*__half2float(Dr[j])) * ATT_SCALE;
            bool blocked = s ? (j >= i) : (j > i);
            v[p] = blocked ? sc - 1e30f : sc;
        } else v[p] = -1e30f;
    }
    float m = fmaxf(fmaxf(v[0], v[1]), fmaxf(v[2], v[3]));
#pragma unroll
    for (int o = 16; o; o >>= 1) m = fmaxf(m, __shfl_xor_sync(0xffffffffu, m, o));
    if (!lane) red[w] = m;
    __syncthreads();
    m = red[lane & 7];
#pragma unroll
    for (int o = 4; o; o >>= 1) m = fmaxf(m, __shfl_xor_sync(0xffffffffu, m, o));
    float sum = 0.f;
#pragma unroll
    for (int p = 0; p < 4; p++) { v[p] = expf(v[p] - m); sum += v[p]; }
#pragma unroll
    for (int o = 16; o; o >>= 1) sum += __shfl_xor_sync(0xffffffffu, sum, o);
    __syncthreads();
    if (!lane) red[w] = sum;
    __syncthreads();
    sum = red[lane & 7];
#pragma unroll
    for (int o = 4; o; o >>= 1) sum += __shfl_xor_sync(0xffffffffu, sum, o);
    const float inv = 1.0f / sum;
    const size_t base = (size_t)s*SSTR + ((size_t)bn << 20) + ((size_t)i << 10);
#pragma unroll
    for (int p = 0; p < 4; p++) {
        int j = t + p*256;
        if (j < jmax) Ph[base + j] = __float2half_rn(v[p] * inv);
    }
}

// ---------------- batched PV GEMM (2-pass: P single x V hi/lo, causal K) ----------------
#define PV_STAGE 32768
#define PV_SMEM (2*PV_STAGE)

__device__ __forceinline__ void pv_load(
    const __half* __restrict__ P, const __half* __restrict__ Vh, const __half* __restrict__ Vl,
    uint32_t st, size_t pbase, size_t vbase, int kc, int tid)
{
    const size_t ko = (size_t)kc * 64;
#pragma unroll
    for (int p = 0; p < 4; p++) {
        int c = p*256 + tid;
        int row = c >> 3, kcol = c & 7;
        uint32_t sw = (uint32_t)(row*128 + kcol*16) ^ ((row & 7) << 4);
        cp16(st + sw, P + pbase + (size_t)row*QL + ko + kcol*8);
    }
#pragma unroll
    for (int p = 0; p < 2; p++) {
        int c = p*256 + tid;
        int row = c >> 3, kcol = c & 7;
        uint32_t sw = (uint32_t)(row*128 + kcol*16) ^ ((row & 7) << 4);
        cp16(st + 16384 + sw, Vh + vbase + (size_t)row*QL + ko + kcol*8);
        cp16(st + 24576 + sw, Vl + vbase + (size_t)row*QL + ko + kcol*8);
    }
    cp_commit();
}

__global__ void __launch_bounds__(256, 1) pv_mma(
    const __half* __restrict__ P, const __half* __restrict__ Vh, const __half* __restrict__ Vl,
    __half* __restrict__ O)
{
    extern __shared__ char dsm[];
    const uint32_t sbase = smem_u32(dsm);
    const int tid = threadIdx.x, lane = tid & 31, warp = tid >> 5;
    const int zz = blockIdx.y, s = zz >> 5, bn = zz & 31, b = bn >> 4, n = bn & 15;
    const int it = blockIdx.x;
    const int i0 = it * 128;
    const int NC = 2*it + 2;
    const size_t pbase = (size_t)s*SSTR + ((size_t)bn << 20) + (size_t)i0*QL;
    const size_t vbase = (size_t)bn * DH * QL;
    const size_t obase = (size_t)s * M2 * DM;

    float acc[2][4][4] = {};
    pv_load(P, Vh, Vl, sbase,            pbase, vbase, 0, tid);
    pv_load(P, Vh, Vl, sbase + PV_STAGE, pbase, vbase, 1, tid);
    asm volatile("cp.async.wait_group 1;" ::: "memory");
    __syncthreads();

    const int wm = (warp & 3) * 32, wn = (warp >> 2) * 32;
    const int arow = wm + (lane & 15), akb = lane & 16;
    const int brow = wn + ((lane & 16) >> 1) + (lane & 7), bkb = (lane & 8) << 1;

    for (int kc = 0; kc < NC; kc++) {
        const uint32_t st = sbase + (kc & 1) * PV_STAGE;
#pragma unroll
        for (int ks = 0; ks < 4; ks++) {
            const int kb = ks*32;
            uint32_t ah[2][4], bh[2][4], bl[2][4];
#pragma unroll
            for (int im = 0; im < 2; im++) {
                int row = arow + im*16;
                uint32_t off = (uint32_t)(row*128 + kb + akb) ^ ((row & 7) << 4);
                ldsm4(ah[im], st + off);
            }
#pragma unroll
            for (int np = 0; np < 2; np++) {
                int row = brow + np*16;
                uint32_t off = (uint32_t)(row*128 + kb + bkb) ^ ((row & 7) << 4);
                ldsm4(bh[np], st + 16384 + off);
                ldsm4(bl[np], st + 24576 + off);
            }
#pragma unroll
            for (int im = 0; im < 2; im++)
#pragma unroll
                for (int in = 0; in < 4; in++) {
                    const int np = in >> 1, hf = (in & 1) * 2;
                    mma16816(acc[im][in], ah[im], bh[np][hf], bh[np][hf+1]);
                    mma16816(acc[im][in], ah[im], bl[np][hf], bl[np][hf+1]);
                }
        }
        __syncthreads();
        if (kc + 2 < NC) {
            pv_load(P, Vh, Vl, sbase + (kc & 1)*PV_STAGE, pbase, vbase, kc + 2, tid);
            asm volatile("cp.async.wait_group 1;" ::: "memory");
        } else {
            asm volatile("cp.async.wait_group 0;" ::: "memory");
        }
        __syncthreads();
    }

    const int rl = wm + (lane >> 2);
    const int cb = wn + 2*(lane & 3);
#pragma unroll
    for (int im = 0; im < 2; im++)
#pragma unroll
        for (int in = 0; in < 4; in++) {
            int col = cb + in*8;
            int r0 = i0 + rl + im*16, r1 = r0 + 8;
            *(__half2*)(O + obase + ((size_t)r0*2 + b)*DM + n*DH + col) =
                __halves2half2(__float2half_rn(acc[im][in][0]), __float2half_rn(acc[im][in][1]));
            *(__half2*)(O + obase + ((size_t)r1*2 + b)*DM + n*DH + col) =
                __halves2half2(__float2half_rn(acc[im][in][2]), __float2half_rn(acc[im][in][3]));
        }
}

// ---------------- residual + LayerNorm (merged streams) ----------------
template<int WB16>
__global__ void __launch_bounds__(256) add_ln(
    const float* __restrict__ a, const float* __restrict__ x0, const float* __restrict__ x1,
    const float* __restrict__ gamma, const float* __restrict__ beta,
    float* __restrict__ out, __half* __restrict__ oh)
{
    __shared__ float buf[1024];
    __shared__ float red[8];
    __shared__ float s_stat;
    const size_t base = (size_t)blockIdx.x << 10;
    const int str = blockIdx.x >> 11;
    const size_t lbase = (size_t)(blockIdx.x & 2047) << 10;
    const float* x = str ? x1 : x0;
    const int t = threadIdx.x, lane = t & 31, w = t >> 5;
    float sum = 0.f;
#pragma unroll
    for (int p = 0; p < 4; p++) {
        float v = a[base + t + p*256] + x[lbase + t + p*256];
        buf[t + p*256] = v; sum += v;
    }
#pragma unroll
    for (int o = 16; o; o >>= 1) sum += __shfl_xor_sync(0xffffffffu, sum, o);
    if (!lane) red[w] = sum;
    __syncthreads();
    if (t == 0) { float s = 0; for (int i = 0; i < 8; i++) s += red[i]; s_stat = s * (1.0f/1024.0f); }
    __syncthreads();
    const float mean = s_stat;
    float vs = 0.f;
#pragma unroll
    for (int p = 0; p < 4; p++) { float d = buf[t + p*256] - mean; vs += d*d; }
#pragma unroll
    for (int o = 16; o; o >>= 1) vs += __shfl_xor_sync(0xffffffffu, vs, o);
    __syncthreads();
    if (!lane) red[w] = vs;
    __syncthreads();
    if (t == 0) { float s = 0; for (int i = 0; i < 8; i++) s += red[i]; s_stat = s * (1.0f/1024.0f); }
    __syncthreads();
    const float r = rsqrtf(s_stat + 1e-12f);
#pragma unroll
    for (int p = 0; p < 4; p++) {
        int c = t + p*256;
        float val = (buf[c] - mean) * r * gamma[c] + beta[c];
        out[base + c] = val;
        if (WB16) oh[base + c] = __float2half_rn(val);
    }
}

// ---------------- host ----------------
extern "C" void kernel_launch(void* const* d_in, const int* in_sizes, int n_in,
                              void* d_out, int out_size)
{
    (void)in_sizes; (void)n_in; (void)out_size;
    const float* h       = (const float*)d_in[0];
    const float* g       = (const float*)d_in[1];
    const float* r       = (const float*)d_in[2];
    const float* seg_mat = (const float*)d_in[5];
    const float* wq      = (const float*)d_in[6];
    const float* wk      = (const float*)d_in[7];
    const float* wv      = (const float*)d_in[8];
    const float* wo      = (const float*)d_in[9];
    const float* wr      = (const float*)d_in[10];
    const float* rwb     = (const float*)d_in[11];
    const float* rrb     = (const float*)d_in[12];
    const float* rsb     = (const float*)d_in[13];
    const float* se      = (const float*)d_in[14];
    const float* lnga    = (const float*)d_in[15];
    const float* lnba    = (const float*)d_in[16];
    const float* w1      = (const float*)d_in[17];
    const float* b1      = (const float*)d_in[18];
    const float* w2      = (const float*)d_in[19];
    const float* b2      = (const float*)d_in[20];
    const float* lngf    = (const float*)d_in[21];
    const float* lnbf    = (const float*)d_in[22];

    cudaFuncSetAttribute(projHKV,       cudaFuncAttributeMaxDynamicSharedMemorySize, GSMEM_BYTES);
    cudaFuncSetAttribute(gemm_mma<0,0>, cudaFuncAttributeMaxDynamicSharedMemorySize, GSMEM_BYTES);
    cudaFuncSetAttribute(gemm_mma<0,2>, cudaFuncAttributeMaxDynamicSharedMemorySize, GSMEM_BYTES);
    cudaFuncSetAttribute(gemm_mma<0,3>, cudaFuncAttributeMaxDynamicSharedMemorySize, GSMEM_BYTES);
    cudaFuncSetAttribute(gemm_mma<2,1>, cudaFuncAttributeMaxDynamicSharedMemorySize, GSMEM_BYTES);
    cudaFuncSetAttribute(gemm_mma<1,0>, cudaFuncAttributeMaxDynamicSharedMemorySize, GSMEM_BYTES);
    cudaFuncSetAttribute(score_mma,     cudaFuncAttributeMaxDynamicSharedMemorySize, SC_SMEM);
    cudaFuncSetAttribute(pv_mma,        cudaFuncAttributeMaxDynamicSharedMemorySize, PV_SMEM);

    float *q2f,*k,*v,*kr,*ef,*o,*y,*z,*bkT,*bkrT,*S,*BD;
    __half *hb,*rb,*gb,*wqT,*wkT,*wvT,*wrT,*woC,*w1T,*w2T,*diffb;
    __half *q1h,*q2h,*khh,*khl,*krh,*krl,*vth,*vtl,*Ph,*at,*yh,*th;
    cudaGetSymbolAddress((void**)&q2f,  g_q2);
    cudaGetSymbolAddress((void**)&k,    g_k);
    cudaGetSymbolAddress((void**)&v,    g_v);
    cudaGetSymbolAddress((void**)&kr,   g_kr);
    cudaGetSymbolAddress((void**)&ef,   g_ef);
    cudaGetSymbolAddress((void**)&o,    g_o);
    cudaGetSymbolAddress((void**)&y,    g_y);
    cudaGetSymbolAddress((void**)&z,    g_z);
    cudaGetSymbolAddress((void**)&bkT,  g_bkT);
    cudaGetSymbolAddress((void**)&bkrT, g_bkrT);
    cudaGetSymbolAddress((void**)&S,    g_S);
    cudaGetSymbolAddress((void**)&BD,   g_BD);
    cudaGetSymbolAddress((void**)&diffb,g_diffb);
    cudaGetSymbolAddress((void**)&hb,   g_hb);
    cudaGetSymbolAddress((void**)&rb,   g_rb);
    cudaGetSymbolAddress((void**)&gb,   g_gb);
    cudaGetSymbolAddress((void**)&wqT,  g_wqT);
    cudaGetSymbolAddress((void**)&wkT,  g_wkT);
    cudaGetSymbolAddress((void**)&wvT,  g_wvT);
    cudaGetSymbolAddress((void**)&wrT,  g_wrT);
    cudaGetSymbolAddress((void**)&woC,  g_woC);
    cudaGetSymbolAddress((void**)&w1T,  g_w1T);
    cudaGetSymbolAddress((void**)&w2T,  g_w2T);
    cudaGetSymbolAddress((void**)&q1h,  g_q1h);
    cudaGetSymbolAddress((void**)&q2h,  g_q2h);
    cudaGetSymbolAddress((void**)&khh,  g_khh);
    cudaGetSymbolAddress((void**)&khl,  g_khl);
    cudaGetSymbolAddress((void**)&krh,  g_krh);
    cudaGetSymbolAddress((void**)&krl,  g_krl);
    cudaGetSymbolAddress((void**)&vth,  g_vth);
    cudaGetSymbolAddress((void**)&vtl,  g_vtl);
    cudaGetSymbolAddress((void**)&Ph,   g_Ph);
    cudaGetSymbolAddress((void**)&at,   g_at);
    cudaGetSymbolAddress((void**)&yh,   g_yh);
    cudaGetSymbolAddress((void**)&th,   g_th);

    dim3 tb(32, 8);
    convT_split<<<dim3(DM/32, DM/32), tb>>>(wk, wkT, wkT + (size_t)DM*DM, DM, DM);
    convT_split<<<dim3(DM/32, DM/32), tb>>>(wv, wvT, wvT + (size_t)DM*DM, DM, DM);
    convT_split<<<dim3(DM/32, DM/32), tb>>>(wq, wqT, wqT + (size_t)DM*DM, DM, DM);
    conv_half<<<(M2*DM/4 + 255)/256, 256>>>(h, hb, M2*DM/4);
    projHKV<<<dim3(8, 16, 3), 256, GSMEM_BYTES>>>();

    convT_split<<<dim3(DM/32, DM/32), tb>>>(wr, wrT, wrT + (size_t)DM*DM, DM, DM);
    conv_half<<<(MR*DM/4 + 255)/256, 256>>>(r, rb, MR*DM/4);
    conv_half<<<(M2*DM/4 + 255)/256, 256>>>(g, gb, M2*DM/4);
    conv_split<<<(DM*DM/4 + 255)/256, 256>>>(wo, woC, woC + (size_t)DM*DM, DM*DM/4);
    convT_split<<<dim3(DI/32, DM/32), tb>>>(w1, w1T, w1T + (size_t)DM*DI, DM, DI);
    convT_split<<<dim3(DM/32, DI/32), tb>>>(w2, w2T, w2T + (size_t)DI*DM, DI, DM);
    prep_diff<<<(2*QL*QL + 255)/256, 256>>>(seg_mat, diffb);

    gemm_mma<0,2><<<dim3(8,32,1), 256, GSMEM_BYTES>>>(rb, wrT, wrT+(size_t)DM*DM,
        nullptr, kr, krh, krl, 0, 0, RL, DM, DM);
    gemm_mma<0,3><<<dim3(8,16,1), 256, GSMEM_BYTES>>>(gb, wqT, wqT+(size_t)DM*DM,
        nullptr, q2f, q2h, nullptr, 0, 0, QL, DM, DM);
    repack_vT<<<dim3(QL/32, DH/32, 32), tb>>>(v, vth, vtl);

    bias_dotT<<<(M2*NH*32 + 255)/256, 256>>>(k,  rwb, bkT,  QL);
    bias_dotT<<<(MR*NH*32 + 255)/256, 256>>>(kr, rrb, bkrT, RL);
    ef_kernel<<<dim3((M2*NH*32 + 255)/256, 2), 256>>>(rsb, se);

    // attention (both streams merged; causal-pruned; 2-pass)
    score_mma<<<dim3(36, 1, 64), 256, SC_SMEM>>>(q1h, q2h, khh, khl, bkT,  S,  SSTR, QL, 0);
    score_mma<<<dim3(9, 8, 64), 256, SC_SMEM>>>(q1h, q2h, krh, krl, bkrT, BD, BSTR, RL, 1);
    softmax_fused<<<dim3(QL, 64), 256>>>(S, BD, diffb, ef, Ph);
    pv_mma<<<dim3(8, 64), 256, PV_SMEM>>>(Ph, vth, vtl, at);
    vmean_fix<<<32, 64>>>(v, at);

    // back half (both streams merged via z)
    gemm_mma<0,0><<<dim3(8,16,2), 256, GSMEM_BYTES>>>(at, woC, woC+(size_t)DM*DM,
        nullptr, o, nullptr, nullptr, (size_t)M2*DM, (size_t)M2*DM, QL, DM, DM);
    add_ln<1><<<2*M2, 256>>>(o, h, g, lnga, lnba, y, yh);
    gemm_mma<2,1><<<dim3(32,16,2), 256, GSMEM_BYTES>>>(yh, w1T, w1T+(size_t)DM*DI,
        b1, nullptr, th, nullptr, (size_t)M2*DM, (size_t)M2*DI, QL, DM, DI);
    gemm_mma<1,0><<<dim3(8,16,2), 256, GSMEM_BYTES>>>(th, w2T, w2T+(size_t)DI*DM,
        b2, z, nullptr, nullptr, (size_t)M2*DI, (size_t)M2*DM, QL, DI, DM);
    add_ln<0><<<2*M2, 256>>>(z, y, y + (size_t)M2*DM, lngf, lnbf, (float*)d_out, nullptr);
}

// round 12
// speedup vs baseline: 2.6596x; 1.4028x over previous
#include <cuda_runtime.h>
#include <cuda_fp16.h>
#include <math.h>
#include <stdint.h>

#define QL 1024
#define NH 16
#define DH 64
#define DM 1024
#define DI 4096
#define RL 2048
#define M2 (QL*2)
#define MR (RL*2)
#define ATT_SCALE 0.125f
#define SSTR ((size_t)32*QL*QL)
#define BSTR ((size_t)32*QL*RL)

__device__ __forceinline__ uint32_t smem_u32(const void* p) {
    uint32_t a;
    asm("{ .reg .u64 t; cvta.to.shared.u64 t, %1; cvt.u32.u64 %0, t; }" : "=r"(a) : "l"(p));
    return a;
}
__device__ __forceinline__ void cp16(uint32_t dst, const void* src) {
    asm volatile("cp.async.cg.shared.global [%0], [%1], 16;" :: "r"(dst), "l"(src));
}
__device__ __forceinline__ void cp_commit() { asm volatile("cp.async.commit_group;" ::: "memory"); }
__device__ __forceinline__ void ldsm4(uint32_t (&r)[4], uint32_t addr) {
    asm volatile("ldmatrix.sync.aligned.m8n8.x4.shared.b16 {%0,%1,%2,%3}, [%4];"
        : "=r"(r[0]), "=r"(r[1]), "=r"(r[2]), "=r"(r[3]) : "r"(addr));
}
__device__ __forceinline__ void mma16816(float (&d)[4], const uint32_t (&a)[4],
                                         uint32_t b0, uint32_t b1) {
    asm volatile("mma.sync.aligned.m16n8k16.row.col.f32.f16.f16.f32 "
        "{%0,%1,%2,%3},{%4,%5,%6,%7},{%8,%9},{%0,%1,%2,%3};"
        : "+f"(d[0]), "+f"(d[1]), "+f"(d[2]), "+f"(d[3])
        : "r"(a[0]), "r"(a[1]), "r"(a[2]), "r"(a[3]), "r"(b0), "r"(b1));
}

// ---------------- scratch ----------------
__device__ float g_q [M2*DM];
__device__ float g_q2[M2*DM];
__device__ float g_k [M2*DM];
__device__ float g_v [M2*DM];
__device__ float g_kr[MR*DM];
__device__ float g_ef[2*M2*NH*2];
__device__ float g_o [2*M2*DM];
__device__ float g_y [2*M2*DM];
__device__ float g_z [2*M2*DM];
__device__ float g_bkT [32*QL];
__device__ float g_bkrT[32*RL];
__device__ float g_S [2*SSTR];
__device__ float g_BD[2*BSTR];
__device__ __align__(256) __half g_diffb[(size_t)2*QL*QL];
__device__ __align__(256) __half g_hb[M2*DM], g_rb[MR*DM], g_gb[M2*DM];
__device__ __align__(256) __half g_wqT[DM*DM], g_wkT[DM*DM], g_wvT[DM*DM];
__device__ __align__(256) __half g_wrT[DM*DM], g_woC[DM*DM];
__device__ __align__(256) __half g_w1T[DM*DI], g_w2T[DI*DM];
__device__ __align__(256) __half g_q1h[32*QL*DH], g_q2h[32*QL*DH];
__device__ __align__(256) __half g_khh[32*QL*DH];
__device__ __align__(256) __half g_krh[32*RL*DH];
__device__ __align__(256) __half g_vth[32*DH*QL];
__device__ __align__(256) __half g_Ph [2*SSTR];
__device__ __align__(256) __half g_at [2*M2*DM];
__device__ __align__(256) __half g_yh [2*M2*DM];
__device__ __align__(256) __half g_th [2*M2*DI];

// ---------------- small kernels ----------------
__global__ void conv_half(const float* __restrict__ X, __half* __restrict__ out, int n4)
{
    int i = blockIdx.x * blockDim.x + threadIdx.x;
    if (i >= n4) return;
    float4 v = ((const float4*)X)[i];
    ((__half2*)out)[2*i]   = __halves2half2(__float2half_rn(v.x), __float2half_rn(v.y));
    ((__half2*)out)[2*i+1] = __halves2half2(__float2half_rn(v.z), __float2half_rn(v.w));
}

__global__ void convT_half(const float* __restrict__ W, __half* __restrict__ out, int K, int N)
{
    __shared__ float t[32][33];
    int k0 = blockIdx.y * 32, n0 = blockIdx.x * 32;
    int tx = threadIdx.x, ty = threadIdx.y;
#pragma unroll
    for (int p = 0; p < 4; p++)
        t[ty + p*8][tx] = W[(size_t)(k0 + ty + p*8)*N + n0 + tx];
    __syncthreads();
#pragma unroll
    for (int p = 0; p < 4; p++)
        out[(size_t)(n0 + ty + p*8)*K + k0 + tx] = __float2half_rn(t[tx][ty + p*8]);
}

__global__ void repack_vT(const float* __restrict__ V, __half* __restrict__ out)
{
    __shared__ float tile[32][33];
    int j0 = blockIdx.x * 32, d0 = blockIdx.y * 32;
    int bn = blockIdx.z, b = bn >> 4, n = bn & 15;
    int tx = threadIdx.x, ty = threadIdx.y;
#pragma unroll
    for (int p = 0; p < 4; p++)
        tile[ty + p*8][tx] = V[((size_t)(j0 + ty + p*8)*2 + b)*DM + n*DH + d0 + tx];
    __syncthreads();
#pragma unroll
    for (int p = 0; p < 4; p++)
        out[((size_t)bn*DH + d0 + ty + p*8)*QL + j0 + tx] = __float2half_rn(tile[tx][ty + p*8]);
}

__global__ void prep_diff(const float* __restrict__ seg_mat, __half* __restrict__ diff)
{
    size_t idx = (size_t)blockIdx.x * blockDim.x + threadIdx.x;
    if (idx >= (size_t)2*QL*QL) return;
    int j = idx & 1023, i = (idx >> 10) & 1023, b = (int)(idx >> 20);
    diff[idx] = __float2half_rn(seg_mat[(((size_t)i*QL + j)*2 + b)*2 + 1]);
}

__global__ void bias_dotT(const float* __restrict__ X, const float* __restrict__ bias,
                          float* __restrict__ outT, int rowsPerB)
{
    const int gw = (blockIdx.x * blockDim.x + threadIdx.x) >> 5;
    const int lane = threadIdx.x & 31;
    if (gw >= rowsPerB * 2 * NH) return;
    const int row = gw >> 4, n = gw & 15;
    const int j = row >> 1, b = row & 1;
    float s = bias[n*DH + lane]      * X[(size_t)row*DM + n*DH + lane]
            + bias[n*DH + 32 + lane] * X[(size_t)row*DM + n*DH + 32 + lane];
#pragma unroll
    for (int o = 16; o; o >>= 1) s += __shfl_xor_sync(0xffffffffu, s, o);
    if (!lane) outT[(size_t)(b*16 + n)*rowsPerB + j] = s;
}

__global__ void ef_kernel(const float* __restrict__ rsb, const float* __restrict__ se)
{
    const int gw = (blockIdx.x * blockDim.x + threadIdx.x) >> 5;
    const int lane = threadIdx.x & 31;
    if (gw >= M2 * NH) return;
    const float* q = blockIdx.y ? g_q2 : g_q;
    float* ef = g_ef + (size_t)blockIdx.y * M2 * NH * 2;
    const int row = gw >> 4, n = gw & 15;
    const float v0 = q[(size_t)row*DM + n*DH + lane]      + rsb[n*DH + lane];
    const float v1 = q[(size_t)row*DM + n*DH + 32 + lane] + rsb[n*DH + 32 + lane];
    float s0 = v0*se[n*DH + lane] + v1*se[n*DH + 32 + lane];
    float s1 = v0*se[NH*DH + n*DH + lane] + v1*se[NH*DH + n*DH + 32 + lane];
#pragma unroll
    for (int o = 16; o; o >>= 1) {
        s0 += __shfl_xor_sync(0xffffffffu, s0, o);
        s1 += __shfl_xor_sync(0xffffffffu, s1, o);
    }
    if (!lane) { ef[gw*2] = s0; ef[gw*2 + 1] = s1; }
}

__global__ void vmean_fix(const float* __restrict__ V, __half* __restrict__ O)
{
    int bn = blockIdx.x, b = bn >> 4, n = bn & 15;
    int d = threadIdx.x;
    float s = 0.f;
    for (int j = 0; j < QL; j++) s += V[((size_t)j*2 + b)*DM + n*DH + d];
    s *= (1.0f/1024.0f);
    O[(size_t)M2*DM + (size_t)b*DM + n*DH + d] = __float2half_rn(s);
}

// ---------------- dense GEMM: 1-pass fp16 (A single x B single), 3-stage, 2 CTA/SM ----------------
#define GSTAGE 32768
#define GSMEM_BYTES (3*GSTAGE)

__device__ __forceinline__ void g_load_stage(
    const __half* __restrict__ A, const __half* __restrict__ B,
    uint32_t st, int m0, int n0, int K, int kc, int tid)
{
    const size_t ko = (size_t)kc * 64;
#pragma unroll
    for (int p = 0; p < 4; p++) {
        int c = p*256 + tid;
        int row = c >> 3, kcol = c & 7;
        uint32_t sw = (uint32_t)(row*128 + kcol*16) ^ ((row & 7) << 4);
        cp16(st + sw,         A + (size_t)(m0 + row)*K + ko + kcol*8);
        cp16(st + 16384 + sw, B + (size_t)(n0 + row)*K + ko + kcol*8);
    }
    cp_commit();
}

// OUT: 0 fp32 C; 1 fp16 single row-major; 3 fp32 C + head-major fp16 single
template<int EPI, int OUT>
__device__ __forceinline__ void gemm_core(
    const __half* __restrict__ A, const __half* __restrict__ B,
    const float* __restrict__ bias, float* __restrict__ C,
    __half* __restrict__ Ch, int rowsPerB, int K, int ldc)
{
    extern __shared__ char dsm[];
    const uint32_t sbase = smem_u32(dsm);
    const int tid = threadIdx.x, lane = tid & 31, warp = tid >> 5;
    const int m0 = blockIdx.y * 128, n0 = blockIdx.x * 128;
    const int wm = (warp & 1) * 64, wn = (warp >> 1) * 32;
    const int NC = K >> 6;

    float acc[4][4][4] = {};
    g_load_stage(A, B, sbase,            m0, n0, K, 0, tid);
    g_load_stage(A, B, sbase + GSTAGE,   m0, n0, K, 1, tid);
    g_load_stage(A, B, sbase + 2*GSTAGE, m0, n0, K, 2, tid);
    asm volatile("cp.async.wait_group 2;" ::: "memory");
    __syncthreads();

    const int arow = wm + (lane & 15), akb = lane & 16;
    const int brow = wn + ((lane & 16) >> 1) + (lane & 7), bkb = (lane & 8) << 1;

    int buf = 0;
    for (int kc = 0; kc < NC; kc++) {
        const uint32_t st = sbase + buf * GSTAGE;
#pragma unroll
        for (int ks = 0; ks < 4; ks++) {
            const int kb = ks*32;
            uint32_t ah[4][4], bh[2][4];
#pragma unroll
            for (int im = 0; im < 4; im++) {
                int row = arow + im*16;
                uint32_t off = (uint32_t)(row*128 + kb + akb) ^ ((row & 7) << 4);
                ldsm4(ah[im], st + off);
            }
#pragma unroll
            for (int np = 0; np < 2; np++) {
                int row = brow + np*16;
                uint32_t off = (uint32_t)(row*128 + kb + bkb) ^ ((row & 7) << 4);
                ldsm4(bh[np], st + 16384 + off);
            }
#pragma unroll
            for (int im = 0; im < 4; im++)
#pragma unroll
                for (int in = 0; in < 4; in++) {
                    const int np = in >> 1, hf = (in & 1) * 2;
                    mma16816(acc[im][in], ah[im], bh[np][hf], bh[np][hf+1]);
                }
        }
        __syncthreads();
        if (kc + 3 < NC) {
            g_load_stage(A, B, sbase + buf*GSTAGE, m0, n0, K, kc + 3, tid);
            asm volatile("cp.async.wait_group 2;" ::: "memory");
        } else if (kc + 2 < NC) {
            asm volatile("cp.async.wait_group 1;" ::: "memory");
        } else {
            asm volatile("cp.async.wait_group 0;" ::: "memory");
        }
        __syncthreads();
        buf++; if (buf == 3) buf = 0;
    }

    const int rbase = m0 + wm + (lane >> 2);
    const int cbase = n0 + wn + 2*(lane & 3);
#pragma unroll
    for (int im = 0; im < 4; im++) {
#pragma unroll
        for (int in = 0; in < 4; in++) {
            int col = cbase + in*8;
            float v0 = acc[im][in][0], v1 = acc[im][in][1];
            float v2 = acc[im][in][2], v3 = acc[im][in][3];
            if (EPI >= 1) {
                float b0 = bias[col], b1 = bias[col+1];
                v0 += b0; v1 += b1; v2 += b0; v3 += b1;
            }
            if (EPI == 2) {
                v0 = 0.5f*v0*(1.0f + erff(v0*0.7071067811865476f));
                v1 = 0.5f*v1*(1.0f + erff(v1*0.7071067811865476f));
                v2 = 0.5f*v2*(1.0f + erff(v2*0.7071067811865476f));
                v3 = 0.5f*v3*(1.0f + erff(v3*0.7071067811865476f));
            }
            int r0 = rbase + im*16, r1 = r0 + 8;
            if (OUT != 1) {
                *(float2*)(C + (size_t)r0*ldc + col) = make_float2(v0, v1);
                *(float2*)(C + (size_t)r1*ldc + col) = make_float2(v2, v3);
            }
            if (OUT == 1) {
                *(__half2*)(Ch + (size_t)r0*ldc + col) =
                    __halves2half2(__float2half_rn(v0), __float2half_rn(v1));
                *(__half2*)(Ch + (size_t)r1*ldc + col) =
                    __halves2half2(__float2half_rn(v2), __float2half_rn(v3));
            }
            if (OUT == 3) {
                int nh = col >> 6, d = col & 63;
                size_t d0 = (((size_t)(r0 & 1)*NH + nh)*rowsPerB + (r0 >> 1))*DH + d;
                size_t d1 = (((size_t)(r1 & 1)*NH + nh)*rowsPerB + (r1 >> 1))*DH + d;
                *(__half2*)(Ch + d0) = __halves2half2(__float2half_rn(v0), __float2half_rn(v1));
                *(__half2*)(Ch + d1) = __halves2half2(__float2half_rn(v2), __float2half_rn(v3));
            }
        }
    }
}

template<int EPI, int OUT>
__global__ void __launch_bounds__(256, 2) gemm_mma(
    const __half* __restrict__ A, const __half* __restrict__ B,
    const float* __restrict__ bias, float* __restrict__ C, __half* __restrict__ Ch,
    size_t zsA, size_t zsC, int rowsPerB, int K, int ldc)
{
    const size_t zo = blockIdx.z;
    gemm_core<EPI, OUT>(A + zo*zsA, B, bias,
                        (OUT != 1) ? C + zo*zsC : C,
                        (OUT >= 1) ? Ch + zo*zsC : Ch,
                        rowsPerB, K, ldc);
}

__global__ void __launch_bounds__(256, 2) projHKV()
{
    switch (blockIdx.z) {
    case 0: gemm_core<0,3>(g_hb, g_wkT, nullptr, g_k, g_khh, QL, DM, DM); break;
    case 1: gemm_core<0,0>(g_hb, g_wvT, nullptr, g_v, nullptr, QL, DM, DM); break;
    default: gemm_core<0,3>(g_hb, g_wqT, nullptr, g_q, g_q1h, QL, DM, DM); break;
    }
}

// ---------------- batched score GEMM (1-pass), causal-pruned ----------------
#define SC_SMEM 32768

__global__ void __launch_bounds__(256, 2) score_mma(
    const __half* __restrict__ Q1, const __half* __restrict__ Q2,
    const __half* __restrict__ Km, const float* __restrict__ biasT,
    float* __restrict__ C, size_t zsC, int Ncols, int window)
{
    extern __shared__ char dsm[];
    const uint32_t st = smem_u32(dsm);
    const int tid = threadIdx.x, lane = tid & 31, warp = tid >> 5;
    const int zz = blockIdx.z, s = zz >> 5, bn = zz & 31;
    const __half* Q = s ? Q2 : Q1;
    C += (size_t)s * zsC;

    int i0, j0;
    if (!window) {
        int t = blockIdx.x;
        int it = (int)((sqrtf(8.f*t + 1.f) - 1.f) * 0.5f);
        if ((it + 1)*(it + 2)/2 <= t) it++;
        else if (it*(it + 1)/2 > t) it--;
        int jt = t - it*(it + 1)/2;
        i0 = it * 128; j0 = jt * 128;
    } else {
        int it = blockIdx.y;
        int bx = blockIdx.x;
        if (bx > it + 1) return;
        i0 = it * 128;
        j0 = (7 - it + bx) * 128;
    }

    const size_t qb = ((size_t)bn*QL + i0)*DH;
    const size_t kb = ((size_t)bn*Ncols + j0)*DH;
#pragma unroll
    for (int p = 0; p < 4; p++) {
        int c = p*256 + tid;
        int row = c >> 3, kcol = c & 7;
        uint32_t sw = (uint32_t)(row*128 + kcol*16) ^ ((row & 7) << 4);
        cp16(st + sw,         Q  + qb + (size_t)row*DH + kcol*8);
        cp16(st + 16384 + sw, Km + kb + (size_t)row*DH + kcol*8);
    }
    cp_commit();
    asm volatile("cp.async.wait_group 0;" ::: "memory");
    __syncthreads();

    const int wm = (warp & 1) * 64, wn = (warp >> 1) * 32;
    const int arow = wm + (lane & 15), akb = lane & 16;
    const int brow = wn + ((lane & 16) >> 1) + (lane & 7), bkb = (lane & 8) << 1;

    float acc[4][4][4] = {};
#pragma unroll
    for (int ks = 0; ks < 4; ks++) {
        const int kbyte = ks*32;
        uint32_t ah[4][4], bh[2][4];
#pragma unroll
        for (int im = 0; im < 4; im++) {
            int row = arow + im*16;
            uint32_t off = (uint32_t)(row*128 + kbyte + akb) ^ ((row & 7) << 4);
            ldsm4(ah[im], st + off);
        }
#pragma unroll
        for (int np = 0; np < 2; np++) {
            int row = brow + np*16;
            uint32_t off = (uint32_t)(row*128 + kbyte + bkb) ^ ((row & 7) << 4);
            ldsm4(bh[np], st + 16384 + off);
        }
#pragma unroll
        for (int im = 0; im < 4; im++)
#pragma unroll
            for (int in = 0; in < 4; in++) {
                const int np = in >> 1, hf = (in & 1) * 2;
                mma16816(acc[im][in], ah[im], bh[np][hf], bh[np][hf+1]);
            }
    }

    float* Cb = C + (size_t)bn*QL*Ncols;
    const float* bt = biasT + (size_t)bn*Ncols;
    const int rbase = i0 + wm + (lane >> 2);
    const int cbase = j0 + wn + 2*(lane & 3);
#pragma unroll
    for (int im = 0; im < 4; im++)
#pragma unroll
        for (int in = 0; in < 4; in++) {
            int col = cbase + in*8;
            float b0 = bt[col], b1 = bt[col+1];
            int r0 = rbase + im*16, r1 = r0 + 8;
            *(float2*)(Cb + (size_t)r0*Ncols + col) =
                make_float2(acc[im][in][0] + b0, acc[im][in][1] + b1);
            *(float2*)(Cb + (size_t)r1*Ncols + col) =
                make_float2(acc[im][in][2] + b0, acc[im][in][3] + b1);
        }
}

// ---------------- fused combine + softmax + fp16 P ----------------
__global__ void __launch_bounds__(256) softmax_fused(
    const float* __restrict__ S, const float* __restrict__ BD,
    const __half* __restrict__ diff, const float* __restrict__ ef,
    __half* __restrict__ Ph)
{
    __shared__ float red[8];
    const int i = blockIdx.x;
    const int zz = blockIdx.y, s = zz >> 5, bn = zz & 31, b = bn >> 4, n = bn & 15;
    const int jmax = ((i >> 7) + 1) << 7;
    const float* Sr = S    + (size_t)s*SSTR + ((size_t)bn << 20) + ((size_t)i << 10);
    const float* Br = BD   + (size_t)s*BSTR + ((size_t)bn << 21) + ((size_t)i << 11) + (QL - i);
    const __half* Dr = diff + ((size_t)b << 20) + ((size_t)i << 10);
    const float* efs = ef + (size_t)s*M2*NH*2;
    const float e0 = efs[(((size_t)i*2 + b)*NH + n)*2];
    const float de = efs[(((size_t)i*2 + b)*NH + n)*2 + 1] - e0;
    const int t = threadIdx.x, lane = t & 31, w = t >> 5;

    float v[4];
#pragma unroll
    for (int p = 0; p < 4; p++) {
        int j = t + p*256;
        if (j < jmax) {
            float sc = (Sr[j] + Br[j] + e0 + de*__half2float(Dr[j])) * ATT_SCALE;
            bool blocked = s ? (j >= i) : (j > i);
            v[p] = blocked ? sc - 1e30f : sc;
        } else v[p] = -1e30f;
    }
    float m = fmaxf(fmaxf(v[0], v[1]), fmaxf(v[2], v[3]));
#pragma unroll
    for (int o = 16; o; o >>= 1) m = fmaxf(m, __shfl_xor_sync(0xffffffffu, m, o));
    if (!lane) red[w] = m;
    __syncthreads();
    m = red[lane & 7];
#pragma unroll
    for (int o = 4; o; o >>= 1) m = fmaxf(m, __shfl_xor_sync(0xffffffffu, m, o));
    float sum = 0.f;
#pragma unroll
    for (int p = 0; p < 4; p++) { v[p] = expf(v[p] - m); sum += v[p]; }
#pragma unroll
    for (int o = 16; o; o >>= 1) sum += __shfl_xor_sync(0xffffffffu, sum, o);
    __syncthreads();
    if (!lane) red[w] = sum;
    __syncthreads();
    sum = red[lane & 7];
#pragma unroll
    for (int o = 4; o; o >>= 1) sum += __shfl_xor_sync(0xffffffffu, sum, o);
    const float inv = 1.0f / sum;
    const size_t base = (size_t)s*SSTR + ((size_t)bn << 20) + ((size_t)i << 10);
#pragma unroll
    for (int p = 0; p < 4; p++) {
        int j = t + p*256;
        if (j < jmax) Ph[base + j] = __float2half_rn(v[p] * inv);
    }
}

// ---------------- batched PV GEMM (1-pass, causal K) ----------------
#define PV_STAGE 24576
#define PV_SMEM (2*PV_STAGE)

__device__ __forceinline__ void pv_load(
    const __half* __restrict__ P, const __half* __restrict__ V,
    uint32_t st, size_t pbase, size_t vbase, int kc, int tid)
{
    const size_t ko = (size_t)kc * 64;
#pragma unroll
    for (int p = 0; p < 4; p++) {
        int c = p*256 + tid;
        int row = c >> 3, kcol = c & 7;
        uint32_t sw = (uint32_t)(row*128 + kcol*16) ^ ((row & 7) << 4);
        cp16(st + sw, P + pbase + (size_t)row*QL + ko + kcol*8);
    }
#pragma unroll
    for (int p = 0; p < 2; p++) {
        int c = p*256 + tid;
        int row = c >> 3, kcol = c & 7;
        uint32_t sw = (uint32_t)(row*128 + kcol*16) ^ ((row & 7) << 4);
        cp16(st + 16384 + sw, V + vbase + (size_t)row*QL + ko + kcol*8);
    }
    cp_commit();
}

__global__ void __launch_bounds__(256, 2) pv_mma(
    const __half* __restrict__ P, const __half* __restrict__ V, __half* __restrict__ O)
{
    extern __shared__ char dsm[];
    const uint32_t sbase = smem_u32(dsm);
    const int tid = threadIdx.x, lane = tid & 31, warp = tid >> 5;
    const int zz = blockIdx.y, s = zz >> 5, bn = zz & 31, b = bn >> 4, n = bn & 15;
    const int it = blockIdx.x;
    const int i0 = it * 128;
    const int NC = 2*it + 2;
    const size_t pbase = (size_t)s*SSTR + ((size_t)bn << 20) + (size_t)i0*QL;
    const size_t vbase = (size_t)bn * DH * QL;
    const size_t obase = (size_t)s * M2 * DM;

    float acc[2][4][4] = {};
    pv_load(P, V, sbase,            pbase, vbase, 0, tid);
    pv_load(P, V, sbase + PV_STAGE, pbase, vbase, 1, tid);
    asm volatile("cp.async.wait_group 1;" ::: "memory");
    __syncthreads();

    const int wm = (warp & 3) * 32, wn = (warp >> 2) * 32;
    const int arow = wm + (lane & 15), akb = lane & 16;
    const int brow = wn + ((lane & 16) >> 1) + (lane & 7), bkb = (lane & 8) << 1;

    for (int kc = 0; kc < NC; kc++) {
        const uint32_t st = sbase + (kc & 1) * PV_STAGE;
#pragma unroll
        for (int ks = 0; ks < 4; ks++) {
            const int kb = ks*32;
            uint32_t ah[2][4], bh[2][4];
#pragma unroll
            for (int im = 0; im < 2; im++) {
                int row = arow + im*16;
                uint32_t off = (uint32_t)(row*128 + kb + akb) ^ ((row & 7) << 4);
                ldsm4(ah[im], st + off);
            }
#pragma unroll
            for (int np = 0; np < 2; np++) {
                int row = brow + np*16;
                uint32_t off = (uint32_t)(row*128 + kb + bkb) ^ ((row & 7) << 4);
                ldsm4(bh[np], st + 16384 + off);
            }
#pragma unroll
            for (int im = 0; im < 2; im++)
#pragma unroll
                for (int in = 0; in < 4; in++) {
                    const int np = in >> 1, hf = (in & 1) * 2;
                    mma16816(acc[im][in], ah[im], bh[np][hf], bh[np][hf+1]);
                }
        }
        __syncthreads();
        if (kc + 2 < NC) {
            pv_load(P, V, sbase + (kc & 1)*PV_STAGE, pbase, vbase, kc + 2, tid);
            asm volatile("cp.async.wait_group 1;" ::: "memory");
        } else {
            asm volatile("cp.async.wait_group 0;" ::: "memory");
        }
        __syncthreads();
    }

    const int rl = wm + (lane >> 2);
    const int cb = wn + 2*(lane & 3);
#pragma unroll
    for (int im = 0; im < 2; im++)
#pragma unroll
        for (int in = 0; in < 4; in++) {
            int col = cb + in*8;
            int r0 = i0 + rl + im*16, r1 = r0 + 8;
            *(__half2*)(O + obase + ((size_t)r0*2 + b)*DM + n*DH + col) =
                __halves2half2(__float2half_rn(acc[im][in][0]), __float2half_rn(acc[im][in][1]));
            *(__half2*)(O + obase + ((size_t)r1*2 + b)*DM + n*DH + col) =
                __halves2half2(__float2half_rn(acc[im][in][2]), __float2half_rn(acc[im][in][3]));
        }
}

// ---------------- residual + LayerNorm (merged streams) ----------------
template<int WB16>
__global__ void __launch_bounds__(256) add_ln(
    const float* __restrict__ a, const float* __restrict__ x0, const float* __restrict__ x1,
    const float* __restrict__ gamma, const float* __restrict__ beta,
    float* __restrict__ out, __half* __restrict__ oh)
{
    __shared__ float buf[1024];
    __shared__ float red[8];
    __shared__ float s_stat;
    const size_t base = (size_t)blockIdx.x << 10;
    const int str = blockIdx.x >> 11;
    const size_t lbase = (size_t)(blockIdx.x & 2047) << 10;
    const float* x = str ? x1 : x0;
    const int t = threadIdx.x, lane = t & 31, w = t >> 5;
    float sum = 0.f;
#pragma unroll
    for (int p = 0; p < 4; p++) {
        float v = a[base + t + p*256] + x[lbase + t + p*256];
        buf[t + p*256] = v; sum += v;
    }
#pragma unroll
    for (int o = 16; o; o >>= 1) sum += __shfl_xor_sync(0xffffffffu, sum, o);
    if (!lane) red[w] = sum;
    __syncthreads();
    if (t == 0) { float s = 0; for (int i = 0; i < 8; i++) s += red[i]; s_stat = s * (1.0f/1024.0f); }
    __syncthreads();
    const float mean = s_stat;
    float vs = 0.f;
#pragma unroll
    for (int p = 0; p < 4; p++) { float d = buf[t + p*256] - mean; vs += d*d; }
#pragma unroll
    for (int o = 16; o; o >>= 1) vs += __shfl_xor_sync(0xffffffffu, vs, o);
    __syncthreads();
    if (!lane) red[w] = vs;
    __syncthreads();
    if (t == 0) { float s = 0; for (int i = 0; i < 8; i++) s += red[i]; s_stat = s * (1.0f/1024.0f); }
    __syncthreads();
    const float r = rsqrtf(s_stat + 1e-12f);
#pragma unroll
    for (int p = 0; p < 4; p++) {
        int c = t + p*256;
        float val = (buf[c] - mean) * r * gamma[c] + beta[c];
        out[base + c] = val;
        if (WB16) oh[base + c] = __float2half_rn(val);
    }
}

// ---------------- host ----------------
extern "C" void kernel_launch(void* const* d_in, const int* in_sizes, int n_in,
                              void* d_out, int out_size)
{
    (void)in_sizes; (void)n_in; (void)out_size;
    const float* h       = (const float*)d_in[0];
    const float* g       = (const float*)d_in[1];
    const float* r       = (const float*)d_in[2];
    const float* seg_mat = (const float*)d_in[5];
    const float* wq      = (const float*)d_in[6];
    const float* wk      = (const float*)d_in[7];
    const float* wv      = (const float*)d_in[8];
    const float* wo      = (const float*)d_in[9];
    const float* wr      = (const float*)d_in[10];
    const float* rwb     = (const float*)d_in[11];
    const float* rrb     = (const float*)d_in[12];
    const float* rsb     = (const float*)d_in[13];
    const float* se      = (const float*)d_in[14];
    const float* lnga    = (const float*)d_in[15];
    const float* lnba    = (const float*)d_in[16];
    const float* w1      = (const float*)d_in[17];
    const float* b1      = (const float*)d_in[18];
    const float* w2      = (const float*)d_in[19];
    const float* b2      = (const float*)d_in[20];
    const float* lngf    = (const float*)d_in[21];
    const float* lnbf    = (const float*)d_in[22];

    cudaFuncSetAttribute(projHKV,       cudaFuncAttributeMaxDynamicSharedMemorySize, GSMEM_BYTES);
    cudaFuncSetAttribute(gemm_mma<0,0>, cudaFuncAttributeMaxDynamicSharedMemorySize, GSMEM_BYTES);
    cudaFuncSetAttribute(gemm_mma<0,3>, cudaFuncAttributeMaxDynamicSharedMemorySize, GSMEM_BYTES);
    cudaFuncSetAttribute(gemm_mma<2,1>, cudaFuncAttributeMaxDynamicSharedMemorySize, GSMEM_BYTES);
    cudaFuncSetAttribute(gemm_mma<1,0>, cudaFuncAttributeMaxDynamicSharedMemorySize, GSMEM_BYTES);
    cudaFuncSetAttribute(score_mma,     cudaFuncAttributeMaxDynamicSharedMemorySize, SC_SMEM);
    cudaFuncSetAttribute(pv_mma,        cudaFuncAttributeMaxDynamicSharedMemorySize, PV_SMEM);

    float *q2f,*k,*v,*kr,*ef,*o,*y,*z,*bkT,*bkrT,*S,*BD;
    __half *hb,*rb,*gb,*wqT,*wkT,*wvT,*wrT,*woC,*w1T,*w2T,*diffb;
    __half *q1h,*q2h,*khh,*krh,*vth,*Ph,*at,*yh,*th;
    cudaGetSymbolAddress((void**)&q2f,  g_q2);
    cudaGetSymbolAddress((void**)&k,    g_k);
    cudaGetSymbolAddress((void**)&v,    g_v);
    cudaGetSymbolAddress((void**)&kr,   g_kr);
    cudaGetSymbolAddress((void**)&ef,   g_ef);
    cudaGetSymbolAddress((void**)&o,    g_o);
    cudaGetSymbolAddress((void**)&y,    g_y);
    cudaGetSymbolAddress((void**)&z,    g_z);
    cudaGetSymbolAddress((void**)&bkT,  g_bkT);
    cudaGetSymbolAddress((void**)&bkrT, g_bkrT);
    cudaGetSymbolAddress((void**)&S,    g_S);
    cudaGetSymbolAddress((void**)&BD,   g_BD);
    cudaGetSymbolAddress((void**)&diffb,g_diffb);
    cudaGetSymbolAddress((void**)&hb,   g_hb);
    cudaGetSymbolAddress((void**)&rb,   g_rb);
    cudaGetSymbolAddress((void**)&gb,   g_gb);
    cudaGetSymbolAddress((void**)&wqT,  g_wqT);
    cudaGetSymbolAddress((void**)&wkT,  g_wkT);
    cudaGetSymbolAddress((void**)&wvT,  g_wvT);
    cudaGetSymbolAddress((void**)&wrT,  g_wrT);
    cudaGetSymbolAddress((void**)&woC,  g_woC);
    cudaGetSymbolAddress((void**)&w1T,  g_w1T);
    cudaGetSymbolAddress((void**)&w2T,  g_w2T);
    cudaGetSymbolAddress((void**)&q1h,  g_q1h);
    cudaGetSymbolAddress((void**)&q2h,  g_q2h);
    cudaGetSymbolAddress((void**)&khh,  g_khh);
    cudaGetSymbolAddress((void**)&krh,  g_krh);
    cudaGetSymbolAddress((void**)&vth,  g_vth);
    cudaGetSymbolAddress((void**)&Ph,   g_Ph);
    cudaGetSymbolAddress((void**)&at,   g_at);
    cudaGetSymbolAddress((void**)&yh,   g_yh);
    cudaGetSymbolAddress((void**)&th,   g_th);

    dim3 tb(32, 8);
    convT_half<<<dim3(DM/32, DM/32), tb>>>(wk, wkT, DM, DM);
    convT_half<<<dim3(DM/32, DM/32), tb>>>(wv, wvT, DM, DM);
    convT_half<<<dim3(DM/32, DM/32), tb>>>(wq, wqT, DM, DM);
    conv_half<<<(M2*DM/4 + 255)/256, 256>>>(h, hb, M2*DM/4);
    projHKV<<<dim3(8, 16, 3), 256, GSMEM_BYTES>>>();

    convT_half<<<dim3(DM/32, DM/32), tb>>>(wr, wrT, DM, DM);
    conv_half<<<(MR*DM/4 + 255)/256, 256>>>(r, rb, MR*DM/4);
    conv_half<<<(M2*DM/4 + 255)/256, 256>>>(g, gb, M2*DM/4);
    conv_half<<<(DM*DM/4 + 255)/256, 256>>>(wo, woC, DM*DM/4);
    convT_half<<<dim3(DI/32, DM/32), tb>>>(w1, w1T, DM, DI);
    convT_half<<<dim3(DM/32, DI/32), tb>>>(w2, w2T, DI, DM);
    prep_diff<<<(2*QL*QL + 255)/256, 256>>>(seg_mat, diffb);

    gemm_mma<0,3><<<dim3(8,32,1), 256, GSMEM_BYTES>>>(rb, wrT, nullptr, kr, krh, 0, 0, RL, DM, DM);
    gemm_mma<0,3><<<dim3(8,16,1), 256, GSMEM_BYTES>>>(gb, wqT, nullptr, q2f, q2h, 0, 0, QL, DM, DM);
    repack_vT<<<dim3(QL/32, DH/32, 32), tb>>>(v, vth);

    bias_dotT<<<(M2*NH*32 + 255)/256, 256>>>(k,  rwb, bkT,  QL);
    bias_dotT<<<(MR*NH*32 + 255)/256, 256>>>(kr, rrb, bkrT, RL);
    ef_kernel<<<dim3((M2*NH*32 + 255)/256, 2), 256>>>(rsb, se);

    // attention (both streams merged; causal-pruned; 1-pass fp16)
    score_mma<<<dim3(36, 1, 64), 256, SC_SMEM>>>(q1h, q2h, khh, bkT,  S,  SSTR, QL, 0);
    score_mma<<<dim3(9, 8, 64), 256, SC_SMEM>>>(q1h, q2h, krh, bkrT, BD, BSTR, RL, 1);
    softmax_fused<<<dim3(QL, 64), 256>>>(S, BD, diffb, ef, Ph);
    pv_mma<<<dim3(8, 64), 256, PV_SMEM>>>(Ph, vth, at);
    vmean_fix<<<32, 64>>>(v, at);

    // back half (both streams merged via z)
    gemm_mma<0,0><<<dim3(8,16,2), 256, GSMEM_BYTES>>>(at, woC, nullptr, o, nullptr,
        (size_t)M2*DM, (size_t)M2*DM, QL, DM, DM);
    add_ln<1><<<2*M2, 256>>>(o, h, g, lnga, lnba, y, yh);
    gemm_mma<2,1><<<dim3(32,16,2), 256, GSMEM_BYTES>>>(yh, w1T, b1, nullptr, th,
        (size_t)M2*DM, (size_t)M2*DI, QL, DM, DI);
    gemm_mma<1,0><<<dim3(8,16,2), 256, GSMEM_BYTES>>>(th, w2T, b2, z, nullptr,
        (size_t)M2*DI, (size_t)M2*DM, QL, DI, DM);
    add_ln<0><<<2*M2, 256>>>(z, y, y + (size_t)M2*DM, lngf, lnbf, (float*)d_out, nullptr);
}